// round 2
// baseline (speedup 1.0000x reference)
#include <cuda_runtime.h>
#include <cuda_bf16.h>

// ---------------------------------------------------------------------------
// BERT-base encoder forward, fp32 baseline.
// B=8, S=512, H=768, NH=12, D=64, F=3072, L=12
// ---------------------------------------------------------------------------

#define BB   8
#define SS   512
#define HH   768
#define NHH  12
#define DD   64
#define FF   3072
#define LL   12
#define BSN  (BB*SS)          // 4096 tokens

// ---------------- scratch (device globals; no allocations) -----------------
__device__ float g_h  [BSN*HH];
__device__ float g_q  [BSN*HH];
__device__ float g_k  [BSN*HH];
__device__ float g_v  [BSN*HH];
__device__ float g_ctx[BSN*HH];
__device__ float g_tmp[BSN*HH];
__device__ float g_ffn[BSN*FF];
__device__ float g_sc [BB*NHH*SS*SS];   // attention scores/probs (~100 MB)
__device__ float g_mask[BSN];           // additive key mask per token

// ---------------- helpers --------------------------------------------------
__device__ __forceinline__ float blockSum(float v, float* red) {
    int tid = threadIdx.x;
    red[tid] = v; __syncthreads();
    for (int s = 128; s > 0; s >>= 1) {
        if (tid < s) red[tid] += red[tid + s];
        __syncthreads();
    }
    float r = red[0]; __syncthreads();
    return r;
}

// ---------------- embeddings + layernorm + mask -----------------------------
__global__ __launch_bounds__(256)
void embed_ln_kernel(const int* __restrict__ ids, const int* __restrict__ tids,
                     const float* __restrict__ we, const float* __restrict__ pe,
                     const float* __restrict__ te, const float* __restrict__ sc,
                     const float* __restrict__ bi, float* __restrict__ out,
                     float* __restrict__ mask)
{
    __shared__ float red[256];
    int row = blockIdx.x;           // token index in [0, BSN)
    int s   = row % SS;
    int tid = threadIdx.x;
    int id  = ids[row];
    int tt  = tids[row];
    if (tid == 0) mask[row] = (id == 0) ? -10000.0f : 0.0f;

    float v[3]; float sum = 0.f;
    #pragma unroll
    for (int i = 0; i < 3; i++) {
        int j = tid + i * 256;
        v[i] = we[(long)id * HH + j] + pe[s * HH + j] + te[tt * HH + j];
        sum += v[i];
    }
    float mu = blockSum(sum, red) * (1.0f / HH);
    float s2 = 0.f;
    #pragma unroll
    for (int i = 0; i < 3; i++) { float d = v[i] - mu; s2 += d * d; }
    float var = blockSum(s2, red) * (1.0f / HH);
    float inv = rsqrtf(var + 1e-12f);
    #pragma unroll
    for (int i = 0; i < 3; i++) {
        int j = tid + i * 256;
        out[(long)row * HH + j] = (v[i] - mu) * inv * sc[j] + bi[j];
    }
}

// ---------------- residual add + layernorm ---------------------------------
__global__ __launch_bounds__(256)
void add_ln_kernel(const float* __restrict__ x, const float* __restrict__ t,
                   const float* __restrict__ sc, const float* __restrict__ bi,
                   float* __restrict__ out)
{
    __shared__ float red[256];
    int row = blockIdx.x;
    int tid = threadIdx.x;
    float v[3]; float sum = 0.f;
    #pragma unroll
    for (int i = 0; i < 3; i++) {
        int j = tid + i * 256;
        v[i] = x[(long)row * HH + j] + t[(long)row * HH + j];
        sum += v[i];
    }
    float mu = blockSum(sum, red) * (1.0f / HH);
    float s2 = 0.f;
    #pragma unroll
    for (int i = 0; i < 3; i++) { float d = v[i] - mu; s2 += d * d; }
    float var = blockSum(s2, red) * (1.0f / HH);
    float inv = rsqrtf(var + 1e-12f);
    #pragma unroll
    for (int i = 0; i < 3; i++) {
        int j = tid + i * 256;
        out[(long)row * HH + j] = (v[i] - mu) * inv * sc[j] + bi[j];
    }
}

// ---------------- softmax over rows of length 512 ---------------------------
__global__ __launch_bounds__(256)
void softmax512_kernel(float* __restrict__ p)
{
    __shared__ float red[256];
    long row = blockIdx.x;
    float* r = p + row * SS;
    int tid = threadIdx.x;
    float a = r[tid], b = r[tid + 256];

    red[tid] = fmaxf(a, b); __syncthreads();
    for (int s = 128; s > 0; s >>= 1) {
        if (tid < s) red[tid] = fmaxf(red[tid], red[tid + s]);
        __syncthreads();
    }
    float m = red[0]; __syncthreads();

    float e0 = __expf(a - m), e1 = __expf(b - m);
    red[tid] = e0 + e1; __syncthreads();
    for (int s = 128; s > 0; s >>= 1) {
        if (tid < s) red[tid] += red[tid + s];
        __syncthreads();
    }
    float inv = 1.0f / red[0];
    r[tid]       = e0 * inv;
    r[tid + 256] = e1 * inv;
}

// ---------------- generic tiled fp32 GEMM (NN) ------------------------------
// C[M,N] = act(A[M,K] @ B[K,N] + bias)
// omode 0: C[row*N+col]
// omode 1: scatter to heads layout [B,NH,S,D]  (QKV projections)
// omode 2: merge  heads -> [B,S,H]             (ctx, batched over z = b*NH+h)
// act 1: exact GELU
#define TBM 64
#define TBN 64
#define TBK 16

__global__ __launch_bounds__(256)
void gemm_nn_kernel(const float* __restrict__ A, const float* __restrict__ Bm,
                    const float* __restrict__ bias, float* __restrict__ C,
                    int M, int N, int K, long sA, long sB, int act, int omode)
{
    __shared__ float As[TBK][TBM + 4];
    __shared__ float Bs[TBK][TBN + 4];

    int z = blockIdx.z;
    A  += (long)z * sA;
    Bm += (long)z * sB;

    int bm0 = blockIdx.y * TBM;
    int bn0 = blockIdx.x * TBN;
    int tid = threadIdx.x;
    int tx = tid & 15, ty = tid >> 4;

    int am = tid >> 2, akq = tid & 3;     // A loader: row am, float4 at k=akq*4
    int bk = tid >> 4, bnq = tid & 15;    // B loader: row bk, float4 at n=bnq*4

    float acc[4][4] = {};

    for (int k0 = 0; k0 < K; k0 += TBK) {
        float4 av = *(const float4*)&A[(long)(bm0 + am) * K + k0 + akq * 4];
        As[akq * 4 + 0][am] = av.x;
        As[akq * 4 + 1][am] = av.y;
        As[akq * 4 + 2][am] = av.z;
        As[akq * 4 + 3][am] = av.w;
        float4 bv = *(const float4*)&Bm[(long)(k0 + bk) * N + bn0 + bnq * 4];
        *(float4*)&Bs[bk][bnq * 4] = bv;
        __syncthreads();
        #pragma unroll
        for (int kk = 0; kk < TBK; kk++) {
            float4 a4 = *(const float4*)&As[kk][ty * 4];
            float4 b4 = *(const float4*)&Bs[kk][tx * 4];
            float ar[4] = {a4.x, a4.y, a4.z, a4.w};
            float br[4] = {b4.x, b4.y, b4.z, b4.w};
            #pragma unroll
            for (int i = 0; i < 4; i++)
                #pragma unroll
                for (int j = 0; j < 4; j++)
                    acc[i][j] += ar[i] * br[j];
        }
        __syncthreads();
    }

    #pragma unroll
    for (int i = 0; i < 4; i++) {
        int row = bm0 + ty * 4 + i;
        #pragma unroll
        for (int j = 0; j < 4; j++) {
            int col = bn0 + tx * 4 + j;
            float val = acc[i][j];
            if (bias) val += bias[col];
            if (act == 1)  // exact GELU
                val = 0.5f * val * (1.0f + erff(val * 0.70710678118654752f));
            if (omode == 0) {
                C[(long)row * N + col] = val;
            } else if (omode == 1) {     // [B*S, H] -> [B,NH,S,D]
                int b = row / SS, s = row % SS;
                int hh = col / DD, d = col % DD;
                C[(((long)(b * NHH + hh)) * SS + s) * DD + d] = val;
            } else {                     // z=b*NH+h, [S,D] -> [B,S,H]
                int b = z / NHH, hh = z % NHH;
                C[((long)(b * SS + row)) * HH + hh * DD + col] = val;
            }
        }
    }
}

// ---------------- batched NT GEMM: scores = Q @ K^T * scale + mask ----------
// per z = b*NH+h : Q[S,D], K[S,D] -> P[S,S]
__global__ __launch_bounds__(256)
void gemm_nt_scores_kernel(const float* __restrict__ Q, const float* __restrict__ Km,
                           float* __restrict__ P, const float* __restrict__ mask)
{
    __shared__ float As[TBK][TBM + 4];
    __shared__ float Bs[TBK][TBN + 4];

    int z = blockIdx.z;
    const float* A  = Q  + (long)z * SS * DD;
    const float* Bt = Km + (long)z * SS * DD;
    float*       C  = P  + (long)z * SS * SS;
    int b = z / NHH;

    int bm0 = blockIdx.y * TBM;
    int bn0 = blockIdx.x * TBN;
    int tid = threadIdx.x;
    int tx = tid & 15, ty = tid >> 4;

    int am = tid >> 2, akq = tid & 3;   // both loaders walk the D (=K) dim

    float acc[4][4] = {};

    for (int k0 = 0; k0 < DD; k0 += TBK) {
        float4 av = *(const float4*)&A[(long)(bm0 + am) * DD + k0 + akq * 4];
        As[akq * 4 + 0][am] = av.x;
        As[akq * 4 + 1][am] = av.y;
        As[akq * 4 + 2][am] = av.z;
        As[akq * 4 + 3][am] = av.w;
        float4 bv = *(const float4*)&Bt[(long)(bn0 + am) * DD + k0 + akq * 4];
        Bs[akq * 4 + 0][am] = bv.x;
        Bs[akq * 4 + 1][am] = bv.y;
        Bs[akq * 4 + 2][am] = bv.z;
        Bs[akq * 4 + 3][am] = bv.w;
        __syncthreads();
        #pragma unroll
        for (int kk = 0; kk < TBK; kk++) {
            float4 a4 = *(const float4*)&As[kk][ty * 4];
            float4 b4 = *(const float4*)&Bs[kk][tx * 4];
            float ar[4] = {a4.x, a4.y, a4.z, a4.w};
            float br[4] = {b4.x, b4.y, b4.z, b4.w};
            #pragma unroll
            for (int i = 0; i < 4; i++)
                #pragma unroll
                for (int j = 0; j < 4; j++)
                    acc[i][j] += ar[i] * br[j];
        }
        __syncthreads();
    }

    #pragma unroll
    for (int i = 0; i < 4; i++) {
        int row = bm0 + ty * 4 + i;
        #pragma unroll
        for (int j = 0; j < 4; j++) {
            int col = bn0 + tx * 4 + j;
            float val = acc[i][j] * 0.125f + mask[b * SS + col];
            C[(long)row * SS + col] = val;
        }
    }
}

// ---------------------------------------------------------------------------
extern "C" void kernel_launch(void* const* d_in, const int* in_sizes, int n_in,
                              void* d_out, int out_size)
{
    const int*   ids  = (const int*)  d_in[0];
    const int*   tids = (const int*)  d_in[1];
    const float* we   = (const float*)d_in[2];
    const float* pe   = (const float*)d_in[3];
    const float* te   = (const float*)d_in[4];
    const float* esc  = (const float*)d_in[5];
    const float* ebi  = (const float*)d_in[6];
    const float* wq   = (const float*)d_in[7];
    const float* bq   = (const float*)d_in[8];
    const float* wk   = (const float*)d_in[9];
    const float* bk   = (const float*)d_in[10];
    const float* wv   = (const float*)d_in[11];
    const float* bv   = (const float*)d_in[12];
    const float* wo   = (const float*)d_in[13];
    const float* bo   = (const float*)d_in[14];
    const float* l1s  = (const float*)d_in[15];
    const float* l1b  = (const float*)d_in[16];
    const float* w1   = (const float*)d_in[17];
    const float* b1   = (const float*)d_in[18];
    const float* w2   = (const float*)d_in[19];
    const float* b2   = (const float*)d_in[20];
    const float* l2s  = (const float*)d_in[21];
    const float* l2b  = (const float*)d_in[22];
    float* out = (float*)d_out;

    float *h, *q, *k, *v, *ctx, *tmp, *ffn, *sc, *mask;
    cudaGetSymbolAddress((void**)&h,    g_h);
    cudaGetSymbolAddress((void**)&q,    g_q);
    cudaGetSymbolAddress((void**)&k,    g_k);
    cudaGetSymbolAddress((void**)&v,    g_v);
    cudaGetSymbolAddress((void**)&ctx,  g_ctx);
    cudaGetSymbolAddress((void**)&tmp,  g_tmp);
    cudaGetSymbolAddress((void**)&ffn,  g_ffn);
    cudaGetSymbolAddress((void**)&sc,   g_sc);
    cudaGetSymbolAddress((void**)&mask, g_mask);

    embed_ln_kernel<<<BSN, 256>>>(ids, tids, we, pe, te, esc, ebi, h, mask);

    for (int l = 0; l < LL; l++) {
        const float* wq_ = wq + (long)l * HH * HH;
        const float* wk_ = wk + (long)l * HH * HH;
        const float* wv_ = wv + (long)l * HH * HH;
        const float* wo_ = wo + (long)l * HH * HH;
        const float* bq_ = bq + (long)l * HH;
        const float* bk_ = bk + (long)l * HH;
        const float* bv_ = bv + (long)l * HH;
        const float* bo_ = bo + (long)l * HH;
        const float* w1_ = w1 + (long)l * HH * FF;
        const float* b1_ = b1 + (long)l * FF;
        const float* w2_ = w2 + (long)l * FF * HH;
        const float* b2_ = b2 + (long)l * HH;
        const float* l1s_ = l1s + (long)l * HH;
        const float* l1b_ = l1b + (long)l * HH;
        const float* l2s_ = l2s + (long)l * HH;
        const float* l2b_ = l2b + (long)l * HH;

        dim3 gHH(HH / TBN, BSN / TBM, 1);                     // (12, 64)
        gemm_nn_kernel<<<gHH, 256>>>(h, wq_, bq_, q, BSN, HH, HH, 0, 0, 0, 1);
        gemm_nn_kernel<<<gHH, 256>>>(h, wk_, bk_, k, BSN, HH, HH, 0, 0, 0, 1);
        gemm_nn_kernel<<<gHH, 256>>>(h, wv_, bv_, v, BSN, HH, HH, 0, 0, 0, 1);

        dim3 gS(SS / TBN, SS / TBM, BB * NHH);                // (8, 8, 96)
        gemm_nt_scores_kernel<<<gS, 256>>>(q, k, sc, mask);

        softmax512_kernel<<<BB * NHH * SS, 256>>>(sc);

        dim3 gC(DD / TBN, SS / TBM, BB * NHH);                // (1, 8, 96)
        gemm_nn_kernel<<<gC, 256>>>(sc, v, nullptr, ctx, SS, DD, SS,
                                    (long)SS * SS, (long)SS * DD, 0, 2);

        gemm_nn_kernel<<<gHH, 256>>>(ctx, wo_, bo_, tmp, BSN, HH, HH, 0, 0, 0, 0);
        add_ln_kernel<<<BSN, 256>>>(h, tmp, l1s_, l1b_, h);

        dim3 gF1(FF / TBN, BSN / TBM, 1);                     // (48, 64)
        gemm_nn_kernel<<<gF1, 256>>>(h, w1_, b1_, ffn, BSN, FF, HH, 0, 0, 1, 0);
        gemm_nn_kernel<<<gHH, 256>>>(ffn, w2_, b2_, tmp, BSN, HH, FF, 0, 0, 0, 0);

        add_ln_kernel<<<BSN, 256>>>(h, tmp, l2s_, l2b_, (l == LL - 1) ? out : h);
    }
}

// round 7
// speedup vs baseline: 1.4152x; 1.4152x over previous
#include <cuda_runtime.h>
#include <cuda_bf16.h>
#include <cstdint>

// ---------------------------------------------------------------------------
// BERT-base encoder forward, split-bf16 mma.sync (HMMA) GEMMs. sm_103-safe PTX.
// B=8, S=512, H=768, NH=12, D=64, F=3072, L=12
// ---------------------------------------------------------------------------

#define BB   8
#define SS   512
#define HH   768
#define NHH  12
#define DD   64
#define FF   3072
#define LL   12
#define BSN  (BB*SS)          // 4096 tokens
#define ZH   (BB*NHH)         // 96

typedef __nv_bfloat16 bf16;

// ---------------- scratch (device globals; no allocations) -----------------
__device__ float g_h  [BSN*HH];
__device__ float g_tmp[BSN*HH];
__device__ float g_sc [(long)ZH*SS*SS];     // attention logits fp32 (~100MB)
__device__ float g_mask[BSN];

__device__ bf16 g_h_hi[BSN*HH],  g_h_lo[BSN*HH];
__device__ bf16 g_q_hi[BSN*HH],  g_q_lo[BSN*HH];    // [z][S][D]
__device__ bf16 g_kt_hi[BSN*HH], g_kt_lo[BSN*HH];   // [z][D][S]
__device__ bf16 g_v_hi[BSN*HH],  g_v_lo[BSN*HH];    // [z][S][D]
__device__ bf16 g_c_hi[BSN*HH],  g_c_lo[BSN*HH];    // ctx [B*S][H]
__device__ bf16 g_a_hi[BSN*FF],  g_a_lo[BSN*FF];    // ffn act
__device__ bf16 g_p_hi[(long)ZH*SS*SS], g_p_lo[(long)ZH*SS*SS]; // probs

__device__ bf16 g_wq_hi[LL*HH*HH], g_wq_lo[LL*HH*HH];
__device__ bf16 g_wk_hi[LL*HH*HH], g_wk_lo[LL*HH*HH];
__device__ bf16 g_wv_hi[LL*HH*HH], g_wv_lo[LL*HH*HH];
__device__ bf16 g_wo_hi[LL*HH*HH], g_wo_lo[LL*HH*HH];
__device__ bf16 g_w1_hi[(long)LL*HH*FF], g_w1_lo[(long)LL*HH*FF];
__device__ bf16 g_w2_hi[(long)LL*FF*HH], g_w2_lo[(long)LL*FF*HH];

// ---------------- small helpers --------------------------------------------
__device__ __forceinline__ uint32_t smem_u32(const void* p) {
    uint32_t a;
    asm("{ .reg .u64 t; cvta.to.shared.u64 t, %1; cvt.u32.u64 %0, t; }" : "=r"(a) : "l"(p));
    return a;
}
__device__ __forceinline__ void cpasync16(uint32_t s, const void* g) {
    asm volatile("cp.async.cg.shared.global [%0], [%1], 16;" :: "r"(s), "l"(g) : "memory");
}
#define CP_COMMIT() asm volatile("cp.async.commit_group;" ::: "memory")
#define CP_WAIT0()  asm volatile("cp.async.wait_group 0;" ::: "memory")
#define CP_WAIT1()  asm volatile("cp.async.wait_group 1;" ::: "memory")

__device__ __forceinline__ void ldsm4(uint32_t& r0, uint32_t& r1, uint32_t& r2,
                                      uint32_t& r3, uint32_t addr) {
    asm volatile("ldmatrix.sync.aligned.m8n8.x4.shared.b16 {%0,%1,%2,%3}, [%4];"
                 : "=r"(r0), "=r"(r1), "=r"(r2), "=r"(r3) : "r"(addr));
}
__device__ __forceinline__ void ldsm4t(uint32_t& r0, uint32_t& r1, uint32_t& r2,
                                       uint32_t& r3, uint32_t addr) {
    asm volatile("ldmatrix.sync.aligned.m8n8.x4.trans.shared.b16 {%0,%1,%2,%3}, [%4];"
                 : "=r"(r0), "=r"(r1), "=r"(r2), "=r"(r3) : "r"(addr));
}
__device__ __forceinline__ void mma16816(float* c, const uint32_t* a,
                                         uint32_t b0, uint32_t b1) {
    asm volatile(
        "mma.sync.aligned.m16n8k16.row.col.f32.bf16.bf16.f32 "
        "{%0,%1,%2,%3}, {%4,%5,%6,%7}, {%8,%9}, {%0,%1,%2,%3};"
        : "+f"(c[0]), "+f"(c[1]), "+f"(c[2]), "+f"(c[3])
        : "r"(a[0]), "r"(a[1]), "r"(a[2]), "r"(a[3]), "r"(b0), "r"(b1));
}
__device__ __forceinline__ void split_store(float v, bf16* __restrict__ hi,
                                            bf16* __restrict__ lo, long o) {
    bf16 h = __float2bfloat16(v);
    hi[o] = h;
    lo[o] = __float2bfloat16(v - __bfloat162float(h));
}

// ---------------------------------------------------------------------------
// mma.sync GEMM: C[M,N] = A[M,K] @ B[K,N], A row-major [M][K], B row-major
// [K][N], both operands split hi/lo bf16.  CTA tile 128 x NT, K-chunk 32.
// ---------------------------------------------------------------------------
#define EPI_F32    0
#define EPI_GELU   1
#define EPI_QK     2   // bias + split scatter [z][S][D]     (Q, V)
#define EPI_KT     3   // bias + split scatter [z][D][S]     (K^T)
#define EPI_SCORES 4   // *0.125 + mask, fp32 [z][S][S]
#define EPI_CTX    5   // split merge heads -> [B*S, H]

template<int NT, int EPI>
__global__ __launch_bounds__(256)
void mma_gemm(const bf16* __restrict__ Ahi, const bf16* __restrict__ Alo,
              const bf16* __restrict__ Bhi, const bf16* __restrict__ Blo,
              const float* __restrict__ bias, const float* __restrict__ mask,
              float* __restrict__ outF, bf16* __restrict__ outHi,
              bf16* __restrict__ outLo,
              int M, int N, int K, long sAz, long sBz)
{
    constexpr int WARPS_N = (NT == 128) ? 4 : 2;
    constexpr int WM = (NT == 128) ? 64 : 32;        // warp tile M
    constexpr int MT = WM / 16;                      // m-tiles (4 or 2)
    constexpr int LDA_S = 40;                        // A smem row elems (32+8)
    constexpr int LDB_S = NT + 8;                    // B smem row elems
    constexpr int ABYTES = 128 * LDA_S * 2;          // 10240
    constexpr int BBYTES = 32 * LDB_S * 2;
    constexpr int OAH = 0, OAL = ABYTES;
    constexpr int OBH = 2 * ABYTES;
    constexpr int OBL = 2 * ABYTES + BBYTES;
    constexpr int BUFB = 2 * ABYTES + 2 * BBYTES;

    extern __shared__ char smem[];
    const uint32_t sb = smem_u32(smem);

    const int tid = threadIdx.x, wid = tid >> 5, lane = tid & 31;
    const int wm = wid / WARPS_N, wn = wid % WARPS_N;
    const int z = blockIdx.z;
    Ahi += (long)z * sAz;  Alo += (long)z * sAz;
    Bhi += (long)z * sBz;  Blo += (long)z * sBz;
    const int bm0 = blockIdx.y * 128;
    const int bn0 = blockIdx.x * NT;

    // ---- async tile loader ----
    auto load_chunk = [&](int buf, int k0) {
        uint32_t base = sb + buf * BUFB;
        #pragma unroll
        for (int i = 0; i < 2; i++) {                 // A: 512 16B chunks
            int idx = tid + i * 256;
            int r = idx >> 2, c = idx & 3;
            long go = (long)(bm0 + r) * K + k0 + c * 8;
            uint32_t so = r * (LDA_S * 2) + c * 16;
            cpasync16(base + OAH + so, Ahi + go);
            cpasync16(base + OAL + so, Alo + go);
        }
        constexpr int BCH = NT / 8;                   // 16B chunks per B row
        constexpr int BTOT = 32 * BCH;                // 512 or 256
        #pragma unroll
        for (int i = 0; i < BTOT / 256; i++) {
            int idx = tid + i * 256;
            int r = idx / BCH, c = idx % BCH;
            long go = (long)(k0 + r) * N + bn0 + c * 8;
            uint32_t so = r * (LDB_S * 2) + c * 16;
            cpasync16(base + OBH + so, Bhi + go);
            cpasync16(base + OBL + so, Blo + go);
        }
        CP_COMMIT();
    };

    float acc[MT][4][4];
    #pragma unroll
    for (int i = 0; i < MT; i++)
        #pragma unroll
        for (int j = 0; j < 4; j++)
            #pragma unroll
            for (int e = 0; e < 4; e++) acc[i][j][e] = 0.f;

    const int nkc = K >> 5;
    load_chunk(0, 0);

    for (int kc = 0; kc < nkc; kc++) {
        const int b = kc & 1;
        if (kc + 1 < nkc) { load_chunk(1 - b, (kc + 1) * 32); CP_WAIT1(); }
        else              { CP_WAIT0(); }
        __syncthreads();

        const uint32_t base = sb + b * BUFB;
        // per-lane ldmatrix base offsets
        const int arow = wm * WM + (lane & 15);
        const int acol8 = (lane >> 4) << 3;
        const int brow = lane & 15;
        const int bcol8 = wn * 32 + ((lane >> 4) << 3);

        #pragma unroll
        for (int ks = 0; ks < 2; ks++) {
            const int k0s = ks * 16;
            uint32_t ah[MT][4], al[MT][4];
            #pragma unroll
            for (int mt = 0; mt < MT; mt++) {
                uint32_t ao = (uint32_t)((arow + mt * 16) * (LDA_S * 2)
                                         + (k0s + acol8) * 2);
                ldsm4(ah[mt][0], ah[mt][1], ah[mt][2], ah[mt][3], base + OAH + ao);
                ldsm4(al[mt][0], al[mt][1], al[mt][2], al[mt][3], base + OAL + ao);
            }
            #pragma unroll
            for (int np = 0; np < 2; np++) {          // pairs of n-tiles
                uint32_t bo = (uint32_t)((k0s + brow) * (LDB_S * 2)
                                         + (bcol8 + np * 16) * 2);
                uint32_t bh[4], bl[4];
                ldsm4t(bh[0], bh[1], bh[2], bh[3], base + OBH + bo);
                ldsm4t(bl[0], bl[1], bl[2], bl[3], base + OBL + bo);
                #pragma unroll
                for (int mt = 0; mt < MT; mt++) {
                    mma16816(acc[mt][np * 2 + 0], ah[mt], bh[0], bh[1]);
                    mma16816(acc[mt][np * 2 + 0], ah[mt], bl[0], bl[1]);
                    mma16816(acc[mt][np * 2 + 0], al[mt], bh[0], bh[1]);
                    mma16816(acc[mt][np * 2 + 1], ah[mt], bh[2], bh[3]);
                    mma16816(acc[mt][np * 2 + 1], ah[mt], bl[2], bl[3]);
                    mma16816(acc[mt][np * 2 + 1], al[mt], bh[2], bh[3]);
                }
            }
        }
        __syncthreads();
    }

    // ---- epilogue ----
    const int zb = z / NHH, zh = z % NHH;
    #pragma unroll
    for (int mt = 0; mt < MT; mt++) {
        #pragma unroll
        for (int nt = 0; nt < 4; nt++) {
            int rA = bm0 + wm * WM + mt * 16 + (lane >> 2);
            int cA = bn0 + wn * 32 + nt * 8 + 2 * (lane & 3);
            #pragma unroll
            for (int e = 0; e < 4; e++) {
                int R   = rA + (e >> 1) * 8;
                int col = cA + (e & 1);
                float v = acc[mt][nt][e];
                if (EPI == EPI_F32) {
                    v += __ldg(&bias[col]);
                    outF[(long)R * N + col] = v;
                } else if (EPI == EPI_GELU) {
                    v += __ldg(&bias[col]);
                    v = 0.5f * v * (1.0f + erff(v * 0.70710678118654752f));
                    split_store(v, outHi, outLo, (long)R * N + col);
                } else if (EPI == EPI_QK) {
                    v += __ldg(&bias[col]);
                    int bi = R >> 9, s = R & 511, hh = col >> 6, d = col & 63;
                    long o = (((long)(bi * NHH + hh)) * SS + s) * DD + d;
                    split_store(v, outHi, outLo, o);
                } else if (EPI == EPI_KT) {
                    v += __ldg(&bias[col]);
                    int bi = R >> 9, s = R & 511, hh = col >> 6, d = col & 63;
                    long o = (((long)(bi * NHH + hh)) * DD + d) * SS + s;
                    split_store(v, outHi, outLo, o);
                } else if (EPI == EPI_SCORES) {
                    v = v * 0.125f + __ldg(&mask[zb * SS + col]);
                    outF[((long)z * SS + R) * SS + col] = v;
                } else {  // EPI_CTX
                    long o = ((long)(zb * SS + R)) * HH + zh * DD + col;
                    split_store(v, outHi, outLo, o);
                }
            }
        }
    }
}

// ---------------- weight split (elementwise, keeps [K][N] layout) -----------
__global__ __launch_bounds__(256)
void wsplit_kernel(const float* __restrict__ W, bf16* __restrict__ hi,
                   bf16* __restrict__ lo, long n)
{
    long i = (long)blockIdx.x * 256 + threadIdx.x;
    long stride = (long)gridDim.x * 256;
    for (; i < n; i += stride) split_store(W[i], hi, lo, i);
}

// ---------------- block reductions ------------------------------------------
__device__ __forceinline__ float blockSum(float v, float* red) {
    int tid = threadIdx.x;
    red[tid] = v; __syncthreads();
    for (int s = 128; s > 0; s >>= 1) {
        if (tid < s) red[tid] += red[tid + s];
        __syncthreads();
    }
    float r = red[0]; __syncthreads();
    return r;
}

// ---------------- embeddings + layernorm + mask + split ---------------------
__global__ __launch_bounds__(256)
void embed_ln_kernel(const int* __restrict__ ids, const int* __restrict__ tids,
                     const float* __restrict__ we, const float* __restrict__ pe,
                     const float* __restrict__ te, const float* __restrict__ sc,
                     const float* __restrict__ bi, float* __restrict__ out,
                     bf16* __restrict__ ohi, bf16* __restrict__ olo,
                     float* __restrict__ mask)
{
    __shared__ float red[256];
    int row = blockIdx.x, s = row % SS, tid = threadIdx.x;
    int id = ids[row], tt = tids[row];
    if (tid == 0) mask[row] = (id == 0) ? -10000.0f : 0.0f;
    float v[3]; float sum = 0.f;
    #pragma unroll
    for (int i = 0; i < 3; i++) {
        int j = tid + i * 256;
        v[i] = we[(long)id * HH + j] + pe[s * HH + j] + te[tt * HH + j];
        sum += v[i];
    }
    float mu = blockSum(sum, red) * (1.0f / HH);
    float s2 = 0.f;
    #pragma unroll
    for (int i = 0; i < 3; i++) { float d = v[i] - mu; s2 += d * d; }
    float inv = rsqrtf(blockSum(s2, red) * (1.0f / HH) + 1e-12f);
    #pragma unroll
    for (int i = 0; i < 3; i++) {
        int j = tid + i * 256;
        float r = (v[i] - mu) * inv * sc[j] + bi[j];
        long o = (long)row * HH + j;
        out[o] = r;
        split_store(r, ohi, olo, o);
    }
}

// ---------------- residual add + layernorm + split ---------------------------
__global__ __launch_bounds__(256)
void add_ln_kernel(const float* __restrict__ x, const float* __restrict__ t,
                   const float* __restrict__ sc, const float* __restrict__ bi,
                   float* __restrict__ out, bf16* __restrict__ ohi,
                   bf16* __restrict__ olo)
{
    __shared__ float red[256];
    int row = blockIdx.x, tid = threadIdx.x;
    float v[3]; float sum = 0.f;
    #pragma unroll
    for (int i = 0; i < 3; i++) {
        int j = tid + i * 256;
        v[i] = x[(long)row * HH + j] + t[(long)row * HH + j];
        sum += v[i];
    }
    float mu = blockSum(sum, red) * (1.0f / HH);
    float s2 = 0.f;
    #pragma unroll
    for (int i = 0; i < 3; i++) { float d = v[i] - mu; s2 += d * d; }
    float inv = rsqrtf(blockSum(s2, red) * (1.0f / HH) + 1e-12f);
    #pragma unroll
    for (int i = 0; i < 3; i++) {
        int j = tid + i * 256;
        float r = (v[i] - mu) * inv * sc[j] + bi[j];
        long o = (long)row * HH + j;
        out[o] = r;
        split_store(r, ohi, olo, o);
    }
}

// ---------------- softmax (512) + split to bf16 hi/lo ------------------------
__global__ __launch_bounds__(256)
void softmax512_split(const float* __restrict__ p, bf16* __restrict__ phi,
                      bf16* __restrict__ plo)
{
    __shared__ float red[256];
    long base = (long)blockIdx.x * SS;
    int tid = threadIdx.x;
    float a = p[base + tid], b = p[base + tid + 256];
    red[tid] = fmaxf(a, b); __syncthreads();
    for (int s = 128; s > 0; s >>= 1) {
        if (tid < s) red[tid] = fmaxf(red[tid], red[tid + s]);
        __syncthreads();
    }
    float m = red[0]; __syncthreads();
    float e0 = __expf(a - m), e1 = __expf(b - m);
    red[tid] = e0 + e1; __syncthreads();
    for (int s = 128; s > 0; s >>= 1) {
        if (tid < s) red[tid] += red[tid + s];
        __syncthreads();
    }
    float inv = 1.0f / red[0];
    split_store(e0 * inv, phi, plo, base + tid);
    split_store(e1 * inv, phi, plo, base + tid + 256);
}

// ---------------------------------------------------------------------------
extern "C" void kernel_launch(void* const* d_in, const int* in_sizes, int n_in,
                              void* d_out, int out_size)
{
    const int*   ids  = (const int*)  d_in[0];
    const int*   tids = (const int*)  d_in[1];
    const float* we   = (const float*)d_in[2];
    const float* pe   = (const float*)d_in[3];
    const float* te   = (const float*)d_in[4];
    const float* esc  = (const float*)d_in[5];
    const float* ebi  = (const float*)d_in[6];
    const float* wq   = (const float*)d_in[7];
    const float* bq   = (const float*)d_in[8];
    const float* wk   = (const float*)d_in[9];
    const float* bk   = (const float*)d_in[10];
    const float* wv   = (const float*)d_in[11];
    const float* bv   = (const float*)d_in[12];
    const float* wo   = (const float*)d_in[13];
    const float* bo   = (const float*)d_in[14];
    const float* l1s  = (const float*)d_in[15];
    const float* l1b  = (const float*)d_in[16];
    const float* w1   = (const float*)d_in[17];
    const float* b1   = (const float*)d_in[18];
    const float* w2   = (const float*)d_in[19];
    const float* b2   = (const float*)d_in[20];
    const float* l2s  = (const float*)d_in[21];
    const float* l2b  = (const float*)d_in[22];
    float* out = (float*)d_out;

    float *h, *tmp, *sc, *mask;
    bf16 *h_hi, *h_lo, *q_hi, *q_lo, *kt_hi, *kt_lo, *v_hi, *v_lo;
    bf16 *c_hi, *c_lo, *a_hi, *a_lo, *p_hi, *p_lo;
    bf16 *wq_hi, *wq_lo, *wk_hi, *wk_lo, *wv_hi, *wv_lo, *wo_hi, *wo_lo;
    bf16 *w1_hi, *w1_lo, *w2_hi, *w2_lo;
    cudaGetSymbolAddress((void**)&h,    g_h);
    cudaGetSymbolAddress((void**)&tmp,  g_tmp);
    cudaGetSymbolAddress((void**)&sc,   g_sc);
    cudaGetSymbolAddress((void**)&mask, g_mask);
    cudaGetSymbolAddress((void**)&h_hi,  g_h_hi);  cudaGetSymbolAddress((void**)&h_lo,  g_h_lo);
    cudaGetSymbolAddress((void**)&q_hi,  g_q_hi);  cudaGetSymbolAddress((void**)&q_lo,  g_q_lo);
    cudaGetSymbolAddress((void**)&kt_hi, g_kt_hi); cudaGetSymbolAddress((void**)&kt_lo, g_kt_lo);
    cudaGetSymbolAddress((void**)&v_hi,  g_v_hi);  cudaGetSymbolAddress((void**)&v_lo,  g_v_lo);
    cudaGetSymbolAddress((void**)&c_hi,  g_c_hi);  cudaGetSymbolAddress((void**)&c_lo,  g_c_lo);
    cudaGetSymbolAddress((void**)&a_hi,  g_a_hi);  cudaGetSymbolAddress((void**)&a_lo,  g_a_lo);
    cudaGetSymbolAddress((void**)&p_hi,  g_p_hi);  cudaGetSymbolAddress((void**)&p_lo,  g_p_lo);
    cudaGetSymbolAddress((void**)&wq_hi, g_wq_hi); cudaGetSymbolAddress((void**)&wq_lo, g_wq_lo);
    cudaGetSymbolAddress((void**)&wk_hi, g_wk_hi); cudaGetSymbolAddress((void**)&wk_lo, g_wk_lo);
    cudaGetSymbolAddress((void**)&wv_hi, g_wv_hi); cudaGetSymbolAddress((void**)&wv_lo, g_wv_lo);
    cudaGetSymbolAddress((void**)&wo_hi, g_wo_hi); cudaGetSymbolAddress((void**)&wo_lo, g_wo_lo);
    cudaGetSymbolAddress((void**)&w1_hi, g_w1_hi); cudaGetSymbolAddress((void**)&w1_lo, g_w1_lo);
    cudaGetSymbolAddress((void**)&w2_hi, g_w2_hi); cudaGetSymbolAddress((void**)&w2_lo, g_w2_lo);

    // dynamic smem sizes: 2 * (2*A + 2*B) bytes
    const int SM128 = 2 * (2 * 10240 + 2 * 32 * 136 * 2);   // 75776
    const int SM64  = 2 * (2 * 10240 + 2 * 32 * 72 * 2);    // 59392
    cudaFuncSetAttribute(mma_gemm<128, EPI_F32>,    cudaFuncAttributeMaxDynamicSharedMemorySize, SM128);
    cudaFuncSetAttribute(mma_gemm<128, EPI_GELU>,   cudaFuncAttributeMaxDynamicSharedMemorySize, SM128);
    cudaFuncSetAttribute(mma_gemm<128, EPI_QK>,     cudaFuncAttributeMaxDynamicSharedMemorySize, SM128);
    cudaFuncSetAttribute(mma_gemm<128, EPI_KT>,     cudaFuncAttributeMaxDynamicSharedMemorySize, SM128);
    cudaFuncSetAttribute(mma_gemm<128, EPI_SCORES>, cudaFuncAttributeMaxDynamicSharedMemorySize, SM128);
    cudaFuncSetAttribute(mma_gemm<64,  EPI_CTX>,    cudaFuncAttributeMaxDynamicSharedMemorySize, SM64);

    // ---- weight prep: elementwise split (keeps [K][N] layout) ----
    wsplit_kernel<<<4096, 256>>>(wq, wq_hi, wq_lo, (long)LL * HH * HH);
    wsplit_kernel<<<4096, 256>>>(wk, wk_hi, wk_lo, (long)LL * HH * HH);
    wsplit_kernel<<<4096, 256>>>(wv, wv_hi, wv_lo, (long)LL * HH * HH);
    wsplit_kernel<<<4096, 256>>>(wo, wo_hi, wo_lo, (long)LL * HH * HH);
    wsplit_kernel<<<8192, 256>>>(w1, w1_hi, w1_lo, (long)LL * HH * FF);
    wsplit_kernel<<<8192, 256>>>(w2, w2_hi, w2_lo, (long)LL * FF * HH);

    embed_ln_kernel<<<BSN, 256>>>(ids, tids, we, pe, te, esc, ebi, h, h_hi, h_lo, mask);

    const dim3 gHH(HH / 128, BSN / 128, 1);     // (6, 32)
    const dim3 gFF(FF / 128, BSN / 128, 1);     // (24, 32)
    const dim3 gSC(SS / 128, SS / 128, ZH);     // (4, 4, 96)
    const dim3 gCX(1, SS / 128, ZH);            // (1, 4, 96)

    for (int l = 0; l < LL; l++) {
        long wOff = (long)l * HH * HH, bOff = (long)l * HH;
        long w1Off = (long)l * HH * FF, b1Off = (long)l * FF;

        mma_gemm<128, EPI_QK><<<gHH, 256, SM128>>>(h_hi, h_lo, wq_hi + wOff, wq_lo + wOff,
            bq + bOff, nullptr, nullptr, q_hi, q_lo, BSN, HH, HH, 0, 0);
        mma_gemm<128, EPI_KT><<<gHH, 256, SM128>>>(h_hi, h_lo, wk_hi + wOff, wk_lo + wOff,
            bk + bOff, nullptr, nullptr, kt_hi, kt_lo, BSN, HH, HH, 0, 0);
        mma_gemm<128, EPI_QK><<<gHH, 256, SM128>>>(h_hi, h_lo, wv_hi + wOff, wv_lo + wOff,
            bv + bOff, nullptr, nullptr, v_hi, v_lo, BSN, HH, HH, 0, 0);

        // scores: A = Q [z][S][D], B = K^T [z][D][S]
        mma_gemm<128, EPI_SCORES><<<gSC, 256, SM128>>>(q_hi, q_lo, kt_hi, kt_lo,
            nullptr, mask, sc, nullptr, nullptr, SS, SS, DD, (long)SS * DD, (long)DD * SS);

        softmax512_split<<<ZH * SS, 256>>>(sc, p_hi, p_lo);

        // ctx: A = P [z][S][S], B = V [z][S][D]
        mma_gemm<64, EPI_CTX><<<gCX, 256, SM64>>>(p_hi, p_lo, v_hi, v_lo,
            nullptr, nullptr, nullptr, c_hi, c_lo, SS, DD, SS, (long)SS * SS, (long)SS * DD);

        mma_gemm<128, EPI_F32><<<gHH, 256, SM128>>>(c_hi, c_lo, wo_hi + wOff, wo_lo + wOff,
            bo + bOff, nullptr, tmp, nullptr, nullptr, BSN, HH, HH, 0, 0);
        add_ln_kernel<<<BSN, 256>>>(h, tmp, l1s + bOff, l1b + bOff, h, h_hi, h_lo);

        mma_gemm<128, EPI_GELU><<<gFF, 256, SM128>>>(h_hi, h_lo, w1_hi + w1Off, w1_lo + w1Off,
            b1 + b1Off, nullptr, nullptr, a_hi, a_lo, BSN, FF, HH, 0, 0);
        mma_gemm<128, EPI_F32><<<gHH, 256, SM128>>>(a_hi, a_lo, w2_hi + w1Off, w2_lo + w1Off,
            b2 + bOff, nullptr, tmp, nullptr, nullptr, BSN, HH, FF, 0, 0);

        add_ln_kernel<<<BSN, 256>>>(h, tmp, l2s + bOff, l2b + bOff,
                                    (l == LL - 1) ? out : h, h_hi, h_lo);
    }
}

// round 9
// speedup vs baseline: 2.2160x; 1.5658x over previous
#include <cuda_runtime.h>
#include <cuda_bf16.h>
#include <cstdint>

// ---------------------------------------------------------------------------
// BERT-base encoder forward, split-bf16 mma.sync (HMMA) GEMMs. sm_103-safe PTX.
// B=8, S=512, H=768, NH=12, D=64, F=3072, L=12
// ---------------------------------------------------------------------------

#define BB   8
#define SS   512
#define HH   768
#define NHH  12
#define DD   64
#define FF   3072
#define LL   12
#define BSN  (BB*SS)          // 4096 tokens
#define ZH   (BB*NHH)         // 96

typedef __nv_bfloat16 bf16;

// ---------------- scratch (device globals; no allocations) -----------------
__device__ float g_h  [BSN*HH];
__device__ float g_tmp[BSN*HH];
__device__ float g_sc [(long)ZH*SS*SS];     // attention logits fp32 (~100MB)
__device__ float g_mask[BSN];

__device__ bf16 g_h_hi[BSN*HH],  g_h_lo[BSN*HH];
__device__ bf16 g_q_hi[BSN*HH],  g_q_lo[BSN*HH];    // [z][S][D]
__device__ bf16 g_k_hi[BSN*HH],  g_k_lo[BSN*HH];    // [z][S][D]
__device__ bf16 g_v_hi[BSN*HH],  g_v_lo[BSN*HH];    // [z][S][D]
__device__ bf16 g_c_hi[BSN*HH],  g_c_lo[BSN*HH];    // ctx [B*S][H]
__device__ bf16 g_a_hi[BSN*FF],  g_a_lo[BSN*FF];    // ffn act
__device__ bf16 g_p_hi[(long)ZH*SS*SS], g_p_lo[(long)ZH*SS*SS]; // probs

__device__ bf16 g_wq_hi[LL*HH*HH], g_wq_lo[LL*HH*HH];
__device__ bf16 g_wk_hi[LL*HH*HH], g_wk_lo[LL*HH*HH];
__device__ bf16 g_wv_hi[LL*HH*HH], g_wv_lo[LL*HH*HH];
__device__ bf16 g_wo_hi[LL*HH*HH], g_wo_lo[LL*HH*HH];
__device__ bf16 g_w1_hi[(long)LL*HH*FF], g_w1_lo[(long)LL*HH*FF];
__device__ bf16 g_w2_hi[(long)LL*FF*HH], g_w2_lo[(long)LL*FF*HH];

// ---------------- small helpers --------------------------------------------
__device__ __forceinline__ uint32_t smem_u32(const void* p) {
    uint32_t a;
    asm("{ .reg .u64 t; cvta.to.shared.u64 t, %1; cvt.u32.u64 %0, t; }" : "=r"(a) : "l"(p));
    return a;
}
__device__ __forceinline__ void cpasync16(uint32_t s, const void* g) {
    asm volatile("cp.async.cg.shared.global [%0], [%1], 16;" :: "r"(s), "l"(g) : "memory");
}
#define CP_COMMIT() asm volatile("cp.async.commit_group;" ::: "memory")
#define CP_WAIT0()  asm volatile("cp.async.wait_group 0;" ::: "memory")
#define CP_WAIT1()  asm volatile("cp.async.wait_group 1;" ::: "memory")

__device__ __forceinline__ void ldsm4(uint32_t& r0, uint32_t& r1, uint32_t& r2,
                                      uint32_t& r3, uint32_t addr) {
    asm volatile("ldmatrix.sync.aligned.m8n8.x4.shared.b16 {%0,%1,%2,%3}, [%4];"
                 : "=r"(r0), "=r"(r1), "=r"(r2), "=r"(r3) : "r"(addr));
}
__device__ __forceinline__ void ldsm4t(uint32_t& r0, uint32_t& r1, uint32_t& r2,
                                       uint32_t& r3, uint32_t addr) {
    asm volatile("ldmatrix.sync.aligned.m8n8.x4.trans.shared.b16 {%0,%1,%2,%3}, [%4];"
                 : "=r"(r0), "=r"(r1), "=r"(r2), "=r"(r3) : "r"(addr));
}
__device__ __forceinline__ void mma16816(float* c, const uint32_t* a,
                                         uint32_t b0, uint32_t b1) {
    asm volatile(
        "mma.sync.aligned.m16n8k16.row.col.f32.bf16.bf16.f32 "
        "{%0,%1,%2,%3}, {%4,%5,%6,%7}, {%8,%9}, {%0,%1,%2,%3};"
        : "+f"(c[0]), "+f"(c[1]), "+f"(c[2]), "+f"(c[3])
        : "r"(a[0]), "r"(a[1]), "r"(a[2]), "r"(a[3]), "r"(b0), "r"(b1));
}
__device__ __forceinline__ void split_store(float v, bf16* __restrict__ hi,
                                            bf16* __restrict__ lo, long o) {
    bf16 h = __float2bfloat16(v);
    hi[o] = h;
    lo[o] = __float2bfloat16(v - __bfloat162float(h));
}

// ---------------------------------------------------------------------------
// mma.sync GEMM: C[M,N] = A[M,K] @ B, A row-major [M][K].
// BNT=false: B row-major [K][N] (k-major), loaded with ldmatrix.trans.
// BNT=true : B row-major [N][K] (n-major, i.e. NT gemm), loaded like A.
// Both operands split hi/lo bf16.  CTA tile 128 x NT, K-chunk 32, 8 warps.
// ---------------------------------------------------------------------------
#define EPI_F32    0
#define EPI_GELU   1
#define EPI_QK     2   // bias + split scatter [z][S][D]     (Q, K, V)
#define EPI_SCORES 4   // *0.125 + mask, fp32 [z][S][S]
#define EPI_CTX    5   // split merge heads -> [B*S, H]

template<int NT, int EPI, bool BNT>
__global__ __launch_bounds__(256, 2)
void mma_gemm(const bf16* __restrict__ Ahi, const bf16* __restrict__ Alo,
              const bf16* __restrict__ Bhi, const bf16* __restrict__ Blo,
              const float* __restrict__ bias, const float* __restrict__ mask,
              float* __restrict__ outF, bf16* __restrict__ outHi,
              bf16* __restrict__ outLo,
              int M, int N, int K, long sAz, long sBz)
{
    constexpr int WARPS_N = (NT == 128) ? 4 : 2;
    constexpr int WM = (NT == 128) ? 64 : 32;        // warp tile M
    constexpr int MT = WM / 16;                      // m-tiles (4 or 2)
    constexpr int LDA_S = 40;                        // A smem row elems (32+8)
    constexpr int ABYTES = 128 * LDA_S * 2;          // 10240
    constexpr int LDB_S = BNT ? 40 : (NT + 8);       // B smem row elems
    constexpr int BBYTES = BNT ? (NT * LDA_S * 2) : (32 * LDB_S * 2);
    constexpr int OAH = 0, OAL = ABYTES;
    constexpr int OBH = 2 * ABYTES;
    constexpr int OBL = 2 * ABYTES + BBYTES;
    constexpr int BUFB = 2 * ABYTES + 2 * BBYTES;

    extern __shared__ char smem[];
    const uint32_t sb = smem_u32(smem);

    const int tid = threadIdx.x, wid = tid >> 5, lane = tid & 31;
    const int wm = wid / WARPS_N, wn = wid % WARPS_N;
    const int z = blockIdx.z;
    Ahi += (long)z * sAz;  Alo += (long)z * sAz;
    Bhi += (long)z * sBz;  Blo += (long)z * sBz;
    const int bm0 = blockIdx.y * 128;
    const int bn0 = blockIdx.x * NT;

    // ---- async tile loader ----
    auto load_chunk = [&](int buf, int k0) {
        uint32_t base = sb + buf * BUFB;
        #pragma unroll
        for (int i = 0; i < 2; i++) {                 // A: 512 16B chunks
            int idx = tid + i * 256;
            int r = idx >> 2, c = idx & 3;
            long go = (long)(bm0 + r) * K + k0 + c * 8;
            uint32_t so = r * (LDA_S * 2) + c * 16;
            cpasync16(base + OAH + so, Ahi + go);
            cpasync16(base + OAL + so, Alo + go);
        }
        if (BNT) {
            #pragma unroll
            for (int i = 0; i < NT * 4 / 256; i++) {
                int idx = tid + i * 256;
                int r = idx >> 2, c = idx & 3;
                long go = (long)(bn0 + r) * K + k0 + c * 8;
                uint32_t so = r * (LDA_S * 2) + c * 16;
                cpasync16(base + OBH + so, Bhi + go);
                cpasync16(base + OBL + so, Blo + go);
            }
        } else {
            constexpr int BCH = NT / 8;               // 16B chunks per B row
            #pragma unroll
            for (int i = 0; i < 32 * BCH / 256; i++) {
                int idx = tid + i * 256;
                int r = idx / BCH, c = idx % BCH;
                long go = (long)(k0 + r) * N + bn0 + c * 8;
                uint32_t so = r * (LDB_S * 2) + c * 16;
                cpasync16(base + OBH + so, Bhi + go);
                cpasync16(base + OBL + so, Blo + go);
            }
        }
        CP_COMMIT();
    };

    float acc[MT][4][4];
    #pragma unroll
    for (int i = 0; i < MT; i++)
        #pragma unroll
        for (int j = 0; j < 4; j++)
            #pragma unroll
            for (int e = 0; e < 4; e++) acc[i][j][e] = 0.f;

    const int nkc = K >> 5;
    load_chunk(0, 0);

    for (int kc = 0; kc < nkc; kc++) {
        const int b = kc & 1;
        if (kc + 1 < nkc) { load_chunk(1 - b, (kc + 1) * 32); CP_WAIT1(); }
        else              { CP_WAIT0(); }
        __syncthreads();

        const uint32_t base = sb + b * BUFB;
        const int arow = wm * WM + (lane & 15);
        const int acol8 = (lane >> 4) << 3;

        #pragma unroll
        for (int ks = 0; ks < 2; ks++) {
            const int k0s = ks * 16;
            uint32_t ah[MT][4], al[MT][4];
            #pragma unroll
            for (int mt = 0; mt < MT; mt++) {
                uint32_t ao = (uint32_t)((arow + mt * 16) * (LDA_S * 2)
                                         + (k0s + acol8) * 2);
                ldsm4(ah[mt][0], ah[mt][1], ah[mt][2], ah[mt][3], base + OAH + ao);
                ldsm4(al[mt][0], al[mt][1], al[mt][2], al[mt][3], base + OAL + ao);
            }
            // B fragments: bp[j][2] = (b0,b1) for n-tile j (8 cols each)
            uint32_t bph[4][2], bpl[4][2];
            if (BNT) {
                #pragma unroll
                for (int half = 0; half < 2; half++) {
                    uint32_t bo = (uint32_t)((wn * 32 + half * 16 + (lane & 15)) * (LDA_S * 2)
                                             + (k0s + acol8) * 2);
                    uint32_t h0, h1, h2, h3, l0, l1, l2, l3;
                    ldsm4(h0, h1, h2, h3, base + OBH + bo);
                    ldsm4(l0, l1, l2, l3, base + OBL + bo);
                    bph[half*2+0][0] = h0; bph[half*2+0][1] = h2;
                    bph[half*2+1][0] = h1; bph[half*2+1][1] = h3;
                    bpl[half*2+0][0] = l0; bpl[half*2+0][1] = l2;
                    bpl[half*2+1][0] = l1; bpl[half*2+1][1] = l3;
                }
            } else {
                const int brow = lane & 15;
                const int bcol8 = wn * 32 + ((lane >> 4) << 3);
                #pragma unroll
                for (int np = 0; np < 2; np++) {
                    uint32_t bo = (uint32_t)((k0s + brow) * (LDB_S * 2)
                                             + (bcol8 + np * 16) * 2);
                    uint32_t h0, h1, h2, h3, l0, l1, l2, l3;
                    ldsm4t(h0, h1, h2, h3, base + OBH + bo);
                    ldsm4t(l0, l1, l2, l3, base + OBL + bo);
                    bph[np*2+0][0] = h0; bph[np*2+0][1] = h1;
                    bph[np*2+1][0] = h2; bph[np*2+1][1] = h3;
                    bpl[np*2+0][0] = l0; bpl[np*2+0][1] = l1;
                    bpl[np*2+1][0] = l2; bpl[np*2+1][1] = l3;
                }
            }
            // product-major MMA order: maximize acc reuse distance
            #pragma unroll
            for (int j = 0; j < 4; j++)
                #pragma unroll
                for (int mt = 0; mt < MT; mt++)
                    mma16816(acc[mt][j], ah[mt], bph[j][0], bph[j][1]);
            #pragma unroll
            for (int j = 0; j < 4; j++)
                #pragma unroll
                for (int mt = 0; mt < MT; mt++)
                    mma16816(acc[mt][j], ah[mt], bpl[j][0], bpl[j][1]);
            #pragma unroll
            for (int j = 0; j < 4; j++)
                #pragma unroll
                for (int mt = 0; mt < MT; mt++)
                    mma16816(acc[mt][j], al[mt], bph[j][0], bph[j][1]);
        }
        __syncthreads();
    }

    // ---- epilogue ----
    const int zb = z / NHH, zh = z % NHH;
    #pragma unroll
    for (int mt = 0; mt < MT; mt++) {
        #pragma unroll
        for (int nt = 0; nt < 4; nt++) {
            int rA = bm0 + wm * WM + mt * 16 + (lane >> 2);
            int cA = bn0 + wn * 32 + nt * 8 + 2 * (lane & 3);
            #pragma unroll
            for (int e = 0; e < 4; e++) {
                int R   = rA + (e >> 1) * 8;
                int col = cA + (e & 1);
                float v = acc[mt][nt][e];
                if (EPI == EPI_F32) {
                    v += __ldg(&bias[col]);
                    outF[(long)R * N + col] = v;
                } else if (EPI == EPI_GELU) {
                    v += __ldg(&bias[col]);
                    v = 0.5f * v * (1.0f + erff(v * 0.70710678118654752f));
                    split_store(v, outHi, outLo, (long)R * N + col);
                } else if (EPI == EPI_QK) {
                    v += __ldg(&bias[col]);
                    int bi = R >> 9, s = R & 511, hh = col >> 6, d = col & 63;
                    long o = (((long)(bi * NHH + hh)) * SS + s) * DD + d;
                    split_store(v, outHi, outLo, o);
                } else if (EPI == EPI_SCORES) {
                    v = v * 0.125f + __ldg(&mask[zb * SS + col]);
                    outF[((long)z * SS + R) * SS + col] = v;
                } else {  // EPI_CTX
                    long o = ((long)(zb * SS + R)) * HH + zh * DD + col;
                    split_store(v, outHi, outLo, o);
                }
            }
        }
    }
}

// ---------------- weight split (elementwise, keeps [K][N] layout) -----------
__global__ __launch_bounds__(256)
void wsplit_kernel(const float* __restrict__ W, bf16* __restrict__ hi,
                   bf16* __restrict__ lo, long n)
{
    long i = (long)blockIdx.x * 256 + threadIdx.x;
    long stride = (long)gridDim.x * 256;
    for (; i < n; i += stride) split_store(W[i], hi, lo, i);
}

// ---------------- block reductions ------------------------------------------
__device__ __forceinline__ float blockSum(float v, float* red) {
    int tid = threadIdx.x;
    red[tid] = v; __syncthreads();
    for (int s = 128; s > 0; s >>= 1) {
        if (tid < s) red[tid] += red[tid + s];
        __syncthreads();
    }
    float r = red[0]; __syncthreads();
    return r;
}

// ---------------- embeddings + layernorm + mask + split ---------------------
__global__ __launch_bounds__(256)
void embed_ln_kernel(const int* __restrict__ ids, const int* __restrict__ tids,
                     const float* __restrict__ we, const float* __restrict__ pe,
                     const float* __restrict__ te, const float* __restrict__ sc,
                     const float* __restrict__ bi, float* __restrict__ out,
                     bf16* __restrict__ ohi, bf16* __restrict__ olo,
                     float* __restrict__ mask)
{
    __shared__ float red[256];
    int row = blockIdx.x, s = row % SS, tid = threadIdx.x;
    int id = ids[row], tt = tids[row];
    if (tid == 0) mask[row] = (id == 0) ? -10000.0f : 0.0f;
    float v[3]; float sum = 0.f;
    #pragma unroll
    for (int i = 0; i < 3; i++) {
        int j = tid + i * 256;
        v[i] = we[(long)id * HH + j] + pe[s * HH + j] + te[tt * HH + j];
        sum += v[i];
    }
    float mu = blockSum(sum, red) * (1.0f / HH);
    float s2 = 0.f;
    #pragma unroll
    for (int i = 0; i < 3; i++) { float d = v[i] - mu; s2 += d * d; }
    float inv = rsqrtf(blockSum(s2, red) * (1.0f / HH) + 1e-12f);
    #pragma unroll
    for (int i = 0; i < 3; i++) {
        int j = tid + i * 256;
        float r = (v[i] - mu) * inv * sc[j] + bi[j];
        long o = (long)row * HH + j;
        out[o] = r;
        split_store(r, ohi, olo, o);
    }
}

// ---------------- residual add + layernorm + split ---------------------------
__global__ __launch_bounds__(256)
void add_ln_kernel(const float* __restrict__ x, const float* __restrict__ t,
                   const float* __restrict__ sc, const float* __restrict__ bi,
                   float* __restrict__ out, bf16* __restrict__ ohi,
                   bf16* __restrict__ olo)
{
    __shared__ float red[256];
    int row = blockIdx.x, tid = threadIdx.x;
    float v[3]; float sum = 0.f;
    #pragma unroll
    for (int i = 0; i < 3; i++) {
        int j = tid + i * 256;
        v[i] = x[(long)row * HH + j] + t[(long)row * HH + j];
        sum += v[i];
    }
    float mu = blockSum(sum, red) * (1.0f / HH);
    float s2 = 0.f;
    #pragma unroll
    for (int i = 0; i < 3; i++) { float d = v[i] - mu; s2 += d * d; }
    float inv = rsqrtf(blockSum(s2, red) * (1.0f / HH) + 1e-12f);
    #pragma unroll
    for (int i = 0; i < 3; i++) {
        int j = tid + i * 256;
        float r = (v[i] - mu) * inv * sc[j] + bi[j];
        long o = (long)row * HH + j;
        out[o] = r;
        split_store(r, ohi, olo, o);
    }
}

// ---------------- softmax (512) + split to bf16 hi/lo ------------------------
__global__ __launch_bounds__(256)
void softmax512_split(const float* __restrict__ p, bf16* __restrict__ phi,
                      bf16* __restrict__ plo)
{
    __shared__ float red[256];
    long base = (long)blockIdx.x * SS;
    int tid = threadIdx.x;
    float a = p[base + tid], b = p[base + tid + 256];
    red[tid] = fmaxf(a, b); __syncthreads();
    for (int s = 128; s > 0; s >>= 1) {
        if (tid < s) red[tid] = fmaxf(red[tid], red[tid + s]);
        __syncthreads();
    }
    float m = red[0]; __syncthreads();
    float e0 = __expf(a - m), e1 = __expf(b - m);
    red[tid] = e0 + e1; __syncthreads();
    for (int s = 128; s > 0; s >>= 1) {
        if (tid < s) red[tid] += red[tid + s];
        __syncthreads();
    }
    float inv = 1.0f / red[0];
    split_store(e0 * inv, phi, plo, base + tid);
    split_store(e1 * inv, phi, plo, base + tid + 256);
}

// ---------------------------------------------------------------------------
extern "C" void kernel_launch(void* const* d_in, const int* in_sizes, int n_in,
                              void* d_out, int out_size)
{
    const int*   ids  = (const int*)  d_in[0];
    const int*   tids = (const int*)  d_in[1];
    const float* we   = (const float*)d_in[2];
    const float* pe   = (const float*)d_in[3];
    const float* te   = (const float*)d_in[4];
    const float* esc  = (const float*)d_in[5];
    const float* ebi  = (const float*)d_in[6];
    const float* wq   = (const float*)d_in[7];
    const float* bq   = (const float*)d_in[8];
    const float* wk   = (const float*)d_in[9];
    const float* bk   = (const float*)d_in[10];
    const float* wv   = (const float*)d_in[11];
    const float* bv   = (const float*)d_in[12];
    const float* wo   = (const float*)d_in[13];
    const float* bo   = (const float*)d_in[14];
    const float* l1s  = (const float*)d_in[15];
    const float* l1b  = (const float*)d_in[16];
    const float* w1   = (const float*)d_in[17];
    const float* b1   = (const float*)d_in[18];
    const float* w2   = (const float*)d_in[19];
    const float* b2   = (const float*)d_in[20];
    const float* l2s  = (const float*)d_in[21];
    const float* l2b  = (const float*)d_in[22];
    float* out = (float*)d_out;

    float *h, *tmp, *sc, *mask;
    bf16 *h_hi, *h_lo, *q_hi, *q_lo, *k_hi, *k_lo, *v_hi, *v_lo;
    bf16 *c_hi, *c_lo, *a_hi, *a_lo, *p_hi, *p_lo;
    bf16 *wq_hi, *wq_lo, *wk_hi, *wk_lo, *wv_hi, *wv_lo, *wo_hi, *wo_lo;
    bf16 *w1_hi, *w1_lo, *w2_hi, *w2_lo;
    cudaGetSymbolAddress((void**)&h,    g_h);
    cudaGetSymbolAddress((void**)&tmp,  g_tmp);
    cudaGetSymbolAddress((void**)&sc,   g_sc);
    cudaGetSymbolAddress((void**)&mask, g_mask);
    cudaGetSymbolAddress((void**)&h_hi,  g_h_hi);  cudaGetSymbolAddress((void**)&h_lo,  g_h_lo);
    cudaGetSymbolAddress((void**)&q_hi,  g_q_hi);  cudaGetSymbolAddress((void**)&q_lo,  g_q_lo);
    cudaGetSymbolAddress((void**)&k_hi,  g_k_hi);  cudaGetSymbolAddress((void**)&k_lo,  g_k_lo);
    cudaGetSymbolAddress((void**)&v_hi,  g_v_hi);  cudaGetSymbolAddress((void**)&v_lo,  g_v_lo);
    cudaGetSymbolAddress((void**)&c_hi,  g_c_hi);  cudaGetSymbolAddress((void**)&c_lo,  g_c_lo);
    cudaGetSymbolAddress((void**)&a_hi,  g_a_hi);  cudaGetSymbolAddress((void**)&a_lo,  g_a_lo);
    cudaGetSymbolAddress((void**)&p_hi,  g_p_hi);  cudaGetSymbolAddress((void**)&p_lo,  g_p_lo);
    cudaGetSymbolAddress((void**)&wq_hi, g_wq_hi); cudaGetSymbolAddress((void**)&wq_lo, g_wq_lo);
    cudaGetSymbolAddress((void**)&wk_hi, g_wk_hi); cudaGetSymbolAddress((void**)&wk_lo, g_wk_lo);
    cudaGetSymbolAddress((void**)&wv_hi, g_wv_hi); cudaGetSymbolAddress((void**)&wv_lo, g_wv_lo);
    cudaGetSymbolAddress((void**)&wo_hi, g_wo_hi); cudaGetSymbolAddress((void**)&wo_lo, g_wo_lo);
    cudaGetSymbolAddress((void**)&w1_hi, g_w1_hi); cudaGetSymbolAddress((void**)&w1_lo, g_w1_lo);
    cudaGetSymbolAddress((void**)&w2_hi, g_w2_hi); cudaGetSymbolAddress((void**)&w2_lo, g_w2_lo);

    // dynamic smem: 2 stages * (2*A + 2*B)
    const int SM_KM  = 2 * (2 * 10240 + 2 * 32 * 136 * 2);  // k-major NT=128: 75776
    const int SM_NT  = 2 * (2 * 10240 + 2 * 10240);         // n-major NT=128: 81920
    const int SM_CX  = 2 * (2 * 10240 + 2 * 32 * 72 * 2);   // k-major NT=64:  59392
    cudaFuncSetAttribute((const void*)mma_gemm<128, EPI_F32,    false>, cudaFuncAttributeMaxDynamicSharedMemorySize, SM_KM);
    cudaFuncSetAttribute((const void*)mma_gemm<128, EPI_GELU,   false>, cudaFuncAttributeMaxDynamicSharedMemorySize, SM_KM);
    cudaFuncSetAttribute((const void*)mma_gemm<128, EPI_QK,     false>, cudaFuncAttributeMaxDynamicSharedMemorySize, SM_KM);
    cudaFuncSetAttribute((const void*)mma_gemm<128, EPI_SCORES, true >, cudaFuncAttributeMaxDynamicSharedMemorySize, SM_NT);
    cudaFuncSetAttribute((const void*)mma_gemm<64,  EPI_CTX,    false>, cudaFuncAttributeMaxDynamicSharedMemorySize, SM_CX);

    const dim3 gHH(HH / 128, BSN / 128, 1);     // (6, 32)
    const dim3 gFF(FF / 128, BSN / 128, 1);     // (24, 32)
    const dim3 gSC(SS / 128, SS / 128, ZH);     // (4, 4, 96)
    const dim3 gCX(1, SS / 128, ZH);            // (1, 4, 96)

    // ---- launches 0-3: attention weight splits ----
    wsplit_kernel<<<4096, 256>>>(wq, wq_hi, wq_lo, (long)LL * HH * HH);
    wsplit_kernel<<<4096, 256>>>(wk, wk_hi, wk_lo, (long)LL * HH * HH);
    wsplit_kernel<<<4096, 256>>>(wv, wv_hi, wv_lo, (long)LL * HH * HH);
    wsplit_kernel<<<4096, 256>>>(wo, wo_hi, wo_lo, (long)LL * HH * HH);
    // ---- launch 4: embeddings ----
    embed_ln_kernel<<<BSN, 256>>>(ids, tids, we, pe, te, esc, ebi, h, h_hi, h_lo, mask);

    for (int l = 0; l < LL; l++) {
        long wOff = (long)l * HH * HH, bOff = (long)l * HH;
        long w1Off = (long)l * HH * FF, b1Off = (long)l * FF;

        // ---- launch 5 (l==0): Q GEMM — ncu capture target ----
        mma_gemm<128, EPI_QK, false><<<gHH, 256, SM_KM>>>(h_hi, h_lo, wq_hi + wOff, wq_lo + wOff,
            bq + bOff, nullptr, nullptr, q_hi, q_lo, BSN, HH, HH, 0, 0);
        if (l == 0) {  // FFN weight splits (needed before FFN1 of layer 0)
            wsplit_kernel<<<8192, 256>>>(w1, w1_hi, w1_lo, (long)LL * HH * FF);
            wsplit_kernel<<<8192, 256>>>(w2, w2_hi, w2_lo, (long)LL * FF * HH);
        }
        mma_gemm<128, EPI_QK, false><<<gHH, 256, SM_KM>>>(h_hi, h_lo, wk_hi + wOff, wk_lo + wOff,
            bk + bOff, nullptr, nullptr, k_hi, k_lo, BSN, HH, HH, 0, 0);
        mma_gemm<128, EPI_QK, false><<<gHH, 256, SM_KM>>>(h_hi, h_lo, wv_hi + wOff, wv_lo + wOff,
            bv + bOff, nullptr, nullptr, v_hi, v_lo, BSN, HH, HH, 0, 0);

        // scores: A = Q [z][S][D], B = K [z][S][D] (NT gemm)
        mma_gemm<128, EPI_SCORES, true><<<gSC, 256, SM_NT>>>(q_hi, q_lo, k_hi, k_lo,
            nullptr, mask, sc, nullptr, nullptr, SS, SS, DD, (long)SS * DD, (long)SS * DD);

        softmax512_split<<<ZH * SS, 256>>>(sc, p_hi, p_lo);

        // ctx: A = P [z][S][S], B = V [z][S][D] (k-major)
        mma_gemm<64, EPI_CTX, false><<<gCX, 256, SM_CX>>>(p_hi, p_lo, v_hi, v_lo,
            nullptr, nullptr, nullptr, c_hi, c_lo, SS, DD, SS, (long)SS * SS, (long)SS * DD);

        mma_gemm<128, EPI_F32, false><<<gHH, 256, SM_KM>>>(c_hi, c_lo, wo_hi + wOff, wo_lo + wOff,
            bo + bOff, nullptr, tmp, nullptr, nullptr, BSN, HH, HH, 0, 0);
        add_ln_kernel<<<BSN, 256>>>(h, tmp, l1s + bOff, l1b + bOff, h, h_hi, h_lo);

        mma_gemm<128, EPI_GELU, false><<<gFF, 256, SM_KM>>>(h_hi, h_lo, w1_hi + w1Off, w1_lo + w1Off,
            b1 + b1Off, nullptr, nullptr, a_hi, a_lo, BSN, FF, HH, 0, 0);
        mma_gemm<128, EPI_F32, false><<<gHH, 256, SM_KM>>>(a_hi, a_lo, w2_hi + w1Off, w2_lo + w1Off,
            b2 + bOff, nullptr, tmp, nullptr, nullptr, BSN, HH, FF, 0, 0);

        add_ln_kernel<<<BSN, 256>>>(h, tmp, l2s + bOff, l2b + bOff,
                                    (l == LL - 1) ? out : h, h_hi, h_lo);
    }
}

// round 10
// speedup vs baseline: 2.3985x; 1.0824x over previous
#include <cuda_runtime.h>
#include <cuda_bf16.h>
#include <cstdint>

// ---------------------------------------------------------------------------
// BERT-base encoder forward, split-bf16 mma.sync (HMMA) GEMMs. sm_103-safe PTX.
// B=8, S=512, H=768, NH=12, D=64, F=3072, L=12
// ---------------------------------------------------------------------------

#define BB   8
#define SS   512
#define HH   768
#define NHH  12
#define DD   64
#define FF   3072
#define LL   12
#define BSN  (BB*SS)          // 4096 tokens
#define ZH   (BB*NHH)         // 96

typedef __nv_bfloat16 bf16;

// ---------------- scratch (device globals; no allocations) -----------------
__device__ float g_h  [BSN*HH];
__device__ float g_tmp[BSN*HH];
__device__ float g_sc [(long)ZH*SS*SS];     // attention logits fp32 (~100MB)
__device__ float g_mask[BSN];

__device__ bf16 g_h_hi[BSN*HH],  g_h_lo[BSN*HH];
__device__ bf16 g_q_hi[BSN*HH],  g_q_lo[BSN*HH];    // [z][S][D]
__device__ bf16 g_k_hi[BSN*HH],  g_k_lo[BSN*HH];    // [z][S][D]
__device__ bf16 g_v_hi[BSN*HH],  g_v_lo[BSN*HH];    // [z][S][D]
__device__ bf16 g_c_hi[BSN*HH],  g_c_lo[BSN*HH];    // ctx [B*S][H]
__device__ bf16 g_a_hi[BSN*FF],  g_a_lo[BSN*FF];    // ffn act
__device__ bf16 g_p_hi[(long)ZH*SS*SS], g_p_lo[(long)ZH*SS*SS]; // probs

__device__ bf16 g_wq_hi[LL*HH*HH], g_wq_lo[LL*HH*HH];
__device__ bf16 g_wk_hi[LL*HH*HH], g_wk_lo[LL*HH*HH];
__device__ bf16 g_wv_hi[LL*HH*HH], g_wv_lo[LL*HH*HH];
__device__ bf16 g_wo_hi[LL*HH*HH], g_wo_lo[LL*HH*HH];
__device__ bf16 g_w1_hi[(long)LL*HH*FF], g_w1_lo[(long)LL*HH*FF];
__device__ bf16 g_w2_hi[(long)LL*FF*HH], g_w2_lo[(long)LL*FF*HH];

// ---------------- small helpers --------------------------------------------
__device__ __forceinline__ uint32_t smem_u32(const void* p) {
    uint32_t a;
    asm("{ .reg .u64 t; cvta.to.shared.u64 t, %1; cvt.u32.u64 %0, t; }" : "=r"(a) : "l"(p));
    return a;
}
__device__ __forceinline__ void cpasync16(uint32_t s, const void* g) {
    asm volatile("cp.async.cg.shared.global [%0], [%1], 16;" :: "r"(s), "l"(g) : "memory");
}
#define CP_COMMIT() asm volatile("cp.async.commit_group;" ::: "memory")
#define CP_WAIT0()  asm volatile("cp.async.wait_group 0;" ::: "memory")
#define CP_WAIT1()  asm volatile("cp.async.wait_group 1;" ::: "memory")
#define CP_WAIT2()  asm volatile("cp.async.wait_group 2;" ::: "memory")

__device__ __forceinline__ void ldsm4(uint32_t& r0, uint32_t& r1, uint32_t& r2,
                                      uint32_t& r3, uint32_t addr) {
    asm volatile("ldmatrix.sync.aligned.m8n8.x4.shared.b16 {%0,%1,%2,%3}, [%4];"
                 : "=r"(r0), "=r"(r1), "=r"(r2), "=r"(r3) : "r"(addr));
}
__device__ __forceinline__ void ldsm4t(uint32_t& r0, uint32_t& r1, uint32_t& r2,
                                       uint32_t& r3, uint32_t addr) {
    asm volatile("ldmatrix.sync.aligned.m8n8.x4.trans.shared.b16 {%0,%1,%2,%3}, [%4];"
                 : "=r"(r0), "=r"(r1), "=r"(r2), "=r"(r3) : "r"(addr));
}
__device__ __forceinline__ void mma16816(float* c, const uint32_t* a,
                                         uint32_t b0, uint32_t b1) {
    // non-volatile: pure register op, let the scheduler interleave
    asm("mma.sync.aligned.m16n8k16.row.col.f32.bf16.bf16.f32 "
        "{%0,%1,%2,%3}, {%4,%5,%6,%7}, {%8,%9}, {%0,%1,%2,%3};"
        : "+f"(c[0]), "+f"(c[1]), "+f"(c[2]), "+f"(c[3])
        : "r"(a[0]), "r"(a[1]), "r"(a[2]), "r"(a[3]), "r"(b0), "r"(b1));
}
__device__ __forceinline__ void split_store(float v, bf16* __restrict__ hi,
                                            bf16* __restrict__ lo, long o) {
    bf16 h = __float2bfloat16(v);
    hi[o] = h;
    lo[o] = __float2bfloat16(v - __bfloat162float(h));
}

// ---------------------------------------------------------------------------
// mma.sync GEMM: C[M,N] = A[M,K] @ B, A row-major [M][K].
// BNT=false: B row-major [K][N] (k-major), loaded with ldmatrix.trans.
// BNT=true : B row-major [N][K] (NT gemm), loaded like A.
// Split hi/lo bf16, 3 products (hh + hl + lh), fp32 accum.
// CTA tile 128 x NT, K-chunk 32, 8 warps, STAGES-deep cp.async pipeline.
// QKV3: gridDim.z = 3 selects {wq->q, wk->k, wv->v} from device globals.
// ---------------------------------------------------------------------------
#define EPI_F32    0
#define EPI_GELU   1
#define EPI_QK     2   // bias + split scatter [z][S][D]     (Q, K, V)
#define EPI_SCORES 4   // *0.125 + mask, fp32 [z][S][S]
#define EPI_CTX    5   // split merge heads -> [B*S, H]

template<int NT, int EPI, bool BNT, int STAGES, bool QKV3>
__global__ __launch_bounds__(256, 2)
void mma_gemm(const bf16* Ahi, const bf16* Alo,
              const bf16* Bhi, const bf16* Blo,
              const float* bias, const float* bias2, const float* bias3,
              const float* mask,
              float* outF, bf16* outHi, bf16* outLo,
              int M, int N, int K, long sAz, long sBz)
{
    constexpr int WARPS_N = (NT == 128) ? 4 : 2;
    constexpr int WM = (NT == 128) ? 64 : 32;        // warp tile M
    constexpr int MT = WM / 16;                      // m-tiles (4 or 2)
    constexpr int LDA_S = 40;                        // A smem row elems (32+8)
    constexpr int ABYTES = 128 * LDA_S * 2;          // 10240
    constexpr int LDB_S = BNT ? 40 : (NT + 8);       // B smem row elems
    constexpr int BBYTES = BNT ? (NT * LDA_S * 2) : (32 * LDB_S * 2);
    constexpr int OAH = 0, OAL = ABYTES;
    constexpr int OBH = 2 * ABYTES;
    constexpr int OBL = 2 * ABYTES + BBYTES;
    constexpr int BUFB = 2 * ABYTES + 2 * BBYTES;

    extern __shared__ char smem[];
    const uint32_t sb = smem_u32(smem);

    const int tid = threadIdx.x, wid = tid >> 5, lane = tid & 31;
    const int wm = wid / WARPS_N, wn = wid % WARPS_N;
    const int z = blockIdx.z;
    if constexpr (QKV3) {
        if (z == 1)      { Bhi = g_wk_hi + sBz; Blo = g_wk_lo + sBz; bias = bias2; outHi = g_k_hi; outLo = g_k_lo; }
        else if (z == 2) { Bhi = g_wv_hi + sBz; Blo = g_wv_lo + sBz; bias = bias3; outHi = g_v_hi; outLo = g_v_lo; }
        else             { Bhi = g_wq_hi + sBz; Blo = g_wq_lo + sBz;               outHi = g_q_hi; outLo = g_q_lo; }
    } else {
        Ahi += (long)z * sAz;  Alo += (long)z * sAz;
        Bhi += (long)z * sBz;  Blo += (long)z * sBz;
    }
    const int bm0 = blockIdx.y * 128;
    const int bn0 = blockIdx.x * NT;

    // ---- async tile loader ----
    auto load_chunk = [&](int buf, int k0) {
        uint32_t base = sb + buf * BUFB;
        #pragma unroll
        for (int i = 0; i < 2; i++) {                 // A: 512 16B chunks
            int idx = tid + i * 256;
            int r = idx >> 2, c = idx & 3;
            long go = (long)(bm0 + r) * K + k0 + c * 8;
            uint32_t so = r * (LDA_S * 2) + c * 16;
            cpasync16(base + OAH + so, Ahi + go);
            cpasync16(base + OAL + so, Alo + go);
        }
        if (BNT) {
            #pragma unroll
            for (int i = 0; i < NT * 4 / 256; i++) {
                int idx = tid + i * 256;
                int r = idx >> 2, c = idx & 3;
                long go = (long)(bn0 + r) * K + k0 + c * 8;
                uint32_t so = r * (LDA_S * 2) + c * 16;
                cpasync16(base + OBH + so, Bhi + go);
                cpasync16(base + OBL + so, Blo + go);
            }
        } else {
            constexpr int BCH = NT / 8;               // 16B chunks per B row
            #pragma unroll
            for (int i = 0; i < 32 * BCH / 256; i++) {
                int idx = tid + i * 256;
                int r = idx / BCH, c = idx % BCH;
                long go = (long)(k0 + r) * N + bn0 + c * 8;
                uint32_t so = r * (LDB_S * 2) + c * 16;
                cpasync16(base + OBH + so, Bhi + go);
                cpasync16(base + OBL + so, Blo + go);
            }
        }
        CP_COMMIT();
    };

    float acc[MT][4][4];
    #pragma unroll
    for (int i = 0; i < MT; i++)
        #pragma unroll
        for (int j = 0; j < 4; j++)
            #pragma unroll
            for (int e = 0; e < 4; e++) acc[i][j][e] = 0.f;

    const int nkc = K >> 5;
    #pragma unroll
    for (int s = 0; s < STAGES - 1; s++)
        if (s < nkc) load_chunk(s, s * 32);

    const int arow = wm * WM + (lane & 15);
    const int acol8 = (lane >> 4) << 3;

    for (int kc = 0; kc < nkc; kc++) {
        __syncthreads();   // all warps done with the stage we are about to refill
        if (kc + STAGES - 1 < nkc)
            load_chunk((kc + STAGES - 1) % STAGES, (kc + STAGES - 1) * 32);
        if (kc + STAGES <= nkc) {
            if (STAGES == 3) { CP_WAIT2(); } else { CP_WAIT1(); }
        } else if (kc + 2 <= nkc) { CP_WAIT1(); }
        else                      { CP_WAIT0(); }
        __syncthreads();

        const uint32_t base = sb + (kc % STAGES) * BUFB;

        // B fragment loader: bf[j] = (b0,b1) for n-tile j (8 cols each)
        auto loadB = [&](uint32_t (&bf)[4][2], uint32_t off, int k0s) {
            uint32_t r0, r1, r2, r3;
            if (BNT) {
                #pragma unroll
                for (int half = 0; half < 2; half++) {
                    uint32_t bo = (uint32_t)((wn * 32 + half * 16 + (lane & 15)) * (LDA_S * 2)
                                             + (k0s + acol8) * 2);
                    ldsm4(r0, r1, r2, r3, base + off + bo);
                    bf[half*2+0][0] = r0; bf[half*2+0][1] = r2;
                    bf[half*2+1][0] = r1; bf[half*2+1][1] = r3;
                }
            } else {
                const int brow = lane & 15;
                const int bcol8 = wn * 32 + ((lane >> 4) << 3);
                #pragma unroll
                for (int np = 0; np < 2; np++) {
                    uint32_t bo = (uint32_t)((k0s + brow) * (LDB_S * 2)
                                             + (bcol8 + np * 16) * 2);
                    ldsm4t(r0, r1, r2, r3, base + off + bo);
                    bf[np*2+0][0] = r0; bf[np*2+0][1] = r1;
                    bf[np*2+1][0] = r2; bf[np*2+1][1] = r3;
                }
            }
        };

        #pragma unroll
        for (int ks = 0; ks < 2; ks++) {
            const int k0s = ks * 16;
            uint32_t af[MT][4];            // A fragment: hi first, reused for lo
            uint32_t bfh[4][2], bfl[4][2];
            #pragma unroll
            for (int mt = 0; mt < MT; mt++) {
                uint32_t ao = (uint32_t)((arow + mt * 16) * (LDA_S * 2)
                                         + (k0s + acol8) * 2);
                ldsm4(af[mt][0], af[mt][1], af[mt][2], af[mt][3], base + OAH + ao);
            }
            loadB(bfh, OBH, k0s);
            loadB(bfl, OBL, k0s);
            // hh
            #pragma unroll
            for (int j = 0; j < 4; j++)
                #pragma unroll
                for (int mt = 0; mt < MT; mt++)
                    mma16816(acc[mt][j], af[mt], bfh[j][0], bfh[j][1]);
            // hl
            #pragma unroll
            for (int j = 0; j < 4; j++)
                #pragma unroll
                for (int mt = 0; mt < MT; mt++)
                    mma16816(acc[mt][j], af[mt], bfl[j][0], bfl[j][1]);
            // reload A-lo into the same registers, then lh
            #pragma unroll
            for (int mt = 0; mt < MT; mt++) {
                uint32_t ao = (uint32_t)((arow + mt * 16) * (LDA_S * 2)
                                         + (k0s + acol8) * 2);
                ldsm4(af[mt][0], af[mt][1], af[mt][2], af[mt][3], base + OAL + ao);
            }
            #pragma unroll
            for (int j = 0; j < 4; j++)
                #pragma unroll
                for (int mt = 0; mt < MT; mt++)
                    mma16816(acc[mt][j], af[mt], bfh[j][0], bfh[j][1]);
        }
    }

    // ---- epilogue ----
    const int zb = z / NHH, zh = z % NHH;
    #pragma unroll
    for (int nt = 0; nt < 4; nt++) {
        const int colb = bn0 + wn * 32 + nt * 8 + 2 * (lane & 3);
        float b0 = 0.f, b1 = 0.f;
        if (EPI == EPI_F32 || EPI == EPI_GELU || EPI == EPI_QK) {
            b0 = __ldg(&bias[colb]); b1 = __ldg(&bias[colb + 1]);
        } else if (EPI == EPI_SCORES) {
            b0 = __ldg(&mask[zb * SS + colb]); b1 = __ldg(&mask[zb * SS + colb + 1]);
        }
        #pragma unroll
        for (int mt = 0; mt < MT; mt++) {
            const int rA = bm0 + wm * WM + mt * 16 + (lane >> 2);
            #pragma unroll
            for (int e = 0; e < 4; e++) {
                int R   = rA + (e >> 1) * 8;
                int col = colb + (e & 1);
                float bb = (e & 1) ? b1 : b0;
                float v = acc[mt][nt][e];
                if (EPI == EPI_F32) {
                    v += bb;
                    outF[(long)R * N + col] = v;
                } else if (EPI == EPI_GELU) {
                    v += bb;
                    v = 0.5f * v * (1.0f + erff(v * 0.70710678118654752f));
                    split_store(v, outHi, outLo, (long)R * N + col);
                } else if (EPI == EPI_QK) {
                    v += bb;
                    int bi = R >> 9, s = R & 511, hh = col >> 6, d = col & 63;
                    long o = (((long)(bi * NHH + hh)) * SS + s) * DD + d;
                    split_store(v, outHi, outLo, o);
                } else if (EPI == EPI_SCORES) {
                    v = v * 0.125f + bb;
                    outF[((long)z * SS + R) * SS + col] = v;
                } else {  // EPI_CTX
                    long o = ((long)(zb * SS + R)) * HH + zh * DD + col;
                    split_store(v, outHi, outLo, o);
                }
            }
        }
    }
}

// ---------------- fused weight splits (z selects tensor) --------------------
__global__ __launch_bounds__(256)
void wsplit4_kernel(const float* __restrict__ a0, const float* __restrict__ a1,
                    const float* __restrict__ a2, const float* __restrict__ a3,
                    long n)
{
    int zs = blockIdx.z;
    const float* W = (zs == 0) ? a0 : (zs == 1) ? a1 : (zs == 2) ? a2 : a3;
    bf16* hi = (zs == 0) ? g_wq_hi : (zs == 1) ? g_wk_hi : (zs == 2) ? g_wv_hi : g_wo_hi;
    bf16* lo = (zs == 0) ? g_wq_lo : (zs == 1) ? g_wk_lo : (zs == 2) ? g_wv_lo : g_wo_lo;
    long i = (long)blockIdx.x * 256 + threadIdx.x;
    long stride = (long)gridDim.x * 256;
    for (; i < n; i += stride) split_store(W[i], hi, lo, i);
}
__global__ __launch_bounds__(256)
void wsplit2_kernel(const float* __restrict__ a0, const float* __restrict__ a1, long n)
{
    int zs = blockIdx.z;
    const float* W = (zs == 0) ? a0 : a1;
    bf16* hi = (zs == 0) ? g_w1_hi : g_w2_hi;
    bf16* lo = (zs == 0) ? g_w1_lo : g_w2_lo;
    long i = (long)blockIdx.x * 256 + threadIdx.x;
    long stride = (long)gridDim.x * 256;
    for (; i < n; i += stride) split_store(W[i], hi, lo, i);
}

// ---------------- block reductions ------------------------------------------
__device__ __forceinline__ float blockSum(float v, float* red) {
    int tid = threadIdx.x;
    red[tid] = v; __syncthreads();
    for (int s = 128; s > 0; s >>= 1) {
        if (tid < s) red[tid] += red[tid + s];
        __syncthreads();
    }
    float r = red[0]; __syncthreads();
    return r;
}

// ---------------- embeddings + layernorm + mask + split ---------------------
__global__ __launch_bounds__(256)
void embed_ln_kernel(const int* __restrict__ ids, const int* __restrict__ tids,
                     const float* __restrict__ we, const float* __restrict__ pe,
                     const float* __restrict__ te, const float* __restrict__ sc,
                     const float* __restrict__ bi, float* __restrict__ out,
                     bf16* __restrict__ ohi, bf16* __restrict__ olo,
                     float* __restrict__ mask)
{
    __shared__ float red[256];
    int row = blockIdx.x, s = row % SS, tid = threadIdx.x;
    int id = ids[row], tt = tids[row];
    if (tid == 0) mask[row] = (id == 0) ? -10000.0f : 0.0f;
    float v[3]; float sum = 0.f;
    #pragma unroll
    for (int i = 0; i < 3; i++) {
        int j = tid + i * 256;
        v[i] = we[(long)id * HH + j] + pe[s * HH + j] + te[tt * HH + j];
        sum += v[i];
    }
    float mu = blockSum(sum, red) * (1.0f / HH);
    float s2 = 0.f;
    #pragma unroll
    for (int i = 0; i < 3; i++) { float d = v[i] - mu; s2 += d * d; }
    float inv = rsqrtf(blockSum(s2, red) * (1.0f / HH) + 1e-12f);
    #pragma unroll
    for (int i = 0; i < 3; i++) {
        int j = tid + i * 256;
        float r = (v[i] - mu) * inv * sc[j] + bi[j];
        long o = (long)row * HH + j;
        out[o] = r;
        split_store(r, ohi, olo, o);
    }
}

// ---------------- residual add + layernorm + split ---------------------------
__global__ __launch_bounds__(256)
void add_ln_kernel(const float* __restrict__ x, const float* __restrict__ t,
                   const float* __restrict__ sc, const float* __restrict__ bi,
                   float* __restrict__ out, bf16* __restrict__ ohi,
                   bf16* __restrict__ olo)
{
    __shared__ float red[256];
    int row = blockIdx.x, tid = threadIdx.x;
    float v[3]; float sum = 0.f;
    #pragma unroll
    for (int i = 0; i < 3; i++) {
        int j = tid + i * 256;
        v[i] = x[(long)row * HH + j] + t[(long)row * HH + j];
        sum += v[i];
    }
    float mu = blockSum(sum, red) * (1.0f / HH);
    float s2 = 0.f;
    #pragma unroll
    for (int i = 0; i < 3; i++) { float d = v[i] - mu; s2 += d * d; }
    float inv = rsqrtf(blockSum(s2, red) * (1.0f / HH) + 1e-12f);
    #pragma unroll
    for (int i = 0; i < 3; i++) {
        int j = tid + i * 256;
        float r = (v[i] - mu) * inv * sc[j] + bi[j];
        long o = (long)row * HH + j;
        out[o] = r;
        split_store(r, ohi, olo, o);
    }
}

// ---------------- softmax (512) + split to bf16 hi/lo ------------------------
__global__ __launch_bounds__(256)
void softmax512_split(const float* __restrict__ p, bf16* __restrict__ phi,
                      bf16* __restrict__ plo)
{
    __shared__ float red[256];
    long base = (long)blockIdx.x * SS;
    int tid = threadIdx.x;
    float a = p[base + tid], b = p[base + tid + 256];
    red[tid] = fmaxf(a, b); __syncthreads();
    for (int s = 128; s > 0; s >>= 1) {
        if (tid < s) red[tid] = fmaxf(red[tid], red[tid + s]);
        __syncthreads();
    }
    float m = red[0]; __syncthreads();
    float e0 = __expf(a - m), e1 = __expf(b - m);
    red[tid] = e0 + e1; __syncthreads();
    for (int s = 128; s > 0; s >>= 1) {
        if (tid < s) red[tid] += red[tid + s];
        __syncthreads();
    }
    float inv = 1.0f / red[0];
    split_store(e0 * inv, phi, plo, base + tid);
    split_store(e1 * inv, phi, plo, base + tid + 256);
}

// ---------------------------------------------------------------------------
extern "C" void kernel_launch(void* const* d_in, const int* in_sizes, int n_in,
                              void* d_out, int out_size)
{
    const int*   ids  = (const int*)  d_in[0];
    const int*   tids = (const int*)  d_in[1];
    const float* we   = (const float*)d_in[2];
    const float* pe   = (const float*)d_in[3];
    const float* te   = (const float*)d_in[4];
    const float* esc  = (const float*)d_in[5];
    const float* ebi  = (const float*)d_in[6];
    const float* wq   = (const float*)d_in[7];
    const float* bq   = (const float*)d_in[8];
    const float* wk   = (const float*)d_in[9];
    const float* bk   = (const float*)d_in[10];
    const float* wv   = (const float*)d_in[11];
    const float* bv   = (const float*)d_in[12];
    const float* wo   = (const float*)d_in[13];
    const float* bo   = (const float*)d_in[14];
    const float* l1s  = (const float*)d_in[15];
    const float* l1b  = (const float*)d_in[16];
    const float* w1   = (const float*)d_in[17];
    const float* b1   = (const float*)d_in[18];
    const float* w2   = (const float*)d_in[19];
    const float* b2   = (const float*)d_in[20];
    const float* l2s  = (const float*)d_in[21];
    const float* l2b  = (const float*)d_in[22];
    float* out = (float*)d_out;

    float *h, *tmp, *sc, *mask;
    bf16 *h_hi, *h_lo, *q_hi, *q_lo, *k_hi, *k_lo, *v_hi, *v_lo;
    bf16 *c_hi, *c_lo, *a_hi, *a_lo, *p_hi, *p_lo;
    bf16 *wo_hi, *wo_lo, *w1_hi, *w1_lo, *w2_hi, *w2_lo;
    cudaGetSymbolAddress((void**)&h,    g_h);
    cudaGetSymbolAddress((void**)&tmp,  g_tmp);
    cudaGetSymbolAddress((void**)&sc,   g_sc);
    cudaGetSymbolAddress((void**)&mask, g_mask);
    cudaGetSymbolAddress((void**)&h_hi,  g_h_hi);  cudaGetSymbolAddress((void**)&h_lo,  g_h_lo);
    cudaGetSymbolAddress((void**)&q_hi,  g_q_hi);  cudaGetSymbolAddress((void**)&q_lo,  g_q_lo);
    cudaGetSymbolAddress((void**)&k_hi,  g_k_hi);  cudaGetSymbolAddress((void**)&k_lo,  g_k_lo);
    cudaGetSymbolAddress((void**)&v_hi,  g_v_hi);  cudaGetSymbolAddress((void**)&v_lo,  g_v_lo);
    cudaGetSymbolAddress((void**)&c_hi,  g_c_hi);  cudaGetSymbolAddress((void**)&c_lo,  g_c_lo);
    cudaGetSymbolAddress((void**)&a_hi,  g_a_hi);  cudaGetSymbolAddress((void**)&a_lo,  g_a_lo);
    cudaGetSymbolAddress((void**)&p_hi,  g_p_hi);  cudaGetSymbolAddress((void**)&p_lo,  g_p_lo);
    cudaGetSymbolAddress((void**)&wo_hi, g_wo_hi); cudaGetSymbolAddress((void**)&wo_lo, g_wo_lo);
    cudaGetSymbolAddress((void**)&w1_hi, g_w1_hi); cudaGetSymbolAddress((void**)&w1_lo, g_w1_lo);
    cudaGetSymbolAddress((void**)&w2_hi, g_w2_hi); cudaGetSymbolAddress((void**)&w2_lo, g_w2_lo);

    // dynamic smem: STAGES * (2*A + 2*B)
    const int SM_KM = 3 * (2 * 10240 + 2 * 32 * 136 * 2);   // k-major NT=128: 113664
    const int SM_NT = 2 * (2 * 10240 + 2 * 10240);          // n-major NT=128: 81920
    const int SM_CX = 3 * (2 * 10240 + 2 * 32 * 72 * 2);    // k-major NT=64:  89088
    cudaFuncSetAttribute((const void*)mma_gemm<128, EPI_QK,     false, 3, true >, cudaFuncAttributeMaxDynamicSharedMemorySize, SM_KM);
    cudaFuncSetAttribute((const void*)mma_gemm<128, EPI_F32,    false, 3, false>, cudaFuncAttributeMaxDynamicSharedMemorySize, SM_KM);
    cudaFuncSetAttribute((const void*)mma_gemm<128, EPI_GELU,   false, 3, false>, cudaFuncAttributeMaxDynamicSharedMemorySize, SM_KM);
    cudaFuncSetAttribute((const void*)mma_gemm<128, EPI_SCORES, true,  2, false>, cudaFuncAttributeMaxDynamicSharedMemorySize, SM_NT);
    cudaFuncSetAttribute((const void*)mma_gemm<64,  EPI_CTX,    false, 3, false>, cudaFuncAttributeMaxDynamicSharedMemorySize, SM_CX);

    const dim3 gQKV(HH / 128, BSN / 128, 3);    // (6, 32, 3) fused QKV
    const dim3 gQ1 (HH / 128, BSN / 128, 1);    // profile duplicate (Q only)
    const dim3 gHH (HH / 128, BSN / 128, 1);    // (6, 32)
    const dim3 gFF (FF / 128, BSN / 128, 1);    // (24, 32)
    const dim3 gSC (SS / 128, SS / 128, ZH);    // (4, 4, 96)
    const dim3 gCX (1, SS / 128, ZH);           // (1, 4, 96)

    // launch 0: embeddings
    embed_ln_kernel<<<BSN, 256>>>(ids, tids, we, pe, te, esc, ebi, h, h_hi, h_lo, mask);
    // launch 1: attention weight splits (fused)
    wsplit4_kernel<<<dim3(2048, 1, 4), 256>>>(wq, wk, wv, wo, (long)LL * HH * HH);

    for (int l = 0; l < LL; l++) {
        long wOff = (long)l * HH * HH, bOff = (long)l * HH;
        long w1Off = (long)l * HH * FF, b1Off = (long)l * FF;

        // launches 2..5 (l==0): fused QKV + 3 idempotent dups — ncu -s 5 target
        mma_gemm<128, EPI_QK, false, 3, true><<<gQKV, 256, SM_KM>>>(
            h_hi, h_lo, nullptr, nullptr, bq + bOff, bk + bOff, bv + bOff,
            nullptr, nullptr, nullptr, nullptr, BSN, HH, HH, 0, wOff);
        if (l == 0) {
            for (int d = 0; d < 3; d++)
                mma_gemm<128, EPI_QK, false, 3, true><<<gQ1, 256, SM_KM>>>(
                    h_hi, h_lo, nullptr, nullptr, bq, bk, bv,
                    nullptr, nullptr, nullptr, nullptr, BSN, HH, HH, 0, 0);
            // FFN weight splits (fused; needed before layer-0 FFN1)
            wsplit2_kernel<<<dim3(4096, 1, 2), 256>>>(w1, w2, (long)LL * HH * FF);
        }

        // scores: A = Q [z][S][D], B = K [z][S][D] (NT gemm)
        mma_gemm<128, EPI_SCORES, true, 2, false><<<gSC, 256, SM_NT>>>(
            q_hi, q_lo, k_hi, k_lo, nullptr, nullptr, nullptr, mask,
            sc, nullptr, nullptr, SS, SS, DD, (long)SS * DD, (long)SS * DD);

        softmax512_split<<<ZH * SS, 256>>>(sc, p_hi, p_lo);

        // ctx: A = P [z][S][S], B = V [z][S][D] (k-major)
        mma_gemm<64, EPI_CTX, false, 3, false><<<gCX, 256, SM_CX>>>(
            p_hi, p_lo, v_hi, v_lo, nullptr, nullptr, nullptr, nullptr,
            nullptr, c_hi, c_lo, SS, DD, SS, (long)SS * SS, (long)SS * DD);

        mma_gemm<128, EPI_F32, false, 3, false><<<gHH, 256, SM_KM>>>(
            c_hi, c_lo, wo_hi + wOff, wo_lo + wOff, bo + bOff, nullptr, nullptr,
            nullptr, tmp, nullptr, nullptr, BSN, HH, HH, 0, 0);
        add_ln_kernel<<<BSN, 256>>>(h, tmp, l1s + bOff, l1b + bOff, h, h_hi, h_lo);

        mma_gemm<128, EPI_GELU, false, 3, false><<<gFF, 256, SM_KM>>>(
            h_hi, h_lo, w1_hi + w1Off, w1_lo + w1Off, b1 + b1Off, nullptr, nullptr,
            nullptr, nullptr, a_hi, a_lo, BSN, FF, HH, 0, 0);
        mma_gemm<128, EPI_F32, false, 3, false><<<gHH, 256, SM_KM>>>(
            a_hi, a_lo, w2_hi + w1Off, w2_lo + w1Off, b2 + bOff, nullptr, nullptr,
            nullptr, tmp, nullptr, nullptr, BSN, HH, FF, 0, 0);

        add_ln_kernel<<<BSN, 256>>>(h, tmp, l2s + bOff, l2b + bOff,
                                    (l == LL - 1) ? out : h, h_hi, h_lo);
    }
}

// round 11
// speedup vs baseline: 2.6360x; 1.0990x over previous
#include <cuda_runtime.h>
#include <cuda_bf16.h>
#include <cstdint>

// ---------------------------------------------------------------------------
// BERT-base encoder forward, split-bf16 mma.sync (HMMA) GEMMs. sm_103-safe PTX.
// B=8, S=512, H=768, NH=12, D=64, F=3072, L=12
// ---------------------------------------------------------------------------

#define BB   8
#define SS   512
#define HH   768
#define NHH  12
#define DD   64
#define FF   3072
#define LL   12
#define BSN  (BB*SS)          // 4096 tokens
#define ZH   (BB*NHH)         // 96

typedef __nv_bfloat16 bf16;

// ---------------- scratch (device globals; no allocations) -----------------
__device__ float g_h  [BSN*HH];
__device__ float g_tmp[3L*BSN*HH];          // split-K partials (3 slices)
__device__ float g_sc [(long)ZH*SS*SS];     // attention logits fp32 (~100MB)
__device__ float g_mask[BSN];

__device__ bf16 g_h_hi[BSN*HH],  g_h_lo[BSN*HH];
__device__ bf16 g_q_hi[BSN*HH],  g_q_lo[BSN*HH];    // [z][S][D]
__device__ bf16 g_k_hi[BSN*HH],  g_k_lo[BSN*HH];    // [z][S][D]
__device__ bf16 g_v_hi[BSN*HH],  g_v_lo[BSN*HH];    // [z][S][D]
__device__ bf16 g_c_hi[BSN*HH],  g_c_lo[BSN*HH];    // ctx [B*S][H]
__device__ bf16 g_a_hi[BSN*FF],  g_a_lo[BSN*FF];    // ffn act
__device__ bf16 g_p_hi[(long)ZH*SS*SS], g_p_lo[(long)ZH*SS*SS]; // probs

__device__ bf16 g_wq_hi[LL*HH*HH], g_wq_lo[LL*HH*HH];
__device__ bf16 g_wk_hi[LL*HH*HH], g_wk_lo[LL*HH*HH];
__device__ bf16 g_wv_hi[LL*HH*HH], g_wv_lo[LL*HH*HH];
__device__ bf16 g_wo_hi[LL*HH*HH], g_wo_lo[LL*HH*HH];
__device__ bf16 g_w1_hi[(long)LL*HH*FF], g_w1_lo[(long)LL*HH*FF];
__device__ bf16 g_w2_hi[(long)LL*FF*HH], g_w2_lo[(long)LL*FF*HH];

// ---------------- small helpers --------------------------------------------
__device__ __forceinline__ uint32_t smem_u32(const void* p) {
    uint32_t a;
    asm("{ .reg .u64 t; cvta.to.shared.u64 t, %1; cvt.u32.u64 %0, t; }" : "=r"(a) : "l"(p));
    return a;
}
__device__ __forceinline__ void cpasync16(uint32_t s, const void* g) {
    asm volatile("cp.async.cg.shared.global [%0], [%1], 16;" :: "r"(s), "l"(g) : "memory");
}
#define CP_COMMIT() asm volatile("cp.async.commit_group;" ::: "memory")
#define CP_WAIT0()  asm volatile("cp.async.wait_group 0;" ::: "memory")
#define CP_WAIT1()  asm volatile("cp.async.wait_group 1;" ::: "memory")
#define CP_WAIT2()  asm volatile("cp.async.wait_group 2;" ::: "memory")

__device__ __forceinline__ void ldsm4(uint32_t& r0, uint32_t& r1, uint32_t& r2,
                                      uint32_t& r3, uint32_t addr) {
    asm volatile("ldmatrix.sync.aligned.m8n8.x4.shared.b16 {%0,%1,%2,%3}, [%4];"
                 : "=r"(r0), "=r"(r1), "=r"(r2), "=r"(r3) : "r"(addr));
}
__device__ __forceinline__ void ldsm4t(uint32_t& r0, uint32_t& r1, uint32_t& r2,
                                       uint32_t& r3, uint32_t addr) {
    asm volatile("ldmatrix.sync.aligned.m8n8.x4.trans.shared.b16 {%0,%1,%2,%3}, [%4];"
                 : "=r"(r0), "=r"(r1), "=r"(r2), "=r"(r3) : "r"(addr));
}
__device__ __forceinline__ void mma16816(float* c, const uint32_t* a,
                                         uint32_t b0, uint32_t b1) {
    asm("mma.sync.aligned.m16n8k16.row.col.f32.bf16.bf16.f32 "
        "{%0,%1,%2,%3}, {%4,%5,%6,%7}, {%8,%9}, {%0,%1,%2,%3};"
        : "+f"(c[0]), "+f"(c[1]), "+f"(c[2]), "+f"(c[3])
        : "r"(a[0]), "r"(a[1]), "r"(a[2]), "r"(a[3]), "r"(b0), "r"(b1));
}
__device__ __forceinline__ void split_store(float v, bf16* __restrict__ hi,
                                            bf16* __restrict__ lo, long o) {
    bf16 h = __float2bfloat16(v);
    hi[o] = h;
    lo[o] = __float2bfloat16(v - __bfloat162float(h));
}

// ---------------------------------------------------------------------------
// mma.sync GEMM: C[M,N] = A[M,K] @ B, A row-major [M][K] (row stride ldA).
// BNT=false: B row-major [K][N] (k-major), loaded with ldmatrix.trans.
// BNT=true : B row-major [N][K] (NT gemm), loaded like A.
// Split hi/lo bf16, 3 products (hh + hl + lh), fp32 accum.
// CTA tile 128 x NT, K-chunk 32, 8 warps, STAGES-deep cp.async pipeline.
// QKV3: gridDim.z = 3 selects {wq->q, wk->k, wv->v} from device globals.
// KSPL>1: split-K over gridDim.z; each part writes outF + z*M*N (no bias).
// ---------------------------------------------------------------------------
#define EPI_F32    0
#define EPI_GELU   1
#define EPI_QK     2   // bias + split scatter [z][S][D]     (Q, K, V)
#define EPI_SCORES 4   // *0.125 + mask, fp32 [z][S][S]
#define EPI_CTX    5   // split merge heads -> [B*S, H]
#define EPI_PART   6   // raw fp32 partial (split-K), no bias

template<int NT, int EPI, bool BNT, int STAGES, bool QKV3, int KSPL>
__global__ __launch_bounds__(256, 2)
void mma_gemm(const bf16* Ahi, const bf16* Alo,
              const bf16* Bhi, const bf16* Blo,
              const float* bias, const float* bias2, const float* bias3,
              const float* mask,
              float* outF, bf16* outHi, bf16* outLo,
              int M, int N, int K, int ldA, long sAz, long sBz)
{
    constexpr int WARPS_N = (NT == 128) ? 4 : 2;
    constexpr int WM = (NT == 128) ? 64 : 32;        // warp tile M
    constexpr int MT = WM / 16;                      // m-tiles (4 or 2)
    constexpr int LDA_S = 40;                        // A smem row elems (32+8)
    constexpr int ABYTES = 128 * LDA_S * 2;          // 10240
    constexpr int LDB_S = BNT ? 40 : (NT + 8);       // B smem row elems
    constexpr int BBYTES = BNT ? (NT * LDA_S * 2) : (32 * LDB_S * 2);
    constexpr int OAH = 0, OAL = ABYTES;
    constexpr int OBH = 2 * ABYTES;
    constexpr int OBL = 2 * ABYTES + BBYTES;
    constexpr int BUFB = 2 * ABYTES + 2 * BBYTES;

    extern __shared__ char smem[];
    const uint32_t sb = smem_u32(smem);

    const int tid = threadIdx.x, wid = tid >> 5, lane = tid & 31;
    const int wm = wid / WARPS_N, wn = wid % WARPS_N;
    const int z = blockIdx.z;
    int Kloop = K;
    if constexpr (QKV3) {
        if (z == 1)      { Bhi = g_wk_hi + sBz; Blo = g_wk_lo + sBz; bias = bias2; outHi = g_k_hi; outLo = g_k_lo; }
        else if (z == 2) { Bhi = g_wv_hi + sBz; Blo = g_wv_lo + sBz; bias = bias3; outHi = g_v_hi; outLo = g_v_lo; }
        else             { Bhi = g_wq_hi + sBz; Blo = g_wq_lo + sBz;               outHi = g_q_hi; outLo = g_q_lo; }
    } else if constexpr (KSPL > 1) {
        int koff = z * (K / KSPL);
        Ahi += koff;             Alo += koff;
        Bhi += (long)koff * N;   Blo += (long)koff * N;
        outF += (long)z * M * N;
        Kloop = K / KSPL;
    } else {
        Ahi += (long)z * sAz;  Alo += (long)z * sAz;
        Bhi += (long)z * sBz;  Blo += (long)z * sBz;
    }
    const int bm0 = blockIdx.y * 128;
    const int bn0 = blockIdx.x * NT;

    // ---- async tile loader ----
    auto load_chunk = [&](int buf, int k0) {
        uint32_t base = sb + buf * BUFB;
        #pragma unroll
        for (int i = 0; i < 2; i++) {                 // A: 512 16B chunks
            int idx = tid + i * 256;
            int r = idx >> 2, c = idx & 3;
            long go = (long)(bm0 + r) * ldA + k0 + c * 8;
            uint32_t so = r * (LDA_S * 2) + c * 16;
            cpasync16(base + OAH + so, Ahi + go);
            cpasync16(base + OAL + so, Alo + go);
        }
        if (BNT) {
            #pragma unroll
            for (int i = 0; i < NT * 4 / 256; i++) {
                int idx = tid + i * 256;
                int r = idx >> 2, c = idx & 3;
                long go = (long)(bn0 + r) * K + k0 + c * 8;
                uint32_t so = r * (LDA_S * 2) + c * 16;
                cpasync16(base + OBH + so, Bhi + go);
                cpasync16(base + OBL + so, Blo + go);
            }
        } else {
            constexpr int BCH = NT / 8;               // 16B chunks per B row
            #pragma unroll
            for (int i = 0; i < 32 * BCH / 256; i++) {
                int idx = tid + i * 256;
                int r = idx / BCH, c = idx % BCH;
                long go = (long)(k0 + r) * N + bn0 + c * 8;
                uint32_t so = r * (LDB_S * 2) + c * 16;
                cpasync16(base + OBH + so, Bhi + go);
                cpasync16(base + OBL + so, Blo + go);
            }
        }
        CP_COMMIT();
    };

    float acc[MT][4][4];
    #pragma unroll
    for (int i = 0; i < MT; i++)
        #pragma unroll
        for (int j = 0; j < 4; j++)
            #pragma unroll
            for (int e = 0; e < 4; e++) acc[i][j][e] = 0.f;

    const int nkc = Kloop >> 5;
    #pragma unroll
    for (int s = 0; s < STAGES - 1; s++)
        if (s < nkc) load_chunk(s, s * 32);

    const int arow = wm * WM + (lane & 15);
    const int acol8 = (lane >> 4) << 3;

    for (int kc = 0; kc < nkc; kc++) {
        // wait for stage kc, one barrier, then refill stage consumed at kc-1
        {
            int pend = STAGES - 2;
            if (nkc - 1 - kc < pend) pend = nkc - 1 - kc;
            if (pend >= 2) { CP_WAIT2(); } else if (pend == 1) { CP_WAIT1(); }
            else           { CP_WAIT0(); }
        }
        __syncthreads();
        if (kc + STAGES - 1 < nkc)
            load_chunk((kc + STAGES - 1) % STAGES, (kc + STAGES - 1) * 32);

        const uint32_t base = sb + (kc % STAGES) * BUFB;

        auto loadB = [&](uint32_t (&bf)[4][2], uint32_t off, int k0s) {
            uint32_t r0, r1, r2, r3;
            if (BNT) {
                #pragma unroll
                for (int half = 0; half < 2; half++) {
                    uint32_t bo = (uint32_t)((wn * 32 + half * 16 + (lane & 15)) * (LDA_S * 2)
                                             + (k0s + acol8) * 2);
                    ldsm4(r0, r1, r2, r3, base + off + bo);
                    bf[half*2+0][0] = r0; bf[half*2+0][1] = r2;
                    bf[half*2+1][0] = r1; bf[half*2+1][1] = r3;
                }
            } else {
                const int brow = lane & 15;
                const int bcol8 = wn * 32 + ((lane >> 4) << 3);
                #pragma unroll
                for (int np = 0; np < 2; np++) {
                    uint32_t bo = (uint32_t)((k0s + brow) * (LDB_S * 2)
                                             + (bcol8 + np * 16) * 2);
                    ldsm4t(r0, r1, r2, r3, base + off + bo);
                    bf[np*2+0][0] = r0; bf[np*2+0][1] = r1;
                    bf[np*2+1][0] = r2; bf[np*2+1][1] = r3;
                }
            }
        };

        #pragma unroll
        for (int ks = 0; ks < 2; ks++) {
            const int k0s = ks * 16;
            uint32_t af[MT][4];            // A fragment: hi first, reused for lo
            uint32_t bfh[4][2], bfl[4][2];
            #pragma unroll
            for (int mt = 0; mt < MT; mt++) {
                uint32_t ao = (uint32_t)((arow + mt * 16) * (LDA_S * 2)
                                         + (k0s + acol8) * 2);
                ldsm4(af[mt][0], af[mt][1], af[mt][2], af[mt][3], base + OAH + ao);
            }
            loadB(bfh, OBH, k0s);
            loadB(bfl, OBL, k0s);
            #pragma unroll
            for (int j = 0; j < 4; j++)
                #pragma unroll
                for (int mt = 0; mt < MT; mt++)
                    mma16816(acc[mt][j], af[mt], bfh[j][0], bfh[j][1]);
            #pragma unroll
            for (int j = 0; j < 4; j++)
                #pragma unroll
                for (int mt = 0; mt < MT; mt++)
                    mma16816(acc[mt][j], af[mt], bfl[j][0], bfl[j][1]);
            #pragma unroll
            for (int mt = 0; mt < MT; mt++) {
                uint32_t ao = (uint32_t)((arow + mt * 16) * (LDA_S * 2)
                                         + (k0s + acol8) * 2);
                ldsm4(af[mt][0], af[mt][1], af[mt][2], af[mt][3], base + OAL + ao);
            }
            #pragma unroll
            for (int j = 0; j < 4; j++)
                #pragma unroll
                for (int mt = 0; mt < MT; mt++)
                    mma16816(acc[mt][j], af[mt], bfh[j][0], bfh[j][1]);
        }
    }

    // ---- epilogue ----
    const int zb = z / NHH, zh = z % NHH;
    #pragma unroll
    for (int nt = 0; nt < 4; nt++) {
        const int colb = bn0 + wn * 32 + nt * 8 + 2 * (lane & 3);
        float b0 = 0.f, b1 = 0.f;
        if (EPI == EPI_F32 || EPI == EPI_GELU || EPI == EPI_QK) {
            b0 = __ldg(&bias[colb]); b1 = __ldg(&bias[colb + 1]);
        } else if (EPI == EPI_SCORES) {
            b0 = __ldg(&mask[zb * SS + colb]); b1 = __ldg(&mask[zb * SS + colb + 1]);
        }
        #pragma unroll
        for (int mt = 0; mt < MT; mt++) {
            const int rA = bm0 + wm * WM + mt * 16 + (lane >> 2);
            #pragma unroll
            for (int e = 0; e < 4; e++) {
                int R   = rA + (e >> 1) * 8;
                int col = colb + (e & 1);
                float bb = (e & 1) ? b1 : b0;
                float v = acc[mt][nt][e];
                if (EPI == EPI_F32) {
                    v += bb;
                    outF[(long)R * N + col] = v;
                } else if (EPI == EPI_PART) {
                    outF[(long)R * N + col] = v;
                } else if (EPI == EPI_GELU) {
                    v += bb;
                    v = 0.5f * v * (1.0f + erff(v * 0.70710678118654752f));
                    split_store(v, outHi, outLo, (long)R * N + col);
                } else if (EPI == EPI_QK) {
                    v += bb;
                    int bi = R >> 9, s = R & 511, hh = col >> 6, d = col & 63;
                    long o = (((long)(bi * NHH + hh)) * SS + s) * DD + d;
                    split_store(v, outHi, outLo, o);
                } else if (EPI == EPI_SCORES) {
                    v = v * 0.125f + bb;
                    outF[((long)z * SS + R) * SS + col] = v;
                } else {  // EPI_CTX
                    long o = ((long)(zb * SS + R)) * HH + zh * DD + col;
                    split_store(v, outHi, outLo, o);
                }
            }
        }
    }
}

// ---------------- fused weight splits (z selects tensor) --------------------
__global__ __launch_bounds__(256)
void wsplit4_kernel(const float* __restrict__ a0, const float* __restrict__ a1,
                    const float* __restrict__ a2, const float* __restrict__ a3,
                    long n)
{
    int zs = blockIdx.z;
    const float* W = (zs == 0) ? a0 : (zs == 1) ? a1 : (zs == 2) ? a2 : a3;
    bf16* hi = (zs == 0) ? g_wq_hi : (zs == 1) ? g_wk_hi : (zs == 2) ? g_wv_hi : g_wo_hi;
    bf16* lo = (zs == 0) ? g_wq_lo : (zs == 1) ? g_wk_lo : (zs == 2) ? g_wv_lo : g_wo_lo;
    long i = (long)blockIdx.x * 256 + threadIdx.x;
    long stride = (long)gridDim.x * 256;
    for (; i < n; i += stride) split_store(W[i], hi, lo, i);
}
__global__ __launch_bounds__(256)
void wsplit2_kernel(const float* __restrict__ a0, const float* __restrict__ a1, long n)
{
    int zs = blockIdx.z;
    const float* W = (zs == 0) ? a0 : a1;
    bf16* hi = (zs == 0) ? g_w1_hi : g_w2_hi;
    bf16* lo = (zs == 0) ? g_w1_lo : g_w2_lo;
    long i = (long)blockIdx.x * 256 + threadIdx.x;
    long stride = (long)gridDim.x * 256;
    for (; i < n; i += stride) split_store(W[i], hi, lo, i);
}

// ---------------- block reductions ------------------------------------------
__device__ __forceinline__ float blockSum(float v, float* red) {
    int tid = threadIdx.x;
    red[tid] = v; __syncthreads();
    for (int s = 128; s > 0; s >>= 1) {
        if (tid < s) red[tid] += red[tid + s];
        __syncthreads();
    }
    float r = red[0]; __syncthreads();
    return r;
}

// ---------------- embeddings + layernorm + mask + split ---------------------
__global__ __launch_bounds__(256)
void embed_ln_kernel(const int* __restrict__ ids, const int* __restrict__ tids,
                     const float* __restrict__ we, const float* __restrict__ pe,
                     const float* __restrict__ te, const float* __restrict__ sc,
                     const float* __restrict__ bi, float* __restrict__ out,
                     bf16* __restrict__ ohi, bf16* __restrict__ olo,
                     float* __restrict__ mask)
{
    __shared__ float red[256];
    int row = blockIdx.x, s = row % SS, tid = threadIdx.x;
    int id = ids[row], tt = tids[row];
    if (tid == 0) mask[row] = (id == 0) ? -10000.0f : 0.0f;
    float v[3]; float sum = 0.f;
    #pragma unroll
    for (int i = 0; i < 3; i++) {
        int j = tid + i * 256;
        v[i] = we[(long)id * HH + j] + pe[s * HH + j] + te[tt * HH + j];
        sum += v[i];
    }
    float mu = blockSum(sum, red) * (1.0f / HH);
    float s2 = 0.f;
    #pragma unroll
    for (int i = 0; i < 3; i++) { float d = v[i] - mu; s2 += d * d; }
    float inv = rsqrtf(blockSum(s2, red) * (1.0f / HH) + 1e-12f);
    #pragma unroll
    for (int i = 0; i < 3; i++) {
        int j = tid + i * 256;
        float r = (v[i] - mu) * inv * sc[j] + bi[j];
        long o = (long)row * HH + j;
        out[o] = r;
        split_store(r, ohi, olo, o);
    }
}

// ---------------- residual + 3 split-K partials + bias + layernorm -----------
__global__ __launch_bounds__(256)
void add_ln3_kernel(const float* __restrict__ x, const float* __restrict__ t,
                    const float* __restrict__ pb, const float* __restrict__ sc,
                    const float* __restrict__ bi, float* __restrict__ out,
                    bf16* __restrict__ ohi, bf16* __restrict__ olo)
{
    __shared__ float red[256];
    int row = blockIdx.x, tid = threadIdx.x;
    const float *t1 = t + (long)BSN * HH, *t2 = t + 2L * BSN * HH;
    float v[3]; float sum = 0.f;
    #pragma unroll
    for (int i = 0; i < 3; i++) {
        int j = tid + i * 256;
        long o = (long)row * HH + j;
        v[i] = x[o] + t[o] + t1[o] + t2[o] + pb[j];
        sum += v[i];
    }
    float mu = blockSum(sum, red) * (1.0f / HH);
    float s2 = 0.f;
    #pragma unroll
    for (int i = 0; i < 3; i++) { float d = v[i] - mu; s2 += d * d; }
    float inv = rsqrtf(blockSum(s2, red) * (1.0f / HH) + 1e-12f);
    #pragma unroll
    for (int i = 0; i < 3; i++) {
        int j = tid + i * 256;
        float r = (v[i] - mu) * inv * sc[j] + bi[j];
        long o = (long)row * HH + j;
        out[o] = r;
        split_store(r, ohi, olo, o);
    }
}

// ---------------- softmax (512) + split to bf16 hi/lo ------------------------
__global__ __launch_bounds__(256)
void softmax512_split(const float* __restrict__ p, bf16* __restrict__ phi,
                      bf16* __restrict__ plo)
{
    __shared__ float red[256];
    long base = (long)blockIdx.x * SS;
    int tid = threadIdx.x;
    float a = p[base + tid], b = p[base + tid + 256];
    red[tid] = fmaxf(a, b); __syncthreads();
    for (int s = 128; s > 0; s >>= 1) {
        if (tid < s) red[tid] = fmaxf(red[tid], red[tid + s]);
        __syncthreads();
    }
    float m = red[0]; __syncthreads();
    float e0 = __expf(a - m), e1 = __expf(b - m);
    red[tid] = e0 + e1; __syncthreads();
    for (int s = 128; s > 0; s >>= 1) {
        if (tid < s) red[tid] += red[tid + s];
        __syncthreads();
    }
    float inv = 1.0f / red[0];
    split_store(e0 * inv, phi, plo, base + tid);
    split_store(e1 * inv, phi, plo, base + tid + 256);
}

// ---------------------------------------------------------------------------
extern "C" void kernel_launch(void* const* d_in, const int* in_sizes, int n_in,
                              void* d_out, int out_size)
{
    const int*   ids  = (const int*)  d_in[0];
    const int*   tids = (const int*)  d_in[1];
    const float* we   = (const float*)d_in[2];
    const float* pe   = (const float*)d_in[3];
    const float* te   = (const float*)d_in[4];
    const float* esc  = (const float*)d_in[5];
    const float* ebi  = (const float*)d_in[6];
    const float* wq   = (const float*)d_in[7];
    const float* bq   = (const float*)d_in[8];
    const float* wk   = (const float*)d_in[9];
    const float* bk   = (const float*)d_in[10];
    const float* wv   = (const float*)d_in[11];
    const float* bv   = (const float*)d_in[12];
    const float* wo   = (const float*)d_in[13];
    const float* bo   = (const float*)d_in[14];
    const float* l1s  = (const float*)d_in[15];
    const float* l1b  = (const float*)d_in[16];
    const float* w1   = (const float*)d_in[17];
    const float* b1   = (const float*)d_in[18];
    const float* w2   = (const float*)d_in[19];
    const float* b2   = (const float*)d_in[20];
    const float* l2s  = (const float*)d_in[21];
    const float* l2b  = (const float*)d_in[22];
    float* out = (float*)d_out;

    float *h, *tmp, *sc, *mask;
    bf16 *h_hi, *h_lo, *q_hi, *q_lo, *k_hi, *k_lo, *v_hi, *v_lo;
    bf16 *c_hi, *c_lo, *a_hi, *a_lo, *p_hi, *p_lo;
    bf16 *wo_hi, *wo_lo, *w1_hi, *w1_lo, *w2_hi, *w2_lo;
    cudaGetSymbolAddress((void**)&h,    g_h);
    cudaGetSymbolAddress((void**)&tmp,  g_tmp);
    cudaGetSymbolAddress((void**)&sc,   g_sc);
    cudaGetSymbolAddress((void**)&mask, g_mask);
    cudaGetSymbolAddress((void**)&h_hi,  g_h_hi);  cudaGetSymbolAddress((void**)&h_lo,  g_h_lo);
    cudaGetSymbolAddress((void**)&q_hi,  g_q_hi);  cudaGetSymbolAddress((void**)&q_lo,  g_q_lo);
    cudaGetSymbolAddress((void**)&k_hi,  g_k_hi);  cudaGetSymbolAddress((void**)&k_lo,  g_k_lo);
    cudaGetSymbolAddress((void**)&v_hi,  g_v_hi);  cudaGetSymbolAddress((void**)&v_lo,  g_v_lo);
    cudaGetSymbolAddress((void**)&c_hi,  g_c_hi);  cudaGetSymbolAddress((void**)&c_lo,  g_c_lo);
    cudaGetSymbolAddress((void**)&a_hi,  g_a_hi);  cudaGetSymbolAddress((void**)&a_lo,  g_a_lo);
    cudaGetSymbolAddress((void**)&p_hi,  g_p_hi);  cudaGetSymbolAddress((void**)&p_lo,  g_p_lo);
    cudaGetSymbolAddress((void**)&wo_hi, g_wo_hi); cudaGetSymbolAddress((void**)&wo_lo, g_wo_lo);
    cudaGetSymbolAddress((void**)&w1_hi, g_w1_hi); cudaGetSymbolAddress((void**)&w1_lo, g_w1_lo);
    cudaGetSymbolAddress((void**)&w2_hi, g_w2_hi); cudaGetSymbolAddress((void**)&w2_lo, g_w2_lo);

    // dynamic smem: STAGES * (2*A + 2*B)
    const int SM_KM = 3 * (2 * 10240 + 2 * 32 * 136 * 2);   // k-major NT=128: 113664
    const int SM_NT = 2 * (2 * 10240 + 2 * 10240);          // n-major NT=128: 81920
    const int SM_CX = 3 * (2 * 10240 + 2 * 32 * 72 * 2);    // k-major NT=64:  89088
    cudaFuncSetAttribute((const void*)mma_gemm<128, EPI_QK,     false, 3, true,  1>, cudaFuncAttributeMaxDynamicSharedMemorySize, SM_KM);
    cudaFuncSetAttribute((const void*)mma_gemm<128, EPI_PART,   false, 3, false, 3>, cudaFuncAttributeMaxDynamicSharedMemorySize, SM_KM);
    cudaFuncSetAttribute((const void*)mma_gemm<128, EPI_GELU,   false, 3, false, 1>, cudaFuncAttributeMaxDynamicSharedMemorySize, SM_KM);
    cudaFuncSetAttribute((const void*)mma_gemm<128, EPI_SCORES, true,  2, false, 1>, cudaFuncAttributeMaxDynamicSharedMemorySize, SM_NT);
    cudaFuncSetAttribute((const void*)mma_gemm<64,  EPI_CTX,    false, 3, false, 1>, cudaFuncAttributeMaxDynamicSharedMemorySize, SM_CX);

    const dim3 gQKV(HH / 128, BSN / 128, 3);    // (6, 32, 3) fused QKV
    const dim3 gSK (HH / 128, BSN / 128, 3);    // (6, 32, 3) split-K proj/FFN2
    const dim3 gFF (FF / 128, BSN / 128, 1);    // (24, 32)
    const dim3 gSC (SS / 128, SS / 128, ZH);    // (4, 4, 96)
    const dim3 gCX (1, SS / 128, ZH);           // (1, 4, 96)

    // launch 0: embeddings; 1-2: weight splits; 3: QKV (ncu -s 5, offset 2)
    embed_ln_kernel<<<BSN, 256>>>(ids, tids, we, pe, te, esc, ebi, h, h_hi, h_lo, mask);
    wsplit4_kernel<<<dim3(2048, 1, 4), 256>>>(wq, wk, wv, wo, (long)LL * HH * HH);
    wsplit2_kernel<<<dim3(4096, 1, 2), 256>>>(w1, w2, (long)LL * HH * FF);

    for (int l = 0; l < LL; l++) {
        long wOff = (long)l * HH * HH, bOff = (long)l * HH;
        long w1Off = (long)l * HH * FF, b1Off = (long)l * FF;

        mma_gemm<128, EPI_QK, false, 3, true, 1><<<gQKV, 256, SM_KM>>>(
            h_hi, h_lo, nullptr, nullptr, bq + bOff, bk + bOff, bv + bOff,
            nullptr, nullptr, nullptr, nullptr, BSN, HH, HH, HH, 0, wOff);

        // scores: A = Q [z][S][D], B = K [z][S][D] (NT gemm)
        mma_gemm<128, EPI_SCORES, true, 2, false, 1><<<gSC, 256, SM_NT>>>(
            q_hi, q_lo, k_hi, k_lo, nullptr, nullptr, nullptr, mask,
            sc, nullptr, nullptr, SS, SS, DD, DD, (long)SS * DD, (long)SS * DD);

        softmax512_split<<<ZH * SS, 256>>>(sc, p_hi, p_lo);

        // ctx: A = P [z][S][S], B = V [z][S][D] (k-major)
        mma_gemm<64, EPI_CTX, false, 3, false, 1><<<gCX, 256, SM_CX>>>(
            p_hi, p_lo, v_hi, v_lo, nullptr, nullptr, nullptr, nullptr,
            nullptr, c_hi, c_lo, SS, DD, SS, SS, (long)SS * SS, (long)SS * DD);

        // wo-proj: split-K=3 partials into tmp[0..2]
        mma_gemm<128, EPI_PART, false, 3, false, 3><<<gSK, 256, SM_KM>>>(
            c_hi, c_lo, wo_hi + wOff, wo_lo + wOff, nullptr, nullptr, nullptr,
            nullptr, tmp, nullptr, nullptr, BSN, HH, HH, HH, 0, 0);
        add_ln3_kernel<<<BSN, 256>>>(h, tmp, bo + bOff, l1s + bOff, l1b + bOff,
                                     h, h_hi, h_lo);

        mma_gemm<128, EPI_GELU, false, 3, false, 1><<<gFF, 256, SM_KM>>>(
            h_hi, h_lo, w1_hi + w1Off, w1_lo + w1Off, b1 + b1Off, nullptr, nullptr,
            nullptr, nullptr, a_hi, a_lo, BSN, FF, HH, HH, 0, 0);
        // FFN2: split-K=3 partials into tmp[0..2]
        mma_gemm<128, EPI_PART, false, 3, false, 3><<<gSK, 256, SM_KM>>>(
            a_hi, a_lo, w2_hi + w1Off, w2_lo + w1Off, nullptr, nullptr, nullptr,
            nullptr, tmp, nullptr, nullptr, BSN, HH, FF, FF, 0, 0);
        add_ln3_kernel<<<BSN, 256>>>(h, tmp, b2 + bOff, l2s + bOff, l2b + bOff,
                                     (l == LL - 1) ? out : h, h_hi, h_lo);
    }
}

// round 12
// speedup vs baseline: 3.1236x; 1.1850x over previous
#include <cuda_runtime.h>
#include <cuda_fp16.h>
#include <cstdint>

// ---------------------------------------------------------------------------
// BERT-base encoder forward, split-fp16 mma.sync (HMMA) GEMMs. sm_103-safe PTX.
// Activations: fp16 hi+lo split (exact to 2^-22). Weights: single fp16.
// Projection GEMMs: 2 products (a_hi*w + a_lo*w). Attention GEMMs: 3 products.
// B=8, S=512, H=768, NH=12, D=64, F=3072, L=12
// ---------------------------------------------------------------------------

#define BB   8
#define SS   512
#define HH   768
#define NHH  12
#define DD   64
#define FF   3072
#define LL   12
#define BSN  (BB*SS)          // 4096 tokens
#define ZH   (BB*NHH)         // 96

typedef __half h16;

// ---------------- scratch (device globals; no allocations) -----------------
__device__ float g_h  [BSN*HH];
__device__ float g_tmp[3L*BSN*HH];          // split-K partials (3 slices)
__device__ float g_sc [(long)ZH*SS*SS];     // attention logits fp32 (~100MB)
__device__ float g_mask[BSN];

__device__ h16 g_h_hi[BSN*HH],  g_h_lo[BSN*HH];
__device__ h16 g_q_hi[BSN*HH],  g_q_lo[BSN*HH];    // [z][S][D]
__device__ h16 g_k_hi[BSN*HH],  g_k_lo[BSN*HH];    // [z][S][D]
__device__ h16 g_v_hi[BSN*HH],  g_v_lo[BSN*HH];    // [z][S][D]
__device__ h16 g_c_hi[BSN*HH],  g_c_lo[BSN*HH];    // ctx [B*S][H]
__device__ h16 g_a_hi[BSN*FF],  g_a_lo[BSN*FF];    // ffn act
__device__ h16 g_p_hi[(long)ZH*SS*SS], g_p_lo[(long)ZH*SS*SS]; // probs

__device__ h16 g_wq[LL*HH*HH], g_wk[LL*HH*HH];     // weights: single fp16
__device__ h16 g_wv[LL*HH*HH], g_wo[LL*HH*HH];
__device__ h16 g_w1[(long)LL*HH*FF], g_w2[(long)LL*FF*HH];

// ---------------- small helpers --------------------------------------------
__device__ __forceinline__ uint32_t smem_u32(const void* p) {
    uint32_t a;
    asm("{ .reg .u64 t; cvta.to.shared.u64 t, %1; cvt.u32.u64 %0, t; }" : "=r"(a) : "l"(p));
    return a;
}
__device__ __forceinline__ void cpasync16(uint32_t s, const void* g) {
    asm volatile("cp.async.cg.shared.global [%0], [%1], 16;" :: "r"(s), "l"(g) : "memory");
}
#define CP_COMMIT() asm volatile("cp.async.commit_group;" ::: "memory")
#define CP_WAIT0()  asm volatile("cp.async.wait_group 0;" ::: "memory")
#define CP_WAIT1()  asm volatile("cp.async.wait_group 1;" ::: "memory")
#define CP_WAIT2()  asm volatile("cp.async.wait_group 2;" ::: "memory")

__device__ __forceinline__ void ldsm4(uint32_t& r0, uint32_t& r1, uint32_t& r2,
                                      uint32_t& r3, uint32_t addr) {
    asm volatile("ldmatrix.sync.aligned.m8n8.x4.shared.b16 {%0,%1,%2,%3}, [%4];"
                 : "=r"(r0), "=r"(r1), "=r"(r2), "=r"(r3) : "r"(addr));
}
__device__ __forceinline__ void ldsm4t(uint32_t& r0, uint32_t& r1, uint32_t& r2,
                                       uint32_t& r3, uint32_t addr) {
    asm volatile("ldmatrix.sync.aligned.m8n8.x4.trans.shared.b16 {%0,%1,%2,%3}, [%4];"
                 : "=r"(r0), "=r"(r1), "=r"(r2), "=r"(r3) : "r"(addr));
}
__device__ __forceinline__ void mma16816(float* c, const uint32_t* a,
                                         uint32_t b0, uint32_t b1) {
    asm("mma.sync.aligned.m16n8k16.row.col.f32.f16.f16.f32 "
        "{%0,%1,%2,%3}, {%4,%5,%6,%7}, {%8,%9}, {%0,%1,%2,%3};"
        : "+f"(c[0]), "+f"(c[1]), "+f"(c[2]), "+f"(c[3])
        : "r"(a[0]), "r"(a[1]), "r"(a[2]), "r"(a[3]), "r"(b0), "r"(b1));
}
__device__ __forceinline__ void split_store(float v, h16* __restrict__ hi,
                                            h16* __restrict__ lo, long o) {
    h16 h = __float2half(v);
    hi[o] = h;
    lo[o] = __float2half(v - __half2float(h));
}

// ---------------------------------------------------------------------------
// mma.sync GEMM: C[M,N] = A[M,K] @ B, A row-major [M][K] (row stride ldA).
// BNT=false: B row-major [K][N] (k-major), loaded with ldmatrix.trans.
// BNT=true : B row-major [N][K] (NT gemm), loaded like A.
// A always split hi/lo fp16. BSPLIT: B also split (3 products) else single (2).
// CTA tile 128 x NT, K-chunk 32, 8 warps, STAGES-deep cp.async pipeline.
// QKV3: gridDim.z = 3 selects {wq->q, wk->k, wv->v} from device globals.
// KSPL>1: split-K over gridDim.z; each part writes outF + z*M*N (no bias).
// ---------------------------------------------------------------------------
#define EPI_F32    0
#define EPI_GELU   1
#define EPI_QK     2   // bias + split scatter [z][S][D]     (Q, K, V)
#define EPI_SCORES 4   // *0.125 + mask, fp32 [z][S][S]
#define EPI_CTX    5   // split merge heads -> [B*S, H]
#define EPI_PART   6   // raw fp32 partial (split-K), no bias

template<int NT, int EPI, bool BNT, int STAGES, bool QKV3, int KSPL, bool BSPLIT>
__global__ __launch_bounds__(256, 2)
void mma_gemm(const h16* Ahi, const h16* Alo,
              const h16* Bhi, const h16* Blo,
              const float* bias, const float* bias2, const float* bias3,
              const float* mask,
              float* outF, h16* outHi, h16* outLo,
              int M, int N, int K, int ldA, long sAz, long sBz)
{
    constexpr int WARPS_N = (NT == 128) ? 4 : 2;
    constexpr int WM = (NT == 128) ? 64 : 32;        // warp tile M
    constexpr int MT = WM / 16;                      // m-tiles (4 or 2)
    constexpr int LDA_S = 40;                        // A smem row elems (32+8)
    constexpr int ABYTES = 128 * LDA_S * 2;          // 10240
    constexpr int LDB_S = BNT ? 40 : (NT + 8);       // B smem row elems
    constexpr int BBYT1 = BNT ? (NT * LDA_S * 2) : (32 * LDB_S * 2);
    constexpr int NB    = BSPLIT ? 2 : 1;
    constexpr int OAH = 0, OAL = ABYTES;
    constexpr int OBH = 2 * ABYTES;
    constexpr int OBL = 2 * ABYTES + BBYT1;
    constexpr int BUFB = 2 * ABYTES + NB * BBYT1;

    extern __shared__ char smem[];
    const uint32_t sb = smem_u32(smem);

    const int tid = threadIdx.x, wid = tid >> 5, lane = tid & 31;
    const int wm = wid / WARPS_N, wn = wid % WARPS_N;
    const int z = blockIdx.z;
    int Kloop = K;
    if constexpr (QKV3) {
        if (z == 1)      { Bhi = g_wk + sBz; bias = bias2; outHi = g_k_hi; outLo = g_k_lo; }
        else if (z == 2) { Bhi = g_wv + sBz; bias = bias3; outHi = g_v_hi; outLo = g_v_lo; }
        else             { Bhi = g_wq + sBz;               outHi = g_q_hi; outLo = g_q_lo; }
    } else if constexpr (KSPL > 1) {
        int koff = z * (K / KSPL);
        Ahi += koff;             Alo += koff;
        Bhi += (long)koff * N;
        outF += (long)z * M * N;
        Kloop = K / KSPL;
    } else {
        Ahi += (long)z * sAz;  Alo += (long)z * sAz;
        Bhi += (long)z * sBz;
        if (BSPLIT) Blo += (long)z * sBz;
    }
    const int bm0 = blockIdx.y * 128;
    const int bn0 = blockIdx.x * NT;

    // ---- async tile loader ----
    auto load_chunk = [&](int buf, int k0) {
        uint32_t base = sb + buf * BUFB;
        #pragma unroll
        for (int i = 0; i < 2; i++) {                 // A: 512 16B chunks
            int idx = tid + i * 256;
            int r = idx >> 2, c = idx & 3;
            long go = (long)(bm0 + r) * ldA + k0 + c * 8;
            uint32_t so = r * (LDA_S * 2) + c * 16;
            cpasync16(base + OAH + so, Ahi + go);
            cpasync16(base + OAL + so, Alo + go);
        }
        if (BNT) {
            #pragma unroll
            for (int i = 0; i < NT * 4 / 256; i++) {
                int idx = tid + i * 256;
                int r = idx >> 2, c = idx & 3;
                long go = (long)(bn0 + r) * K + k0 + c * 8;
                uint32_t so = r * (LDA_S * 2) + c * 16;
                cpasync16(base + OBH + so, Bhi + go);
                if (BSPLIT) cpasync16(base + OBL + so, Blo + go);
            }
        } else {
            constexpr int BCH = NT / 8;               // 16B chunks per B row
            #pragma unroll
            for (int i = 0; i < 32 * BCH / 256; i++) {
                int idx = tid + i * 256;
                int r = idx / BCH, c = idx % BCH;
                long go = (long)(k0 + r) * N + bn0 + c * 8;
                uint32_t so = r * (LDB_S * 2) + c * 16;
                cpasync16(base + OBH + so, Bhi + go);
                if (BSPLIT) cpasync16(base + OBL + so, Blo + go);
            }
        }
        CP_COMMIT();
    };

    float acc[MT][4][4];
    #pragma unroll
    for (int i = 0; i < MT; i++)
        #pragma unroll
        for (int j = 0; j < 4; j++)
            #pragma unroll
            for (int e = 0; e < 4; e++) acc[i][j][e] = 0.f;

    const int nkc = Kloop >> 5;
    #pragma unroll
    for (int s = 0; s < STAGES - 1; s++)
        if (s < nkc) load_chunk(s, s * 32);

    const int arow = wm * WM + (lane & 15);
    const int acol8 = (lane >> 4) << 3;

    for (int kc = 0; kc < nkc; kc++) {
        {
            int pend = STAGES - 2;
            if (nkc - 1 - kc < pend) pend = nkc - 1 - kc;
            if (pend >= 2) { CP_WAIT2(); } else if (pend == 1) { CP_WAIT1(); }
            else           { CP_WAIT0(); }
        }
        __syncthreads();
        if (kc + STAGES - 1 < nkc)
            load_chunk((kc + STAGES - 1) % STAGES, (kc + STAGES - 1) * 32);

        const uint32_t base = sb + (kc % STAGES) * BUFB;

        auto loadB = [&](uint32_t (&bf)[4][2], uint32_t off, int k0s) {
            uint32_t r0, r1, r2, r3;
            if (BNT) {
                #pragma unroll
                for (int half = 0; half < 2; half++) {
                    uint32_t bo = (uint32_t)((wn * 32 + half * 16 + (lane & 15)) * (LDA_S * 2)
                                             + (k0s + acol8) * 2);
                    ldsm4(r0, r1, r2, r3, base + off + bo);
                    bf[half*2+0][0] = r0; bf[half*2+0][1] = r2;
                    bf[half*2+1][0] = r1; bf[half*2+1][1] = r3;
                }
            } else {
                const int brow = lane & 15;
                const int bcol8 = wn * 32 + ((lane >> 4) << 3);
                #pragma unroll
                for (int np = 0; np < 2; np++) {
                    uint32_t bo = (uint32_t)((k0s + brow) * (LDB_S * 2)
                                             + (bcol8 + np * 16) * 2);
                    ldsm4t(r0, r1, r2, r3, base + off + bo);
                    bf[np*2+0][0] = r0; bf[np*2+0][1] = r1;
                    bf[np*2+1][0] = r2; bf[np*2+1][1] = r3;
                }
            }
        };

        #pragma unroll
        for (int ks = 0; ks < 2; ks++) {
            const int k0s = ks * 16;
            uint32_t af[MT][4];            // A fragment: hi first, reused for lo
            uint32_t bfh[4][2], bfl[4][2];
            #pragma unroll
            for (int mt = 0; mt < MT; mt++) {
                uint32_t ao = (uint32_t)((arow + mt * 16) * (LDA_S * 2)
                                         + (k0s + acol8) * 2);
                ldsm4(af[mt][0], af[mt][1], af[mt][2], af[mt][3], base + OAH + ao);
            }
            loadB(bfh, OBH, k0s);
            if (BSPLIT) loadB(bfl, OBL, k0s);
            // a_hi * b_hi
            #pragma unroll
            for (int j = 0; j < 4; j++)
                #pragma unroll
                for (int mt = 0; mt < MT; mt++)
                    mma16816(acc[mt][j], af[mt], bfh[j][0], bfh[j][1]);
            // a_hi * b_lo (split-B only)
            if (BSPLIT) {
                #pragma unroll
                for (int j = 0; j < 4; j++)
                    #pragma unroll
                    for (int mt = 0; mt < MT; mt++)
                        mma16816(acc[mt][j], af[mt], bfl[j][0], bfl[j][1]);
            }
            // reload A-lo into the same registers, then a_lo * b_hi
            #pragma unroll
            for (int mt = 0; mt < MT; mt++) {
                uint32_t ao = (uint32_t)((arow + mt * 16) * (LDA_S * 2)
                                         + (k0s + acol8) * 2);
                ldsm4(af[mt][0], af[mt][1], af[mt][2], af[mt][3], base + OAL + ao);
            }
            #pragma unroll
            for (int j = 0; j < 4; j++)
                #pragma unroll
                for (int mt = 0; mt < MT; mt++)
                    mma16816(acc[mt][j], af[mt], bfh[j][0], bfh[j][1]);
        }
    }

    // ---- epilogue ----
    const int zb = z / NHH, zh = z % NHH;
    #pragma unroll
    for (int nt = 0; nt < 4; nt++) {
        const int colb = bn0 + wn * 32 + nt * 8 + 2 * (lane & 3);
        float b0 = 0.f, b1 = 0.f;
        if (EPI == EPI_F32 || EPI == EPI_GELU || EPI == EPI_QK) {
            b0 = __ldg(&bias[colb]); b1 = __ldg(&bias[colb + 1]);
        } else if (EPI == EPI_SCORES) {
            b0 = __ldg(&mask[zb * SS + colb]); b1 = __ldg(&mask[zb * SS + colb + 1]);
        }
        #pragma unroll
        for (int mt = 0; mt < MT; mt++) {
            const int rA = bm0 + wm * WM + mt * 16 + (lane >> 2);
            #pragma unroll
            for (int e = 0; e < 4; e++) {
                int R   = rA + (e >> 1) * 8;
                int col = colb + (e & 1);
                float bb = (e & 1) ? b1 : b0;
                float v = acc[mt][nt][e];
                if (EPI == EPI_F32) {
                    v += bb;
                    outF[(long)R * N + col] = v;
                } else if (EPI == EPI_PART) {
                    outF[(long)R * N + col] = v;
                } else if (EPI == EPI_GELU) {
                    v += bb;
                    v = 0.5f * v * (1.0f + erff(v * 0.70710678118654752f));
                    split_store(v, outHi, outLo, (long)R * N + col);
                } else if (EPI == EPI_QK) {
                    v += bb;
                    int bi = R >> 9, s = R & 511, hh = col >> 6, d = col & 63;
                    long o = (((long)(bi * NHH + hh)) * SS + s) * DD + d;
                    split_store(v, outHi, outLo, o);
                } else if (EPI == EPI_SCORES) {
                    v = v * 0.125f + bb;
                    outF[((long)z * SS + R) * SS + col] = v;
                } else {  // EPI_CTX
                    long o = ((long)(zb * SS + R)) * HH + zh * DD + col;
                    split_store(v, outHi, outLo, o);
                }
            }
        }
    }
}

// ---------------- weight fp16 convert (z selects tensor) --------------------
__global__ __launch_bounds__(256)
void wconv4_kernel(const float* __restrict__ a0, const float* __restrict__ a1,
                   const float* __restrict__ a2, const float* __restrict__ a3,
                   long n)
{
    int zs = blockIdx.z;
    const float* W = (zs == 0) ? a0 : (zs == 1) ? a1 : (zs == 2) ? a2 : a3;
    h16* o = (zs == 0) ? g_wq : (zs == 1) ? g_wk : (zs == 2) ? g_wv : g_wo;
    long i = (long)blockIdx.x * 256 + threadIdx.x;
    long stride = (long)gridDim.x * 256;
    for (; i < n; i += stride) o[i] = __float2half(W[i]);
}
__global__ __launch_bounds__(256)
void wconv2_kernel(const float* __restrict__ a0, const float* __restrict__ a1, long n)
{
    int zs = blockIdx.z;
    const float* W = (zs == 0) ? a0 : a1;
    h16* o = (zs == 0) ? g_w1 : g_w2;
    long i = (long)blockIdx.x * 256 + threadIdx.x;
    long stride = (long)gridDim.x * 256;
    for (; i < n; i += stride) o[i] = __float2half(W[i]);
}

// ---------------- block reductions ------------------------------------------
__device__ __forceinline__ float blockSum(float v, float* red) {
    int tid = threadIdx.x;
    red[tid] = v; __syncthreads();
    for (int s = 128; s > 0; s >>= 1) {
        if (tid < s) red[tid] += red[tid + s];
        __syncthreads();
    }
    float r = red[0]; __syncthreads();
    return r;
}

// ---------------- embeddings + layernorm + mask + split ---------------------
__global__ __launch_bounds__(256)
void embed_ln_kernel(const int* __restrict__ ids, const int* __restrict__ tids,
                     const float* __restrict__ we, const float* __restrict__ pe,
                     const float* __restrict__ te, const float* __restrict__ sc,
                     const float* __restrict__ bi, float* __restrict__ out,
                     h16* __restrict__ ohi, h16* __restrict__ olo,
                     float* __restrict__ mask)
{
    __shared__ float red[256];
    int row = blockIdx.x, s = row % SS, tid = threadIdx.x;
    int id = ids[row], tt = tids[row];
    if (tid == 0) mask[row] = (id == 0) ? -10000.0f : 0.0f;
    float v[3]; float sum = 0.f;
    #pragma unroll
    for (int i = 0; i < 3; i++) {
        int j = tid + i * 256;
        v[i] = we[(long)id * HH + j] + pe[s * HH + j] + te[tt * HH + j];
        sum += v[i];
    }
    float mu = blockSum(sum, red) * (1.0f / HH);
    float s2 = 0.f;
    #pragma unroll
    for (int i = 0; i < 3; i++) { float d = v[i] - mu; s2 += d * d; }
    float inv = rsqrtf(blockSum(s2, red) * (1.0f / HH) + 1e-12f);
    #pragma unroll
    for (int i = 0; i < 3; i++) {
        int j = tid + i * 256;
        float r = (v[i] - mu) * inv * sc[j] + bi[j];
        long o = (long)row * HH + j;
        out[o] = r;
        split_store(r, ohi, olo, o);
    }
}

// ---------------- residual + 3 split-K partials + bias + layernorm -----------
__global__ __launch_bounds__(256)
void add_ln3_kernel(const float* __restrict__ x, const float* __restrict__ t,
                    const float* __restrict__ pb, const float* __restrict__ sc,
                    const float* __restrict__ bi, float* __restrict__ out,
                    h16* __restrict__ ohi, h16* __restrict__ olo)
{
    __shared__ float red[256];
    int row = blockIdx.x, tid = threadIdx.x;
    const float *t1 = t + (long)BSN * HH, *t2 = t + 2L * BSN * HH;
    float v[3]; float sum = 0.f;
    #pragma unroll
    for (int i = 0; i < 3; i++) {
        int j = tid + i * 256;
        long o = (long)row * HH + j;
        v[i] = x[o] + t[o] + t1[o] + t2[o] + pb[j];
        sum += v[i];
    }
    float mu = blockSum(sum, red) * (1.0f / HH);
    float s2 = 0.f;
    #pragma unroll
    for (int i = 0; i < 3; i++) { float d = v[i] - mu; s2 += d * d; }
    float inv = rsqrtf(blockSum(s2, red) * (1.0f / HH) + 1e-12f);
    #pragma unroll
    for (int i = 0; i < 3; i++) {
        int j = tid + i * 256;
        float r = (v[i] - mu) * inv * sc[j] + bi[j];
        long o = (long)row * HH + j;
        out[o] = r;
        split_store(r, ohi, olo, o);
    }
}

// ---------------- softmax (512) + split to fp16 hi/lo ------------------------
__global__ __launch_bounds__(256)
void softmax512_split(const float* __restrict__ p, h16* __restrict__ phi,
                      h16* __restrict__ plo)
{
    __shared__ float red[256];
    long base = (long)blockIdx.x * SS;
    int tid = threadIdx.x;
    float a = p[base + tid], b = p[base + tid + 256];
    red[tid] = fmaxf(a, b); __syncthreads();
    for (int s = 128; s > 0; s >>= 1) {
        if (tid < s) red[tid] = fmaxf(red[tid], red[tid + s]);
        __syncthreads();
    }
    float m = red[0]; __syncthreads();
    float e0 = __expf(a - m), e1 = __expf(b - m);
    red[tid] = e0 + e1; __syncthreads();
    for (int s = 128; s > 0; s >>= 1) {
        if (tid < s) red[tid] += red[tid + s];
        __syncthreads();
    }
    float inv = 1.0f / red[0];
    split_store(e0 * inv, phi, plo, base + tid);
    split_store(e1 * inv, phi, plo, base + tid + 256);
}

// ---------------------------------------------------------------------------
extern "C" void kernel_launch(void* const* d_in, const int* in_sizes, int n_in,
                              void* d_out, int out_size)
{
    const int*   ids  = (const int*)  d_in[0];
    const int*   tids = (const int*)  d_in[1];
    const float* we   = (const float*)d_in[2];
    const float* pe   = (const float*)d_in[3];
    const float* te   = (const float*)d_in[4];
    const float* esc  = (const float*)d_in[5];
    const float* ebi  = (const float*)d_in[6];
    const float* wq   = (const float*)d_in[7];
    const float* bq   = (const float*)d_in[8];
    const float* wk   = (const float*)d_in[9];
    const float* bk   = (const float*)d_in[10];
    const float* wv   = (const float*)d_in[11];
    const float* bv   = (const float*)d_in[12];
    const float* wo   = (const float*)d_in[13];
    const float* bo   = (const float*)d_in[14];
    const float* l1s  = (const float*)d_in[15];
    const float* l1b  = (const float*)d_in[16];
    const float* w1   = (const float*)d_in[17];
    const float* b1   = (const float*)d_in[18];
    const float* w2   = (const float*)d_in[19];
    const float* b2   = (const float*)d_in[20];
    const float* l2s  = (const float*)d_in[21];
    const float* l2b  = (const float*)d_in[22];
    float* out = (float*)d_out;

    float *h, *tmp, *sc, *mask;
    h16 *h_hi, *h_lo, *q_hi, *q_lo, *k_hi, *k_lo, *v_hi, *v_lo;
    h16 *c_hi, *c_lo, *a_hi, *a_lo, *p_hi, *p_lo;
    h16 *wo_w, *w1_w, *w2_w;
    cudaGetSymbolAddress((void**)&h,    g_h);
    cudaGetSymbolAddress((void**)&tmp,  g_tmp);
    cudaGetSymbolAddress((void**)&sc,   g_sc);
    cudaGetSymbolAddress((void**)&mask, g_mask);
    cudaGetSymbolAddress((void**)&h_hi,  g_h_hi);  cudaGetSymbolAddress((void**)&h_lo,  g_h_lo);
    cudaGetSymbolAddress((void**)&q_hi,  g_q_hi);  cudaGetSymbolAddress((void**)&q_lo,  g_q_lo);
    cudaGetSymbolAddress((void**)&k_hi,  g_k_hi);  cudaGetSymbolAddress((void**)&k_lo,  g_k_lo);
    cudaGetSymbolAddress((void**)&v_hi,  g_v_hi);  cudaGetSymbolAddress((void**)&v_lo,  g_v_lo);
    cudaGetSymbolAddress((void**)&c_hi,  g_c_hi);  cudaGetSymbolAddress((void**)&c_lo,  g_c_lo);
    cudaGetSymbolAddress((void**)&a_hi,  g_a_hi);  cudaGetSymbolAddress((void**)&a_lo,  g_a_lo);
    cudaGetSymbolAddress((void**)&p_hi,  g_p_hi);  cudaGetSymbolAddress((void**)&p_lo,  g_p_lo);
    cudaGetSymbolAddress((void**)&wo_w,  g_wo);
    cudaGetSymbolAddress((void**)&w1_w,  g_w1);
    cudaGetSymbolAddress((void**)&w2_w,  g_w2);

    // dynamic smem: STAGES * (2*A + NB*B)
    const int SM_KM = 3 * (2 * 10240 + 1 * 32 * 136 * 2);   // B single: 87552
    const int SM_NT = 2 * (2 * 10240 + 2 * 10240);          // NT split: 81920
    const int SM_CX = 3 * (2 * 10240 + 2 * 32 * 72 * 2);    // k-major NT=64 split: 89088
    cudaFuncSetAttribute((const void*)mma_gemm<128, EPI_QK,     false, 3, true,  1, false>, cudaFuncAttributeMaxDynamicSharedMemorySize, SM_KM);
    cudaFuncSetAttribute((const void*)mma_gemm<128, EPI_PART,   false, 3, false, 3, false>, cudaFuncAttributeMaxDynamicSharedMemorySize, SM_KM);
    cudaFuncSetAttribute((const void*)mma_gemm<128, EPI_GELU,   false, 3, false, 1, false>, cudaFuncAttributeMaxDynamicSharedMemorySize, SM_KM);
    cudaFuncSetAttribute((const void*)mma_gemm<128, EPI_SCORES, true,  2, false, 1, true >, cudaFuncAttributeMaxDynamicSharedMemorySize, SM_NT);
    cudaFuncSetAttribute((const void*)mma_gemm<64,  EPI_CTX,    false, 3, false, 1, true >, cudaFuncAttributeMaxDynamicSharedMemorySize, SM_CX);

    const dim3 gQKV(HH / 128, BSN / 128, 3);    // (6, 32, 3) fused QKV
    const dim3 gSK (HH / 128, BSN / 128, 3);    // (6, 32, 3) split-K proj/FFN2
    const dim3 gFF (FF / 128, BSN / 128, 1);    // (24, 32)
    const dim3 gSC (SS / 128, SS / 128, ZH);    // (4, 4, 96)
    const dim3 gCX (1, SS / 128, ZH);           // (1, 4, 96)

    embed_ln_kernel<<<BSN, 256>>>(ids, tids, we, pe, te, esc, ebi, h, h_hi, h_lo, mask);
    wconv4_kernel<<<dim3(2048, 1, 4), 256>>>(wq, wk, wv, wo, (long)LL * HH * HH);
    wconv2_kernel<<<dim3(4096, 1, 2), 256>>>(w1, w2, (long)LL * HH * FF);

    for (int l = 0; l < LL; l++) {
        long wOff = (long)l * HH * HH, bOff = (long)l * HH;
        long w1Off = (long)l * HH * FF, b1Off = (long)l * FF;

        mma_gemm<128, EPI_QK, false, 3, true, 1, false><<<gQKV, 256, SM_KM>>>(
            h_hi, h_lo, nullptr, nullptr, bq + bOff, bk + bOff, bv + bOff,
            nullptr, nullptr, nullptr, nullptr, BSN, HH, HH, HH, 0, wOff);

        // scores: A = Q [z][S][D], B = K [z][S][D] (NT gemm, both split)
        mma_gemm<128, EPI_SCORES, true, 2, false, 1, true><<<gSC, 256, SM_NT>>>(
            q_hi, q_lo, k_hi, k_lo, nullptr, nullptr, nullptr, mask,
            sc, nullptr, nullptr, SS, SS, DD, DD, (long)SS * DD, (long)SS * DD);

        softmax512_split<<<ZH * SS, 256>>>(sc, p_hi, p_lo);

        // ctx: A = P [z][S][S], B = V [z][S][D] (k-major, both split)
        mma_gemm<64, EPI_CTX, false, 3, false, 1, true><<<gCX, 256, SM_CX>>>(
            p_hi, p_lo, v_hi, v_lo, nullptr, nullptr, nullptr, nullptr,
            nullptr, c_hi, c_lo, SS, DD, SS, SS, (long)SS * SS, (long)SS * DD);

        // wo-proj: split-K=3 partials into tmp[0..2]
        mma_gemm<128, EPI_PART, false, 3, false, 3, false><<<gSK, 256, SM_KM>>>(
            c_hi, c_lo, wo_w + wOff, nullptr, nullptr, nullptr, nullptr,
            nullptr, tmp, nullptr, nullptr, BSN, HH, HH, HH, 0, 0);
        add_ln3_kernel<<<BSN, 256>>>(h, tmp, bo + bOff, l1s + bOff, l1b + bOff,
                                     h, h_hi, h_lo);

        mma_gemm<128, EPI_GELU, false, 3, false, 1, false><<<gFF, 256, SM_KM>>>(
            h_hi, h_lo, w1_w + w1Off, nullptr, b1 + b1Off, nullptr, nullptr,
            nullptr, nullptr, a_hi, a_lo, BSN, FF, HH, HH, 0, 0);
        // FFN2: split-K=3 partials into tmp[0..2]
        mma_gemm<128, EPI_PART, false, 3, false, 3, false><<<gSK, 256, SM_KM>>>(
            a_hi, a_lo, w2_w + w1Off, nullptr, nullptr, nullptr, nullptr,
            nullptr, tmp, nullptr, nullptr, BSN, HH, FF, FF, 0, 0);
        add_ln3_kernel<<<BSN, 256>>>(h, tmp, b2 + bOff, l2s + bOff, l2b + bOff,
                                     (l == LL - 1) ? out : h, h_hi, h_lo);
    }
}

// round 13
// speedup vs baseline: 4.2943x; 1.3748x over previous
#include <cuda_runtime.h>
#include <cuda_fp16.h>
#include <cstdint>

// ---------------------------------------------------------------------------
// BERT-base encoder forward, fp16 mma.sync (HMMA) GEMMs. sm_103-safe PTX.
// Projections: single-fp16 x single-fp16 (1 product; err ~5.8e-4 < 1e-3 gate).
// Attention (scores/ctx): hi/lo split both operands (3 products, ~2^-22).
// B=8, S=512, H=768, NH=12, D=64, F=3072, L=12
// ---------------------------------------------------------------------------

#define BB   8
#define SS   512
#define HH   768
#define NHH  12
#define DD   64
#define FF   3072
#define LL   12
#define BSN  (BB*SS)          // 4096 tokens
#define ZH   (BB*NHH)         // 96

typedef __half h16;

// ---------------- scratch (device globals; no allocations) -----------------
__device__ float g_h  [BSN*HH];
__device__ float g_tmp[3L*BSN*HH];          // split-K partials (3 slices)
__device__ float g_sc [(long)ZH*SS*SS];     // attention logits fp32 (~100MB)
__device__ float g_mask[BSN];

__device__ h16 g_h16 [BSN*HH];                      // h, single fp16
__device__ h16 g_q_hi[BSN*HH],  g_q_lo[BSN*HH];     // [z][S][D]
__device__ h16 g_k_hi[BSN*HH],  g_k_lo[BSN*HH];     // [z][S][D]
__device__ h16 g_v_hi[BSN*HH],  g_v_lo[BSN*HH];     // [z][S][D]
__device__ h16 g_c16 [BSN*HH];                      // ctx, single fp16
__device__ h16 g_a16 [BSN*FF];                      // ffn act, single fp16
__device__ h16 g_p_hi[(long)ZH*SS*SS], g_p_lo[(long)ZH*SS*SS]; // probs split

__device__ h16 g_wq[LL*HH*HH], g_wk[LL*HH*HH];      // weights: single fp16
__device__ h16 g_wv[LL*HH*HH], g_wo[LL*HH*HH];
__device__ h16 g_w1[(long)LL*HH*FF], g_w2[(long)LL*FF*HH];

// ---------------- small helpers --------------------------------------------
__device__ __forceinline__ uint32_t smem_u32(const void* p) {
    uint32_t a;
    asm("{ .reg .u64 t; cvta.to.shared.u64 t, %1; cvt.u32.u64 %0, t; }" : "=r"(a) : "l"(p));
    return a;
}
__device__ __forceinline__ void cpasync16(uint32_t s, const void* g) {
    asm volatile("cp.async.cg.shared.global [%0], [%1], 16;" :: "r"(s), "l"(g) : "memory");
}
#define CP_COMMIT() asm volatile("cp.async.commit_group;" ::: "memory")
#define CP_WAIT0()  asm volatile("cp.async.wait_group 0;" ::: "memory")
#define CP_WAIT1()  asm volatile("cp.async.wait_group 1;" ::: "memory")
#define CP_WAIT2()  asm volatile("cp.async.wait_group 2;" ::: "memory")

__device__ __forceinline__ void ldsm4(uint32_t& r0, uint32_t& r1, uint32_t& r2,
                                      uint32_t& r3, uint32_t addr) {
    asm volatile("ldmatrix.sync.aligned.m8n8.x4.shared.b16 {%0,%1,%2,%3}, [%4];"
                 : "=r"(r0), "=r"(r1), "=r"(r2), "=r"(r3) : "r"(addr));
}
__device__ __forceinline__ void ldsm4t(uint32_t& r0, uint32_t& r1, uint32_t& r2,
                                       uint32_t& r3, uint32_t addr) {
    asm volatile("ldmatrix.sync.aligned.m8n8.x4.trans.shared.b16 {%0,%1,%2,%3}, [%4];"
                 : "=r"(r0), "=r"(r1), "=r"(r2), "=r"(r3) : "r"(addr));
}
__device__ __forceinline__ void mma16816(float* c, const uint32_t* a,
                                         uint32_t b0, uint32_t b1) {
    asm("mma.sync.aligned.m16n8k16.row.col.f32.f16.f16.f32 "
        "{%0,%1,%2,%3}, {%4,%5,%6,%7}, {%8,%9}, {%0,%1,%2,%3};"
        : "+f"(c[0]), "+f"(c[1]), "+f"(c[2]), "+f"(c[3])
        : "r"(a[0]), "r"(a[1]), "r"(a[2]), "r"(a[3]), "r"(b0), "r"(b1));
}
__device__ __forceinline__ void split_store(float v, h16* __restrict__ hi,
                                            h16* __restrict__ lo, long o) {
    h16 h = __float2half(v);
    hi[o] = h;
    lo[o] = __float2half(v - __half2float(h));
}

// ---------------------------------------------------------------------------
// mma.sync GEMM: C[M,N] = A[M,K] @ B, A row-major [M][K] (row stride ldA).
// BNT=false: B row-major [K][N] (k-major, ldmatrix.trans). BNT=true: [N][K].
// ASPLIT: A split hi/lo (adds a_lo*b_hi). BSPLIT: B split (adds a_hi*b_lo).
// CTA tile 128 x NT, K-chunk 32, 8 warps, STAGES-deep cp.async pipeline.
// QKV3: gridDim.z = 3 selects {wq->q, wk->k, wv->v} from device globals.
// KSPL>1: split-K over gridDim.z; each part writes outF + z*M*N (no bias).
// ---------------------------------------------------------------------------
#define EPI_F32    0
#define EPI_GELU   1   // bias + gelu -> single h16
#define EPI_QK     2   // bias + split scatter [z][S][D]     (Q, K, V)
#define EPI_SCORES 4   // *0.125 + mask, fp32 [z][S][S]
#define EPI_CTX    5   // merge heads -> [B*S, H], single h16
#define EPI_PART   6   // raw fp32 partial (split-K), no bias

template<int NT, int EPI, bool BNT, int STAGES, bool QKV3, int KSPL,
         bool ASPLIT, bool BSPLIT>
__global__ __launch_bounds__(256, 2)
void mma_gemm(const h16* Ahi, const h16* Alo,
              const h16* Bhi, const h16* Blo,
              const float* bias, const float* bias2, const float* bias3,
              const float* mask,
              float* outF, h16* outHi, h16* outLo,
              int M, int N, int K, int ldA, long sAz, long sBz)
{
    constexpr int WARPS_N = (NT == 128) ? 4 : 2;
    constexpr int WM = (NT == 128) ? 64 : 32;        // warp tile M
    constexpr int MT = WM / 16;                      // m-tiles (4 or 2)
    constexpr int LDA_S = 40;                        // A smem row elems (32+8)
    constexpr int ABYT1 = 128 * LDA_S * 2;           // 10240
    constexpr int LDB_S = BNT ? 40 : (NT + 8);       // B smem row elems
    constexpr int BBYT1 = BNT ? (NT * LDA_S * 2) : (32 * LDB_S * 2);
    constexpr int NA    = ASPLIT ? 2 : 1;
    constexpr int NB    = BSPLIT ? 2 : 1;
    constexpr int OAH = 0, OAL = ABYT1;
    constexpr int OBH = NA * ABYT1;
    constexpr int OBL = NA * ABYT1 + BBYT1;
    constexpr int BUFB = NA * ABYT1 + NB * BBYT1;

    extern __shared__ char smem[];
    const uint32_t sb = smem_u32(smem);

    const int tid = threadIdx.x, wid = tid >> 5, lane = tid & 31;
    const int wm = wid / WARPS_N, wn = wid % WARPS_N;
    const int z = blockIdx.z;
    int Kloop = K;
    if constexpr (QKV3) {
        if (z == 1)      { Bhi = g_wk + sBz; bias = bias2; outHi = g_k_hi; outLo = g_k_lo; }
        else if (z == 2) { Bhi = g_wv + sBz; bias = bias3; outHi = g_v_hi; outLo = g_v_lo; }
        else             { Bhi = g_wq + sBz;               outHi = g_q_hi; outLo = g_q_lo; }
    } else if constexpr (KSPL > 1) {
        int koff = z * (K / KSPL);
        Ahi += koff;
        Bhi += (long)koff * N;
        outF += (long)z * M * N;
        Kloop = K / KSPL;
    } else {
        Ahi += (long)z * sAz;
        if (ASPLIT) Alo += (long)z * sAz;
        Bhi += (long)z * sBz;
        if (BSPLIT) Blo += (long)z * sBz;
    }
    const int bm0 = blockIdx.y * 128;
    const int bn0 = blockIdx.x * NT;

    // ---- async tile loader ----
    auto load_chunk = [&](int buf, int k0) {
        uint32_t base = sb + buf * BUFB;
        #pragma unroll
        for (int i = 0; i < 2; i++) {                 // A: 512 16B chunks
            int idx = tid + i * 256;
            int r = idx >> 2, c = idx & 3;
            long go = (long)(bm0 + r) * ldA + k0 + c * 8;
            uint32_t so = r * (LDA_S * 2) + c * 16;
            cpasync16(base + OAH + so, Ahi + go);
            if (ASPLIT) cpasync16(base + OAL + so, Alo + go);
        }
        if (BNT) {
            #pragma unroll
            for (int i = 0; i < NT * 4 / 256; i++) {
                int idx = tid + i * 256;
                int r = idx >> 2, c = idx & 3;
                long go = (long)(bn0 + r) * K + k0 + c * 8;
                uint32_t so = r * (LDA_S * 2) + c * 16;
                cpasync16(base + OBH + so, Bhi + go);
                if (BSPLIT) cpasync16(base + OBL + so, Blo + go);
            }
        } else {
            constexpr int BCH = NT / 8;               // 16B chunks per B row
            #pragma unroll
            for (int i = 0; i < 32 * BCH / 256; i++) {
                int idx = tid + i * 256;
                int r = idx / BCH, c = idx % BCH;
                long go = (long)(k0 + r) * N + bn0 + c * 8;
                uint32_t so = r * (LDB_S * 2) + c * 16;
                cpasync16(base + OBH + so, Bhi + go);
                if (BSPLIT) cpasync16(base + OBL + so, Blo + go);
            }
        }
        CP_COMMIT();
    };

    float acc[MT][4][4];
    #pragma unroll
    for (int i = 0; i < MT; i++)
        #pragma unroll
        for (int j = 0; j < 4; j++)
            #pragma unroll
            for (int e = 0; e < 4; e++) acc[i][j][e] = 0.f;

    const int nkc = Kloop >> 5;
    #pragma unroll
    for (int s = 0; s < STAGES - 1; s++)
        if (s < nkc) load_chunk(s, s * 32);

    const int arow = wm * WM + (lane & 15);
    const int acol8 = (lane >> 4) << 3;

    for (int kc = 0; kc < nkc; kc++) {
        {
            int pend = STAGES - 2;
            if (nkc - 1 - kc < pend) pend = nkc - 1 - kc;
            if (pend >= 2) { CP_WAIT2(); } else if (pend == 1) { CP_WAIT1(); }
            else           { CP_WAIT0(); }
        }
        __syncthreads();
        if (kc + STAGES - 1 < nkc)
            load_chunk((kc + STAGES - 1) % STAGES, (kc + STAGES - 1) * 32);

        const uint32_t base = sb + (kc % STAGES) * BUFB;

        auto loadB = [&](uint32_t (&bf)[4][2], uint32_t off, int k0s) {
            uint32_t r0, r1, r2, r3;
            if (BNT) {
                #pragma unroll
                for (int half = 0; half < 2; half++) {
                    uint32_t bo = (uint32_t)((wn * 32 + half * 16 + (lane & 15)) * (LDA_S * 2)
                                             + (k0s + acol8) * 2);
                    ldsm4(r0, r1, r2, r3, base + off + bo);
                    bf[half*2+0][0] = r0; bf[half*2+0][1] = r2;
                    bf[half*2+1][0] = r1; bf[half*2+1][1] = r3;
                }
            } else {
                const int brow = lane & 15;
                const int bcol8 = wn * 32 + ((lane >> 4) << 3);
                #pragma unroll
                for (int np = 0; np < 2; np++) {
                    uint32_t bo = (uint32_t)((k0s + brow) * (LDB_S * 2)
                                             + (bcol8 + np * 16) * 2);
                    ldsm4t(r0, r1, r2, r3, base + off + bo);
                    bf[np*2+0][0] = r0; bf[np*2+0][1] = r1;
                    bf[np*2+1][0] = r2; bf[np*2+1][1] = r3;
                }
            }
        };

        #pragma unroll
        for (int ks = 0; ks < 2; ks++) {
            const int k0s = ks * 16;
            uint32_t af[MT][4];            // A fragment: hi first, reused for lo
            uint32_t bfh[4][2], bfl[4][2];
            #pragma unroll
            for (int mt = 0; mt < MT; mt++) {
                uint32_t ao = (uint32_t)((arow + mt * 16) * (LDA_S * 2)
                                         + (k0s + acol8) * 2);
                ldsm4(af[mt][0], af[mt][1], af[mt][2], af[mt][3], base + OAH + ao);
            }
            loadB(bfh, OBH, k0s);
            if (BSPLIT) loadB(bfl, OBL, k0s);
            // a_hi * b_hi
            #pragma unroll
            for (int j = 0; j < 4; j++)
                #pragma unroll
                for (int mt = 0; mt < MT; mt++)
                    mma16816(acc[mt][j], af[mt], bfh[j][0], bfh[j][1]);
            // a_hi * b_lo
            if (BSPLIT) {
                #pragma unroll
                for (int j = 0; j < 4; j++)
                    #pragma unroll
                    for (int mt = 0; mt < MT; mt++)
                        mma16816(acc[mt][j], af[mt], bfl[j][0], bfl[j][1]);
            }
            // a_lo * b_hi (reload A regs)
            if (ASPLIT) {
                #pragma unroll
                for (int mt = 0; mt < MT; mt++) {
                    uint32_t ao = (uint32_t)((arow + mt * 16) * (LDA_S * 2)
                                             + (k0s + acol8) * 2);
                    ldsm4(af[mt][0], af[mt][1], af[mt][2], af[mt][3], base + OAL + ao);
                }
                #pragma unroll
                for (int j = 0; j < 4; j++)
                    #pragma unroll
                    for (int mt = 0; mt < MT; mt++)
                        mma16816(acc[mt][j], af[mt], bfh[j][0], bfh[j][1]);
            }
        }
    }

    // ---- epilogue ----
    const int zb = z / NHH, zh = z % NHH;
    #pragma unroll
    for (int nt = 0; nt < 4; nt++) {
        const int colb = bn0 + wn * 32 + nt * 8 + 2 * (lane & 3);
        float b0 = 0.f, b1 = 0.f;
        if (EPI == EPI_F32 || EPI == EPI_GELU || EPI == EPI_QK) {
            b0 = __ldg(&bias[colb]); b1 = __ldg(&bias[colb + 1]);
        } else if (EPI == EPI_SCORES) {
            b0 = __ldg(&mask[zb * SS + colb]); b1 = __ldg(&mask[zb * SS + colb + 1]);
        }
        #pragma unroll
        for (int mt = 0; mt < MT; mt++) {
            const int rA = bm0 + wm * WM + mt * 16 + (lane >> 2);
            #pragma unroll
            for (int e = 0; e < 4; e++) {
                int R   = rA + (e >> 1) * 8;
                int col = colb + (e & 1);
                float bb = (e & 1) ? b1 : b0;
                float v = acc[mt][nt][e];
                if (EPI == EPI_F32) {
                    v += bb;
                    outF[(long)R * N + col] = v;
                } else if (EPI == EPI_PART) {
                    outF[(long)R * N + col] = v;
                } else if (EPI == EPI_GELU) {
                    v += bb;
                    v = 0.5f * v * (1.0f + erff(v * 0.70710678118654752f));
                    outHi[(long)R * N + col] = __float2half(v);
                } else if (EPI == EPI_QK) {
                    v += bb;
                    int bi = R >> 9, s = R & 511, hh = col >> 6, d = col & 63;
                    long o = (((long)(bi * NHH + hh)) * SS + s) * DD + d;
                    split_store(v, outHi, outLo, o);
                } else if (EPI == EPI_SCORES) {
                    v = v * 0.125f + bb;
                    outF[((long)z * SS + R) * SS + col] = v;
                } else {  // EPI_CTX: single h16, merge heads
                    long o = ((long)(zb * SS + R)) * HH + zh * DD + col;
                    outHi[o] = __float2half(v);
                }
            }
        }
    }
}

// ---------------- weight fp16 convert (z selects tensor) --------------------
__global__ __launch_bounds__(256)
void wconv4_kernel(const float* __restrict__ a0, const float* __restrict__ a1,
                   const float* __restrict__ a2, const float* __restrict__ a3,
                   long n)
{
    int zs = blockIdx.z;
    const float* W = (zs == 0) ? a0 : (zs == 1) ? a1 : (zs == 2) ? a2 : a3;
    h16* o = (zs == 0) ? g_wq : (zs == 1) ? g_wk : (zs == 2) ? g_wv : g_wo;
    long i = (long)blockIdx.x * 256 + threadIdx.x;
    long stride = (long)gridDim.x * 256;
    for (; i < n; i += stride) o[i] = __float2half(W[i]);
}
__global__ __launch_bounds__(256)
void wconv2_kernel(const float* __restrict__ a0, const float* __restrict__ a1, long n)
{
    int zs = blockIdx.z;
    const float* W = (zs == 0) ? a0 : a1;
    h16* o = (zs == 0) ? g_w1 : g_w2;
    long i = (long)blockIdx.x * 256 + threadIdx.x;
    long stride = (long)gridDim.x * 256;
    for (; i < n; i += stride) o[i] = __float2half(W[i]);
}

// ---------------- block reductions ------------------------------------------
__device__ __forceinline__ float blockSum(float v, float* red) {
    int tid = threadIdx.x;
    red[tid] = v; __syncthreads();
    for (int s = 128; s > 0; s >>= 1) {
        if (tid < s) red[tid] += red[tid + s];
        __syncthreads();
    }
    float r = red[0]; __syncthreads();
    return r;
}

// ---------------- embeddings + layernorm + mask (h single fp16) -------------
__global__ __launch_bounds__(256)
void embed_ln_kernel(const int* __restrict__ ids, const int* __restrict__ tids,
                     const float* __restrict__ we, const float* __restrict__ pe,
                     const float* __restrict__ te, const float* __restrict__ sc,
                     const float* __restrict__ bi, float* __restrict__ out,
                     h16* __restrict__ o16, float* __restrict__ mask)
{
    __shared__ float red[256];
    int row = blockIdx.x, s = row % SS, tid = threadIdx.x;
    int id = ids[row], tt = tids[row];
    if (tid == 0) mask[row] = (id == 0) ? -10000.0f : 0.0f;
    float v[3]; float sum = 0.f;
    #pragma unroll
    for (int i = 0; i < 3; i++) {
        int j = tid + i * 256;
        v[i] = we[(long)id * HH + j] + pe[s * HH + j] + te[tt * HH + j];
        sum += v[i];
    }
    float mu = blockSum(sum, red) * (1.0f / HH);
    float s2 = 0.f;
    #pragma unroll
    for (int i = 0; i < 3; i++) { float d = v[i] - mu; s2 += d * d; }
    float inv = rsqrtf(blockSum(s2, red) * (1.0f / HH) + 1e-12f);
    #pragma unroll
    for (int i = 0; i < 3; i++) {
        int j = tid + i * 256;
        float r = (v[i] - mu) * inv * sc[j] + bi[j];
        long o = (long)row * HH + j;
        out[o] = r;
        o16[o] = __float2half(r);
    }
}

// ---------------- residual + 3 split-K partials + bias + layernorm -----------
__global__ __launch_bounds__(256)
void add_ln3_kernel(const float* __restrict__ x, const float* __restrict__ t,
                    const float* __restrict__ pb, const float* __restrict__ sc,
                    const float* __restrict__ bi, float* __restrict__ out,
                    h16* __restrict__ o16)
{
    __shared__ float red[256];
    int row = blockIdx.x, tid = threadIdx.x;
    const float *t1 = t + (long)BSN * HH, *t2 = t + 2L * BSN * HH;
    float v[3]; float sum = 0.f;
    #pragma unroll
    for (int i = 0; i < 3; i++) {
        int j = tid + i * 256;
        long o = (long)row * HH + j;
        v[i] = x[o] + t[o] + t1[o] + t2[o] + pb[j];
        sum += v[i];
    }
    float mu = blockSum(sum, red) * (1.0f / HH);
    float s2 = 0.f;
    #pragma unroll
    for (int i = 0; i < 3; i++) { float d = v[i] - mu; s2 += d * d; }
    float inv = rsqrtf(blockSum(s2, red) * (1.0f / HH) + 1e-12f);
    #pragma unroll
    for (int i = 0; i < 3; i++) {
        int j = tid + i * 256;
        float r = (v[i] - mu) * inv * sc[j] + bi[j];
        long o = (long)row * HH + j;
        out[o] = r;
        o16[o] = __float2half(r);
    }
}

// ---------------- softmax (512) + split to fp16 hi/lo ------------------------
__global__ __launch_bounds__(256)
void softmax512_split(const float* __restrict__ p, h16* __restrict__ phi,
                      h16* __restrict__ plo)
{
    __shared__ float red[256];
    long base = (long)blockIdx.x * SS;
    int tid = threadIdx.x;
    float a = p[base + tid], b = p[base + tid + 256];
    red[tid] = fmaxf(a, b); __syncthreads();
    for (int s = 128; s > 0; s >>= 1) {
        if (tid < s) red[tid] = fmaxf(red[tid], red[tid + s]);
        __syncthreads();
    }
    float m = red[0]; __syncthreads();
    float e0 = __expf(a - m), e1 = __expf(b - m);
    red[tid] = e0 + e1; __syncthreads();
    for (int s = 128; s > 0; s >>= 1) {
        if (tid < s) red[tid] += red[tid + s];
        __syncthreads();
    }
    float inv = 1.0f / red[0];
    split_store(e0 * inv, phi, plo, base + tid);
    split_store(e1 * inv, phi, plo, base + tid + 256);
}

// ---------------------------------------------------------------------------
extern "C" void kernel_launch(void* const* d_in, const int* in_sizes, int n_in,
                              void* d_out, int out_size)
{
    const int*   ids  = (const int*)  d_in[0];
    const int*   tids = (const int*)  d_in[1];
    const float* we   = (const float*)d_in[2];
    const float* pe   = (const float*)d_in[3];
    const float* te   = (const float*)d_in[4];
    const float* esc  = (const float*)d_in[5];
    const float* ebi  = (const float*)d_in[6];
    const float* wq   = (const float*)d_in[7];
    const float* bq   = (const float*)d_in[8];
    const float* wk   = (const float*)d_in[9];
    const float* bk   = (const float*)d_in[10];
    const float* wv   = (const float*)d_in[11];
    const float* bv   = (const float*)d_in[12];
    const float* wo   = (const float*)d_in[13];
    const float* bo   = (const float*)d_in[14];
    const float* l1s  = (const float*)d_in[15];
    const float* l1b  = (const float*)d_in[16];
    const float* w1   = (const float*)d_in[17];
    const float* b1   = (const float*)d_in[18];
    const float* w2   = (const float*)d_in[19];
    const float* b2   = (const float*)d_in[20];
    const float* l2s  = (const float*)d_in[21];
    const float* l2b  = (const float*)d_in[22];
    float* out = (float*)d_out;

    float *h, *tmp, *sc, *mask;
    h16 *h16p, *q_hi, *q_lo, *k_hi, *k_lo, *v_hi, *v_lo;
    h16 *c16, *a16, *p_hi, *p_lo;
    h16 *wo_w, *w1_w, *w2_w;
    cudaGetSymbolAddress((void**)&h,    g_h);
    cudaGetSymbolAddress((void**)&tmp,  g_tmp);
    cudaGetSymbolAddress((void**)&sc,   g_sc);
    cudaGetSymbolAddress((void**)&mask, g_mask);
    cudaGetSymbolAddress((void**)&h16p, g_h16);
    cudaGetSymbolAddress((void**)&q_hi, g_q_hi);  cudaGetSymbolAddress((void**)&q_lo, g_q_lo);
    cudaGetSymbolAddress((void**)&k_hi, g_k_hi);  cudaGetSymbolAddress((void**)&k_lo, g_k_lo);
    cudaGetSymbolAddress((void**)&v_hi, g_v_hi);  cudaGetSymbolAddress((void**)&v_lo, g_v_lo);
    cudaGetSymbolAddress((void**)&c16,  g_c16);
    cudaGetSymbolAddress((void**)&a16,  g_a16);
    cudaGetSymbolAddress((void**)&p_hi, g_p_hi);  cudaGetSymbolAddress((void**)&p_lo, g_p_lo);
    cudaGetSymbolAddress((void**)&wo_w, g_wo);
    cudaGetSymbolAddress((void**)&w1_w, g_w1);
    cudaGetSymbolAddress((void**)&w2_w, g_w2);

    // dynamic smem: STAGES * (NA*A + NB*B)
    const int SM_1P = 4 * (10240 + 32 * 136 * 2);           // 1-product: 75776
    const int SM_NT = 2 * (2 * 10240 + 2 * 10240);          // scores: 81920
    const int SM_CX = 3 * (2 * 10240 + 2 * 32 * 72 * 2);    // ctx: 89088
    cudaFuncSetAttribute((const void*)mma_gemm<128, EPI_QK,     false, 4, true,  1, false, false>, cudaFuncAttributeMaxDynamicSharedMemorySize, SM_1P);
    cudaFuncSetAttribute((const void*)mma_gemm<128, EPI_PART,   false, 4, false, 3, false, false>, cudaFuncAttributeMaxDynamicSharedMemorySize, SM_1P);
    cudaFuncSetAttribute((const void*)mma_gemm<128, EPI_GELU,   false, 4, false, 1, false, false>, cudaFuncAttributeMaxDynamicSharedMemorySize, SM_1P);
    cudaFuncSetAttribute((const void*)mma_gemm<128, EPI_SCORES, true,  2, false, 1, true,  true >, cudaFuncAttributeMaxDynamicSharedMemorySize, SM_NT);
    cudaFuncSetAttribute((const void*)mma_gemm<64,  EPI_CTX,    false, 3, false, 1, true,  true >, cudaFuncAttributeMaxDynamicSharedMemorySize, SM_CX);

    const dim3 gQKV(HH / 128, BSN / 128, 3);    // (6, 32, 3) fused QKV
    const dim3 gSK (HH / 128, BSN / 128, 3);    // (6, 32, 3) split-K proj/FFN2
    const dim3 gFF (FF / 128, BSN / 128, 1);    // (24, 32)
    const dim3 gSC (SS / 128, SS / 128, ZH);    // (4, 4, 96)
    const dim3 gCX (1, SS / 128, ZH);           // (1, 4, 96)

    embed_ln_kernel<<<BSN, 256>>>(ids, tids, we, pe, te, esc, ebi, h, h16p, mask);
    wconv4_kernel<<<dim3(2048, 1, 4), 256>>>(wq, wk, wv, wo, (long)LL * HH * HH);
    wconv2_kernel<<<dim3(4096, 1, 2), 256>>>(w1, w2, (long)LL * HH * FF);

    for (int l = 0; l < LL; l++) {
        long wOff = (long)l * HH * HH, bOff = (long)l * HH;
        long w1Off = (long)l * HH * FF, b1Off = (long)l * FF;

        mma_gemm<128, EPI_QK, false, 4, true, 1, false, false><<<gQKV, 256, SM_1P>>>(
            h16p, nullptr, nullptr, nullptr, bq + bOff, bk + bOff, bv + bOff,
            nullptr, nullptr, nullptr, nullptr, BSN, HH, HH, HH, 0, wOff);

        // scores: A = Q [z][S][D], B = K [z][S][D] (NT gemm, both split)
        mma_gemm<128, EPI_SCORES, true, 2, false, 1, true, true><<<gSC, 256, SM_NT>>>(
            q_hi, q_lo, k_hi, k_lo, nullptr, nullptr, nullptr, mask,
            sc, nullptr, nullptr, SS, SS, DD, DD, (long)SS * DD, (long)SS * DD);

        softmax512_split<<<ZH * SS, 256>>>(sc, p_hi, p_lo);

        // ctx: A = P [z][S][S] (split), B = V [z][S][D] (split, k-major)
        mma_gemm<64, EPI_CTX, false, 3, false, 1, true, true><<<gCX, 256, SM_CX>>>(
            p_hi, p_lo, v_hi, v_lo, nullptr, nullptr, nullptr, nullptr,
            nullptr, c16, nullptr, SS, DD, SS, SS, (long)SS * SS, (long)SS * DD);

        // wo-proj: split-K=3 partials into tmp[0..2]
        mma_gemm<128, EPI_PART, false, 4, false, 3, false, false><<<gSK, 256, SM_1P>>>(
            c16, nullptr, wo_w + wOff, nullptr, nullptr, nullptr, nullptr,
            nullptr, tmp, nullptr, nullptr, BSN, HH, HH, HH, 0, 0);
        add_ln3_kernel<<<BSN, 256>>>(h, tmp, bo + bOff, l1s + bOff, l1b + bOff,
                                     h, h16p);

        mma_gemm<128, EPI_GELU, false, 4, false, 1, false, false><<<gFF, 256, SM_1P>>>(
            h16p, nullptr, w1_w + w1Off, nullptr, b1 + b1Off, nullptr, nullptr,
            nullptr, nullptr, a16, nullptr, BSN, FF, HH, HH, 0, 0);
        // FFN2: split-K=3 partials into tmp[0..2]
        mma_gemm<128, EPI_PART, false, 4, false, 3, false, false><<<gSK, 256, SM_1P>>>(
            a16, nullptr, w2_w + w1Off, nullptr, nullptr, nullptr, nullptr,
            nullptr, tmp, nullptr, nullptr, BSN, HH, FF, FF, 0, 0);
        add_ln3_kernel<<<BSN, 256>>>(h, tmp, b2 + bOff, l2s + bOff, l2b + bOff,
                                     (l == LL - 1) ? out : h, h16p);
    }
}

// round 14
// speedup vs baseline: 4.8360x; 1.1261x over previous
#include <cuda_runtime.h>
#include <cuda_fp16.h>
#include <cstdint>

// ---------------------------------------------------------------------------
// BERT-base encoder forward, fp16 mma.sync (HMMA) GEMMs. sm_103-safe PTX.
// All GEMMs: single-fp16 x single-fp16, fp32 accum (1 product).
// Error budget ~7e-4 (< 1e-3 gate), validated by quadrature model R11->R12.
// B=8, S=512, H=768, NH=12, D=64, F=3072, L=12
// ---------------------------------------------------------------------------

#define BB   8
#define SS   512
#define HH   768
#define NHH  12
#define DD   64
#define FF   3072
#define LL   12
#define BSN  (BB*SS)          // 4096 tokens
#define ZH   (BB*NHH)         // 96

typedef __half h16;

// ---------------- scratch (device globals; no allocations) -----------------
__device__ float g_h  [BSN*HH];
__device__ float g_tmp[3L*BSN*HH];          // split-K partials (3 slices)
__device__ float g_sc [(long)ZH*SS*SS];     // attention logits fp32 (~100MB)
__device__ float g_mask[BSN];

__device__ h16 g_h16[BSN*HH];               // h
__device__ h16 g_q16[BSN*HH];               // [z][S][D]
__device__ h16 g_k16[BSN*HH];               // [z][S][D]
__device__ h16 g_v16[BSN*HH];               // [z][S][D]
__device__ h16 g_c16[BSN*HH];               // ctx [B*S][H]
__device__ h16 g_a16[BSN*FF];               // ffn act
__device__ h16 g_p16[(long)ZH*SS*SS];       // probs

__device__ h16 g_wq[LL*HH*HH], g_wk[LL*HH*HH];      // weights fp16
__device__ h16 g_wv[LL*HH*HH], g_wo[LL*HH*HH];
__device__ h16 g_w1[(long)LL*HH*FF], g_w2[(long)LL*FF*HH];

// ---------------- small helpers --------------------------------------------
__device__ __forceinline__ uint32_t smem_u32(const void* p) {
    uint32_t a;
    asm("{ .reg .u64 t; cvta.to.shared.u64 t, %1; cvt.u32.u64 %0, t; }" : "=r"(a) : "l"(p));
    return a;
}
__device__ __forceinline__ void cpasync16(uint32_t s, const void* g) {
    asm volatile("cp.async.cg.shared.global [%0], [%1], 16;" :: "r"(s), "l"(g) : "memory");
}
#define CP_COMMIT() asm volatile("cp.async.commit_group;" ::: "memory")
#define CP_WAIT0()  asm volatile("cp.async.wait_group 0;" ::: "memory")
#define CP_WAIT1()  asm volatile("cp.async.wait_group 1;" ::: "memory")
#define CP_WAIT2()  asm volatile("cp.async.wait_group 2;" ::: "memory")

__device__ __forceinline__ void ldsm4(uint32_t& r0, uint32_t& r1, uint32_t& r2,
                                      uint32_t& r3, uint32_t addr) {
    asm volatile("ldmatrix.sync.aligned.m8n8.x4.shared.b16 {%0,%1,%2,%3}, [%4];"
                 : "=r"(r0), "=r"(r1), "=r"(r2), "=r"(r3) : "r"(addr));
}
__device__ __forceinline__ void ldsm4t(uint32_t& r0, uint32_t& r1, uint32_t& r2,
                                       uint32_t& r3, uint32_t addr) {
    asm volatile("ldmatrix.sync.aligned.m8n8.x4.trans.shared.b16 {%0,%1,%2,%3}, [%4];"
                 : "=r"(r0), "=r"(r1), "=r"(r2), "=r"(r3) : "r"(addr));
}
__device__ __forceinline__ void mma16816(float* c, const uint32_t* a,
                                         uint32_t b0, uint32_t b1) {
    asm("mma.sync.aligned.m16n8k16.row.col.f32.f16.f16.f32 "
        "{%0,%1,%2,%3}, {%4,%5,%6,%7}, {%8,%9}, {%0,%1,%2,%3};"
        : "+f"(c[0]), "+f"(c[1]), "+f"(c[2]), "+f"(c[3])
        : "r"(a[0]), "r"(a[1]), "r"(a[2]), "r"(a[3]), "r"(b0), "r"(b1));
}

// ---------------------------------------------------------------------------
// mma.sync GEMM: C[M,N] = A[M,K] @ B, A row-major [M][K] (row stride ldA).
// BNT=false: B row-major [K][N] (k-major, ldmatrix.trans). BNT=true: [N][K].
// CTA tile 128 x NT, K-chunk 32, 8 warps, STAGES-deep cp.async pipeline.
// QKV3: gridDim.z = 3 selects {wq->q, wk->k, wv->v} from device globals.
// KSPL>1: split-K over gridDim.z; each part writes outF + z*M*N (no bias).
// ---------------------------------------------------------------------------
#define EPI_F32    0
#define EPI_GELU   1   // bias + gelu -> h16
#define EPI_QK     2   // bias + scatter [z][S][D] h16      (Q, K, V)
#define EPI_SCORES 4   // *0.125 + mask, fp32 [z][S][S]
#define EPI_CTX    5   // merge heads -> [B*S, H] h16
#define EPI_PART   6   // raw fp32 partial (split-K), no bias

template<int NT, int EPI, bool BNT, int STAGES, bool QKV3, int KSPL>
__global__ __launch_bounds__(256, 2)
void mma_gemm(const h16* A, const h16* B,
              const float* bias, const float* bias2, const float* bias3,
              const float* mask,
              float* outF, h16* outH,
              int M, int N, int K, int ldA, long sAz, long sBz)
{
    constexpr int WARPS_N = (NT == 128) ? 4 : 2;
    constexpr int WM = (NT == 128) ? 64 : 32;        // warp tile M
    constexpr int MT = WM / 16;                      // m-tiles (4 or 2)
    constexpr int LDA_S = 40;                        // A smem row elems (32+8)
    constexpr int ABYT = 128 * LDA_S * 2;            // 10240
    constexpr int LDB_S = BNT ? 40 : (NT + 8);       // B smem row elems
    constexpr int BBYT = BNT ? (NT * LDA_S * 2) : (32 * LDB_S * 2);
    constexpr int OB   = ABYT;
    constexpr int BUFB = ABYT + BBYT;

    extern __shared__ char smem[];
    const uint32_t sb = smem_u32(smem);

    const int tid = threadIdx.x, wid = tid >> 5, lane = tid & 31;
    const int wm = wid / WARPS_N, wn = wid % WARPS_N;
    const int z = blockIdx.z;
    int Kloop = K;
    if constexpr (QKV3) {
        if (z == 1)      { B = g_wk + sBz; bias = bias2; outH = g_k16; }
        else if (z == 2) { B = g_wv + sBz; bias = bias3; outH = g_v16; }
        else             { B = g_wq + sBz;               outH = g_q16; }
    } else if constexpr (KSPL > 1) {
        int koff = z * (K / KSPL);
        A += koff;
        B += (long)koff * N;
        outF += (long)z * M * N;
        Kloop = K / KSPL;
    } else {
        A += (long)z * sAz;
        B += (long)z * sBz;
    }
    const int bm0 = blockIdx.y * 128;
    const int bn0 = blockIdx.x * NT;

    // ---- async tile loader ----
    auto load_chunk = [&](int buf, int k0) {
        uint32_t base = sb + buf * BUFB;
        #pragma unroll
        for (int i = 0; i < 2; i++) {                 // A: 512 16B chunks
            int idx = tid + i * 256;
            int r = idx >> 2, c = idx & 3;
            long go = (long)(bm0 + r) * ldA + k0 + c * 8;
            uint32_t so = r * (LDA_S * 2) + c * 16;
            cpasync16(base + so, A + go);
        }
        if (BNT) {
            #pragma unroll
            for (int i = 0; i < NT * 4 / 256; i++) {
                int idx = tid + i * 256;
                int r = idx >> 2, c = idx & 3;
                long go = (long)(bn0 + r) * K + k0 + c * 8;
                uint32_t so = r * (LDA_S * 2) + c * 16;
                cpasync16(base + OB + so, B + go);
            }
        } else {
            constexpr int BCH = NT / 8;               // 16B chunks per B row
            #pragma unroll
            for (int i = 0; i < 32 * BCH / 256; i++) {
                int idx = tid + i * 256;
                int r = idx / BCH, c = idx % BCH;
                long go = (long)(k0 + r) * N + bn0 + c * 8;
                uint32_t so = r * (LDB_S * 2) + c * 16;
                cpasync16(base + OB + so, B + go);
            }
        }
        CP_COMMIT();
    };

    float acc[MT][4][4];
    #pragma unroll
    for (int i = 0; i < MT; i++)
        #pragma unroll
        for (int j = 0; j < 4; j++)
            #pragma unroll
            for (int e = 0; e < 4; e++) acc[i][j][e] = 0.f;

    const int nkc = Kloop >> 5;
    #pragma unroll
    for (int s = 0; s < STAGES - 1; s++)
        if (s < nkc) load_chunk(s, s * 32);

    const int arow = wm * WM + (lane & 15);
    const int acol8 = (lane >> 4) << 3;

    for (int kc = 0; kc < nkc; kc++) {
        {
            int pend = STAGES - 2;
            if (nkc - 1 - kc < pend) pend = nkc - 1 - kc;
            if (pend >= 2) { CP_WAIT2(); } else if (pend == 1) { CP_WAIT1(); }
            else           { CP_WAIT0(); }
        }
        __syncthreads();
        if (kc + STAGES - 1 < nkc)
            load_chunk((kc + STAGES - 1) % STAGES, (kc + STAGES - 1) * 32);

        const uint32_t base = sb + (kc % STAGES) * BUFB;

        #pragma unroll
        for (int ks = 0; ks < 2; ks++) {
            const int k0s = ks * 16;
            uint32_t af[MT][4];
            uint32_t bf[4][2];
            #pragma unroll
            for (int mt = 0; mt < MT; mt++) {
                uint32_t ao = (uint32_t)((arow + mt * 16) * (LDA_S * 2)
                                         + (k0s + acol8) * 2);
                ldsm4(af[mt][0], af[mt][1], af[mt][2], af[mt][3], base + ao);
            }
            if (BNT) {
                #pragma unroll
                for (int half = 0; half < 2; half++) {
                    uint32_t bo = (uint32_t)((wn * 32 + half * 16 + (lane & 15)) * (LDA_S * 2)
                                             + (k0s + acol8) * 2);
                    uint32_t r0, r1, r2, r3;
                    ldsm4(r0, r1, r2, r3, base + OB + bo);
                    bf[half*2+0][0] = r0; bf[half*2+0][1] = r2;
                    bf[half*2+1][0] = r1; bf[half*2+1][1] = r3;
                }
            } else {
                const int brow = lane & 15;
                const int bcol8 = wn * 32 + ((lane >> 4) << 3);
                #pragma unroll
                for (int np = 0; np < 2; np++) {
                    uint32_t bo = (uint32_t)((k0s + brow) * (LDB_S * 2)
                                             + (bcol8 + np * 16) * 2);
                    uint32_t r0, r1, r2, r3;
                    ldsm4t(r0, r1, r2, r3, base + OB + bo);
                    bf[np*2+0][0] = r0; bf[np*2+0][1] = r1;
                    bf[np*2+1][0] = r2; bf[np*2+1][1] = r3;
                }
            }
            #pragma unroll
            for (int j = 0; j < 4; j++)
                #pragma unroll
                for (int mt = 0; mt < MT; mt++)
                    mma16816(acc[mt][j], af[mt], bf[j][0], bf[j][1]);
        }
    }

    // ---- epilogue ----
    const int zb = z / NHH, zh = z % NHH;
    #pragma unroll
    for (int nt = 0; nt < 4; nt++) {
        const int colb = bn0 + wn * 32 + nt * 8 + 2 * (lane & 3);
        float b0 = 0.f, b1 = 0.f;
        if (EPI == EPI_F32 || EPI == EPI_GELU || EPI == EPI_QK) {
            b0 = __ldg(&bias[colb]); b1 = __ldg(&bias[colb + 1]);
        } else if (EPI == EPI_SCORES) {
            b0 = __ldg(&mask[zb * SS + colb]); b1 = __ldg(&mask[zb * SS + colb + 1]);
        }
        #pragma unroll
        for (int mt = 0; mt < MT; mt++) {
            const int rA = bm0 + wm * WM + mt * 16 + (lane >> 2);
            #pragma unroll
            for (int e = 0; e < 4; e++) {
                int R   = rA + (e >> 1) * 8;
                int col = colb + (e & 1);
                float bb = (e & 1) ? b1 : b0;
                float v = acc[mt][nt][e];
                if (EPI == EPI_F32) {
                    v += bb;
                    outF[(long)R * N + col] = v;
                } else if (EPI == EPI_PART) {
                    outF[(long)R * N + col] = v;
                } else if (EPI == EPI_GELU) {
                    v += bb;
                    v = 0.5f * v * (1.0f + erff(v * 0.70710678118654752f));
                    outH[(long)R * N + col] = __float2half(v);
                } else if (EPI == EPI_QK) {
                    v += bb;
                    int bi = R >> 9, s = R & 511, hh = col >> 6, d = col & 63;
                    long o = (((long)(bi * NHH + hh)) * SS + s) * DD + d;
                    outH[o] = __float2half(v);
                } else if (EPI == EPI_SCORES) {
                    v = v * 0.125f + bb;
                    outF[((long)z * SS + R) * SS + col] = v;
                } else {  // EPI_CTX: merge heads
                    long o = ((long)(zb * SS + R)) * HH + zh * DD + col;
                    outH[o] = __float2half(v);
                }
            }
        }
    }
}

// ---------------- weight fp16 convert (z selects tensor) --------------------
__global__ __launch_bounds__(256)
void wconv4_kernel(const float* __restrict__ a0, const float* __restrict__ a1,
                   const float* __restrict__ a2, const float* __restrict__ a3,
                   long n)
{
    int zs = blockIdx.z;
    const float* W = (zs == 0) ? a0 : (zs == 1) ? a1 : (zs == 2) ? a2 : a3;
    h16* o = (zs == 0) ? g_wq : (zs == 1) ? g_wk : (zs == 2) ? g_wv : g_wo;
    long i = (long)blockIdx.x * 256 + threadIdx.x;
    long stride = (long)gridDim.x * 256;
    for (; i < n; i += stride) o[i] = __float2half(W[i]);
}
__global__ __launch_bounds__(256)
void wconv2_kernel(const float* __restrict__ a0, const float* __restrict__ a1, long n)
{
    int zs = blockIdx.z;
    const float* W = (zs == 0) ? a0 : a1;
    h16* o = (zs == 0) ? g_w1 : g_w2;
    long i = (long)blockIdx.x * 256 + threadIdx.x;
    long stride = (long)gridDim.x * 256;
    for (; i < n; i += stride) o[i] = __float2half(W[i]);
}

// ---------------- block reductions ------------------------------------------
__device__ __forceinline__ float blockSum(float v, float* red) {
    int tid = threadIdx.x;
    red[tid] = v; __syncthreads();
    for (int s = 128; s > 0; s >>= 1) {
        if (tid < s) red[tid] += red[tid + s];
        __syncthreads();
    }
    float r = red[0]; __syncthreads();
    return r;
}

// ---------------- embeddings + layernorm + mask -----------------------------
__global__ __launch_bounds__(256)
void embed_ln_kernel(const int* __restrict__ ids, const int* __restrict__ tids,
                     const float* __restrict__ we, const float* __restrict__ pe,
                     const float* __restrict__ te, const float* __restrict__ sc,
                     const float* __restrict__ bi, float* __restrict__ out,
                     h16* __restrict__ o16, float* __restrict__ mask)
{
    __shared__ float red[256];
    int row = blockIdx.x, s = row % SS, tid = threadIdx.x;
    int id = ids[row], tt = tids[row];
    if (tid == 0) mask[row] = (id == 0) ? -10000.0f : 0.0f;
    float v[3]; float sum = 0.f;
    #pragma unroll
    for (int i = 0; i < 3; i++) {
        int j = tid + i * 256;
        v[i] = we[(long)id * HH + j] + pe[s * HH + j] + te[tt * HH + j];
        sum += v[i];
    }
    float mu = blockSum(sum, red) * (1.0f / HH);
    float s2 = 0.f;
    #pragma unroll
    for (int i = 0; i < 3; i++) { float d = v[i] - mu; s2 += d * d; }
    float inv = rsqrtf(blockSum(s2, red) * (1.0f / HH) + 1e-12f);
    #pragma unroll
    for (int i = 0; i < 3; i++) {
        int j = tid + i * 256;
        float r = (v[i] - mu) * inv * sc[j] + bi[j];
        long o = (long)row * HH + j;
        out[o] = r;
        o16[o] = __float2half(r);
    }
}

// ---------------- residual + 3 split-K partials + bias + layernorm -----------
__global__ __launch_bounds__(256)
void add_ln3_kernel(const float* __restrict__ x, const float* __restrict__ t,
                    const float* __restrict__ pb, const float* __restrict__ sc,
                    const float* __restrict__ bi, float* __restrict__ out,
                    h16* __restrict__ o16)
{
    __shared__ float red[256];
    int row = blockIdx.x, tid = threadIdx.x;
    const float *t1 = t + (long)BSN * HH, *t2 = t + 2L * BSN * HH;
    float v[3]; float sum = 0.f;
    #pragma unroll
    for (int i = 0; i < 3; i++) {
        int j = tid + i * 256;
        long o = (long)row * HH + j;
        v[i] = x[o] + t[o] + t1[o] + t2[o] + pb[j];
        sum += v[i];
    }
    float mu = blockSum(sum, red) * (1.0f / HH);
    float s2 = 0.f;
    #pragma unroll
    for (int i = 0; i < 3; i++) { float d = v[i] - mu; s2 += d * d; }
    float inv = rsqrtf(blockSum(s2, red) * (1.0f / HH) + 1e-12f);
    #pragma unroll
    for (int i = 0; i < 3; i++) {
        int j = tid + i * 256;
        float r = (v[i] - mu) * inv * sc[j] + bi[j];
        long o = (long)row * HH + j;
        out[o] = r;
        o16[o] = __float2half(r);
    }
}

// ---------------- softmax (512) -> single fp16 -------------------------------
__global__ __launch_bounds__(256)
void softmax512_kernel(const float* __restrict__ p, h16* __restrict__ p16)
{
    __shared__ float red[256];
    long base = (long)blockIdx.x * SS;
    int tid = threadIdx.x;
    float a = p[base + tid], b = p[base + tid + 256];
    red[tid] = fmaxf(a, b); __syncthreads();
    for (int s = 128; s > 0; s >>= 1) {
        if (tid < s) red[tid] = fmaxf(red[tid], red[tid + s]);
        __syncthreads();
    }
    float m = red[0]; __syncthreads();
    float e0 = __expf(a - m), e1 = __expf(b - m);
    red[tid] = e0 + e1; __syncthreads();
    for (int s = 128; s > 0; s >>= 1) {
        if (tid < s) red[tid] += red[tid + s];
        __syncthreads();
    }
    float inv = 1.0f / red[0];
    p16[base + tid]       = __float2half(e0 * inv);
    p16[base + tid + 256] = __float2half(e1 * inv);
}

// ---------------------------------------------------------------------------
extern "C" void kernel_launch(void* const* d_in, const int* in_sizes, int n_in,
                              void* d_out, int out_size)
{
    const int*   ids  = (const int*)  d_in[0];
    const int*   tids = (const int*)  d_in[1];
    const float* we   = (const float*)d_in[2];
    const float* pe   = (const float*)d_in[3];
    const float* te   = (const float*)d_in[4];
    const float* esc  = (const float*)d_in[5];
    const float* ebi  = (const float*)d_in[6];
    const float* wq   = (const float*)d_in[7];
    const float* bq   = (const float*)d_in[8];
    const float* wk   = (const float*)d_in[9];
    const float* bk   = (const float*)d_in[10];
    const float* wv   = (const float*)d_in[11];
    const float* bv   = (const float*)d_in[12];
    const float* wo   = (const float*)d_in[13];
    const float* bo   = (const float*)d_in[14];
    const float* l1s  = (const float*)d_in[15];
    const float* l1b  = (const float*)d_in[16];
    const float* w1   = (const float*)d_in[17];
    const float* b1   = (const float*)d_in[18];
    const float* w2   = (const float*)d_in[19];
    const float* b2   = (const float*)d_in[20];
    const float* l2s  = (const float*)d_in[21];
    const float* l2b  = (const float*)d_in[22];
    float* out = (float*)d_out;

    float *h, *tmp, *sc, *mask;
    h16 *h16p, *q16, *k16, *v16, *c16, *a16, *p16;
    h16 *wo_w, *w1_w, *w2_w;
    cudaGetSymbolAddress((void**)&h,    g_h);
    cudaGetSymbolAddress((void**)&tmp,  g_tmp);
    cudaGetSymbolAddress((void**)&sc,   g_sc);
    cudaGetSymbolAddress((void**)&mask, g_mask);
    cudaGetSymbolAddress((void**)&h16p, g_h16);
    cudaGetSymbolAddress((void**)&q16,  g_q16);
    cudaGetSymbolAddress((void**)&k16,  g_k16);
    cudaGetSymbolAddress((void**)&v16,  g_v16);
    cudaGetSymbolAddress((void**)&c16,  g_c16);
    cudaGetSymbolAddress((void**)&a16,  g_a16);
    cudaGetSymbolAddress((void**)&p16,  g_p16);
    cudaGetSymbolAddress((void**)&wo_w, g_wo);
    cudaGetSymbolAddress((void**)&w1_w, g_w1);
    cudaGetSymbolAddress((void**)&w2_w, g_w2);

    // dynamic smem: STAGES * (A + B)
    const int SM_1P = 4 * (10240 + 32 * 136 * 2);     // k-major NT=128: 75776
    const int SM_NT = 2 * (10240 + 10240);            // scores: 40960
    const int SM_CX = 4 * (10240 + 32 * 72 * 2);      // ctx NT=64: 59392
    cudaFuncSetAttribute((const void*)mma_gemm<128, EPI_QK,     false, 4, true,  1>, cudaFuncAttributeMaxDynamicSharedMemorySize, SM_1P);
    cudaFuncSetAttribute((const void*)mma_gemm<128, EPI_PART,   false, 4, false, 3>, cudaFuncAttributeMaxDynamicSharedMemorySize, SM_1P);
    cudaFuncSetAttribute((const void*)mma_gemm<128, EPI_GELU,   false, 4, false, 1>, cudaFuncAttributeMaxDynamicSharedMemorySize, SM_1P);
    cudaFuncSetAttribute((const void*)mma_gemm<128, EPI_SCORES, true,  2, false, 1>, cudaFuncAttributeMaxDynamicSharedMemorySize, SM_NT);
    cudaFuncSetAttribute((const void*)mma_gemm<64,  EPI_CTX,    false, 4, false, 1>, cudaFuncAttributeMaxDynamicSharedMemorySize, SM_CX);

    const dim3 gQKV(HH / 128, BSN / 128, 3);    // (6, 32, 3) fused QKV
    const dim3 gSK (HH / 128, BSN / 128, 3);    // (6, 32, 3) split-K proj/FFN2
    const dim3 gFF (FF / 128, BSN / 128, 1);    // (24, 32)
    const dim3 gSC (SS / 128, SS / 128, ZH);    // (4, 4, 96)
    const dim3 gCX (1, SS / 128, ZH);           // (1, 4, 96)

    embed_ln_kernel<<<BSN, 256>>>(ids, tids, we, pe, te, esc, ebi, h, h16p, mask);
    wconv4_kernel<<<dim3(2048, 1, 4), 256>>>(wq, wk, wv, wo, (long)LL * HH * HH);
    wconv2_kernel<<<dim3(4096, 1, 2), 256>>>(w1, w2, (long)LL * HH * FF);

    for (int l = 0; l < LL; l++) {
        long wOff = (long)l * HH * HH, bOff = (long)l * HH;
        long w1Off = (long)l * HH * FF, b1Off = (long)l * FF;

        mma_gemm<128, EPI_QK, false, 4, true, 1><<<gQKV, 256, SM_1P>>>(
            h16p, nullptr, bq + bOff, bk + bOff, bv + bOff,
            nullptr, nullptr, nullptr, BSN, HH, HH, HH, 0, wOff);

        // scores: A = Q [z][S][D], B = K [z][S][D] (NT gemm)
        mma_gemm<128, EPI_SCORES, true, 2, false, 1><<<gSC, 256, SM_NT>>>(
            q16, k16, nullptr, nullptr, nullptr, mask,
            sc, nullptr, SS, SS, DD, DD, (long)SS * DD, (long)SS * DD);

        softmax512_kernel<<<ZH * SS, 256>>>(sc, p16);

        // ctx: A = P [z][S][S], B = V [z][S][D] (k-major)
        mma_gemm<64, EPI_CTX, false, 4, false, 1><<<gCX, 256, SM_CX>>>(
            p16, v16, nullptr, nullptr, nullptr, nullptr,
            nullptr, c16, SS, DD, SS, SS, (long)SS * SS, (long)SS * DD);

        // wo-proj: split-K=3 partials into tmp[0..2]
        mma_gemm<128, EPI_PART, false, 4, false, 3><<<gSK, 256, SM_1P>>>(
            c16, wo_w + wOff, nullptr, nullptr, nullptr,
            nullptr, tmp, nullptr, BSN, HH, HH, HH, 0, 0);
        add_ln3_kernel<<<BSN, 256>>>(h, tmp, bo + bOff, l1s + bOff, l1b + bOff,
                                     h, h16p);

        mma_gemm<128, EPI_GELU, false, 4, false, 1><<<gFF, 256, SM_1P>>>(
            h16p, w1_w + w1Off, b1 + b1Off, nullptr, nullptr,
            nullptr, nullptr, a16, BSN, FF, HH, HH, 0, 0);
        // FFN2: split-K=3 partials into tmp[0..2]
        mma_gemm<128, EPI_PART, false, 4, false, 3><<<gSK, 256, SM_1P>>>(
            a16, w2_w + w1Off, nullptr, nullptr, nullptr,
            nullptr, tmp, nullptr, BSN, HH, FF, FF, 0, 0);
        add_ln3_kernel<<<BSN, 256>>>(h, tmp, b2 + bOff, l2s + bOff, l2b + bOff,
                                     (l == LL - 1) ? out : h, h16p);
    }
}

// round 15
// speedup vs baseline: 5.8303x; 1.2056x over previous
#include <cuda_runtime.h>
#include <cuda_fp16.h>
#include <cstdint>

// ---------------------------------------------------------------------------
// BERT-base encoder forward, fp16 mma.sync (HMMA) GEMMs. sm_103-safe PTX.
// All GEMMs single-fp16 x single-fp16, fp32 accum. K-epoch 64 (2x fewer
// barriers), 3-stage cp.async pipeline, vectorized epilogues.
// B=8, S=512, H=768, NH=12, D=64, F=3072, L=12
// ---------------------------------------------------------------------------

#define BB   8
#define SS   512
#define HH   768
#define NHH  12
#define DD   64
#define FF   3072
#define LL   12
#define BSN  (BB*SS)          // 4096 tokens
#define ZH   (BB*NHH)         // 96

typedef __half h16;

// ---------------- scratch (device globals; no allocations) -----------------
__device__ float g_h  [BSN*HH];
__device__ float g_tmp[3L*BSN*HH];          // split-K partials (3 slices)
__device__ float g_sc [(long)ZH*SS*SS];     // attention logits fp32 (~100MB)
__device__ float g_mask[BSN];

__device__ h16 g_h16[BSN*HH];               // h
__device__ h16 g_q16[BSN*HH];               // [z][S][D]
__device__ h16 g_k16[BSN*HH];               // [z][S][D]
__device__ h16 g_v16[BSN*HH];               // [z][S][D]
__device__ h16 g_c16[BSN*HH];               // ctx [B*S][H]
__device__ h16 g_a16[BSN*FF];               // ffn act
__device__ h16 g_p16[(long)ZH*SS*SS];       // probs

__device__ h16 g_wq[LL*HH*HH], g_wk[LL*HH*HH];      // weights fp16
__device__ h16 g_wv[LL*HH*HH], g_wo[LL*HH*HH];
__device__ h16 g_w1[(long)LL*HH*FF], g_w2[(long)LL*FF*HH];

// ---------------- small helpers --------------------------------------------
__device__ __forceinline__ uint32_t smem_u32(const void* p) {
    uint32_t a;
    asm("{ .reg .u64 t; cvta.to.shared.u64 t, %1; cvt.u32.u64 %0, t; }" : "=r"(a) : "l"(p));
    return a;
}
__device__ __forceinline__ void cpasync16(uint32_t s, const void* g) {
    asm volatile("cp.async.cg.shared.global [%0], [%1], 16;" :: "r"(s), "l"(g) : "memory");
}
#define CP_COMMIT() asm volatile("cp.async.commit_group;" ::: "memory")
#define CP_WAIT0()  asm volatile("cp.async.wait_group 0;" ::: "memory")
#define CP_WAIT1()  asm volatile("cp.async.wait_group 1;" ::: "memory")

__device__ __forceinline__ void ldsm4(uint32_t& r0, uint32_t& r1, uint32_t& r2,
                                      uint32_t& r3, uint32_t addr) {
    asm volatile("ldmatrix.sync.aligned.m8n8.x4.shared.b16 {%0,%1,%2,%3}, [%4];"
                 : "=r"(r0), "=r"(r1), "=r"(r2), "=r"(r3) : "r"(addr));
}
__device__ __forceinline__ void ldsm4t(uint32_t& r0, uint32_t& r1, uint32_t& r2,
                                       uint32_t& r3, uint32_t addr) {
    asm volatile("ldmatrix.sync.aligned.m8n8.x4.trans.shared.b16 {%0,%1,%2,%3}, [%4];"
                 : "=r"(r0), "=r"(r1), "=r"(r2), "=r"(r3) : "r"(addr));
}
__device__ __forceinline__ void mma16816(float* c, const uint32_t* a,
                                         uint32_t b0, uint32_t b1) {
    asm("mma.sync.aligned.m16n8k16.row.col.f32.f16.f16.f32 "
        "{%0,%1,%2,%3}, {%4,%5,%6,%7}, {%8,%9}, {%0,%1,%2,%3};"
        : "+f"(c[0]), "+f"(c[1]), "+f"(c[2]), "+f"(c[3])
        : "r"(a[0]), "r"(a[1]), "r"(a[2]), "r"(a[3]), "r"(b0), "r"(b1));
}

// ---------------------------------------------------------------------------
// mma.sync GEMM: C[M,N] = A[M,K] @ B, A row-major [M][K] (row stride ldA).
// BNT=false: B row-major [K][N] (k-major, ldmatrix.trans). BNT=true: [N][K].
// CTA tile 128 x NT, K-EPOCH 64 (4 x k16 per barrier), 8 warps,
// STAGES-deep cp.async pipeline.
// QKV3: gridDim.z = 3 selects {wq->q, wk->k, wv->v} from device globals.
// KSPL>1: split-K over gridDim.z; each part writes outF + z*M*N (no bias).
// ---------------------------------------------------------------------------
#define EPI_F32    0
#define EPI_GELU   1   // bias + gelu -> h16
#define EPI_QK     2   // bias + scatter [z][S][D] h16      (Q, K, V)
#define EPI_SCORES 4   // *0.125 + mask, fp32 [z][S][S]
#define EPI_CTX    5   // merge heads -> [B*S, H] h16
#define EPI_PART   6   // raw fp32 partial (split-K), no bias

template<int NT, int EPI, bool BNT, int STAGES, bool QKV3, int KSPL>
__global__ __launch_bounds__(256, 2)
void mma_gemm(const h16* A, const h16* B,
              const float* bias, const float* bias2, const float* bias3,
              const float* mask,
              float* outF, h16* outH,
              int M, int N, int K, int ldA, long sAz, long sBz)
{
    constexpr int WARPS_N = (NT == 128) ? 4 : 2;
    constexpr int WM = (NT == 128) ? 64 : 32;        // warp tile M
    constexpr int MT = WM / 16;                      // m-tiles (4 or 2)
    constexpr int LDA_S = 72;                        // A smem row elems (64+8)
    constexpr int ABYT = 128 * LDA_S * 2;            // 18432
    constexpr int LDB_S = BNT ? 72 : (NT + 8);       // B smem row elems
    constexpr int BBYT = BNT ? (NT * LDA_S * 2) : (64 * LDB_S * 2);
    constexpr int OB   = ABYT;
    constexpr int BUFB = ABYT + BBYT;

    extern __shared__ char smem[];
    const uint32_t sb = smem_u32(smem);

    const int tid = threadIdx.x, wid = tid >> 5, lane = tid & 31;
    const int wm = wid / WARPS_N, wn = wid % WARPS_N;
    const int z = blockIdx.z;
    int Kloop = K;
    if constexpr (QKV3) {
        if (z == 1)      { B = g_wk + sBz; bias = bias2; outH = g_k16; }
        else if (z == 2) { B = g_wv + sBz; bias = bias3; outH = g_v16; }
        else             { B = g_wq + sBz;               outH = g_q16; }
    } else if constexpr (KSPL > 1) {
        int koff = z * (K / KSPL);
        A += koff;
        B += (long)koff * N;
        outF += (long)z * M * N;
        Kloop = K / KSPL;
    } else {
        A += (long)z * sAz;
        B += (long)z * sBz;
    }
    const int bm0 = blockIdx.y * 128;
    const int bn0 = blockIdx.x * NT;

    // ---- async epoch loader (64 k) ----
    auto load_chunk = [&](int buf, int k0) {
        uint32_t base = sb + buf * BUFB;
        #pragma unroll
        for (int i = 0; i < 4; i++) {                 // A: 128 rows x 8 16B chunks
            int idx = tid + i * 256;
            int r = idx >> 3, c = idx & 7;
            long go = (long)(bm0 + r) * ldA + k0 + c * 8;
            uint32_t so = r * (LDA_S * 2) + c * 16;
            cpasync16(base + so, A + go);
        }
        if (BNT) {
            #pragma unroll
            for (int i = 0; i < NT * 8 / 256; i++) {  // B: NT rows x 8 chunks
                int idx = tid + i * 256;
                int r = idx >> 3, c = idx & 7;
                long go = (long)(bn0 + r) * K + k0 + c * 8;
                uint32_t so = r * (LDA_S * 2) + c * 16;
                cpasync16(base + OB + so, B + go);
            }
        } else {
            constexpr int BCH = NT / 8;               // 16B chunks per B row
            #pragma unroll
            for (int i = 0; i < 64 * BCH / 256; i++) { // B: 64 rows
                int idx = tid + i * 256;
                int r = idx / BCH, c = idx % BCH;
                long go = (long)(k0 + r) * N + bn0 + c * 8;
                uint32_t so = r * (LDB_S * 2) + c * 16;
                cpasync16(base + OB + so, B + go);
            }
        }
        CP_COMMIT();
    };

    float acc[MT][4][4];
    #pragma unroll
    for (int i = 0; i < MT; i++)
        #pragma unroll
        for (int j = 0; j < 4; j++)
            #pragma unroll
            for (int e = 0; e < 4; e++) acc[i][j][e] = 0.f;

    const int nkc = Kloop >> 6;                      // epochs of 64
    #pragma unroll
    for (int s = 0; s < STAGES - 1; s++)
        if (s < nkc) load_chunk(s, s * 64);

    const int arow = wm * WM + (lane & 15);
    const int acol8 = (lane >> 4) << 3;

    for (int kc = 0; kc < nkc; kc++) {
        {
            int pend = STAGES - 2;
            if (nkc - 1 - kc < pend) pend = nkc - 1 - kc;
            if (pend >= 1) { CP_WAIT1(); } else { CP_WAIT0(); }
        }
        __syncthreads();
        if (kc + STAGES - 1 < nkc)
            load_chunk((kc + STAGES - 1) % STAGES, (kc + STAGES - 1) * 64);

        const uint32_t base = sb + (kc % STAGES) * BUFB;

        #pragma unroll
        for (int ks = 0; ks < 4; ks++) {
            const int k0s = ks * 16;
            uint32_t af[MT][4];
            uint32_t bf[4][2];
            #pragma unroll
            for (int mt = 0; mt < MT; mt++) {
                uint32_t ao = (uint32_t)((arow + mt * 16) * (LDA_S * 2)
                                         + (k0s + acol8) * 2);
                ldsm4(af[mt][0], af[mt][1], af[mt][2], af[mt][3], base + ao);
            }
            if (BNT) {
                #pragma unroll
                for (int half = 0; half < 2; half++) {
                    uint32_t bo = (uint32_t)((wn * 32 + half * 16 + (lane & 15)) * (LDA_S * 2)
                                             + (k0s + acol8) * 2);
                    uint32_t r0, r1, r2, r3;
                    ldsm4(r0, r1, r2, r3, base + OB + bo);
                    bf[half*2+0][0] = r0; bf[half*2+0][1] = r2;
                    bf[half*2+1][0] = r1; bf[half*2+1][1] = r3;
                }
            } else {
                const int brow = lane & 15;
                const int bcol8 = wn * 32 + ((lane >> 4) << 3);
                #pragma unroll
                for (int np = 0; np < 2; np++) {
                    uint32_t bo = (uint32_t)((k0s + brow) * (LDB_S * 2)
                                             + (bcol8 + np * 16) * 2);
                    uint32_t r0, r1, r2, r3;
                    ldsm4t(r0, r1, r2, r3, base + OB + bo);
                    bf[np*2+0][0] = r0; bf[np*2+0][1] = r1;
                    bf[np*2+1][0] = r2; bf[np*2+1][1] = r3;
                }
            }
            #pragma unroll
            for (int j = 0; j < 4; j++)
                #pragma unroll
                for (int mt = 0; mt < MT; mt++)
                    mma16816(acc[mt][j], af[mt], bf[j][0], bf[j][1]);
        }
    }

    // ---- epilogue (vectorized: col pairs are contiguous) ----
    const int zb = z / NHH, zh = z % NHH;
    #pragma unroll
    for (int nt = 0; nt < 4; nt++) {
        const int colb = bn0 + wn * 32 + nt * 8 + 2 * (lane & 3);
        float b0 = 0.f, b1 = 0.f;
        if (EPI == EPI_F32 || EPI == EPI_GELU || EPI == EPI_QK) {
            b0 = __ldg(&bias[colb]); b1 = __ldg(&bias[colb + 1]);
        } else if (EPI == EPI_SCORES) {
            b0 = __ldg(&mask[zb * SS + colb]); b1 = __ldg(&mask[zb * SS + colb + 1]);
        }
        #pragma unroll
        for (int mt = 0; mt < MT; mt++) {
            const int rA = bm0 + wm * WM + mt * 16 + (lane >> 2);
            #pragma unroll
            for (int half = 0; half < 2; half++) {   // row r and r+8
                int R = rA + half * 8;
                float v0 = acc[mt][nt][half * 2 + 0];
                float v1 = acc[mt][nt][half * 2 + 1];
                if (EPI == EPI_F32) {
                    float2 w = {v0 + b0, v1 + b1};
                    *(float2*)&outF[(long)R * N + colb] = w;
                } else if (EPI == EPI_PART) {
                    float2 w = {v0, v1};
                    *(float2*)&outF[(long)R * N + colb] = w;
                } else if (EPI == EPI_SCORES) {
                    float2 w = {v0 * 0.125f + b0, v1 * 0.125f + b1};
                    *(float2*)&outF[((long)z * SS + R) * SS + colb] = w;
                } else if (EPI == EPI_GELU) {
                    v0 += b0; v1 += b1;
                    v0 = 0.5f * v0 * (1.0f + erff(v0 * 0.70710678118654752f));
                    v1 = 0.5f * v1 * (1.0f + erff(v1 * 0.70710678118654752f));
                    *(__half2*)&outH[(long)R * N + colb] =
                        __halves2half2(__float2half(v0), __float2half(v1));
                } else if (EPI == EPI_QK) {
                    v0 += b0; v1 += b1;
                    int bi = R >> 9, s = R & 511, hh = colb >> 6, d = colb & 63;
                    long o = (((long)(bi * NHH + hh)) * SS + s) * DD + d;
                    *(__half2*)&outH[o] =
                        __halves2half2(__float2half(v0), __float2half(v1));
                } else {  // EPI_CTX
                    long o = ((long)(zb * SS + R)) * HH + zh * DD + colb;
                    *(__half2*)&outH[o] =
                        __halves2half2(__float2half(v0), __float2half(v1));
                }
            }
        }
    }
}

// ---------------- weight fp16 convert (z selects tensor) --------------------
__global__ __launch_bounds__(256)
void wconv4_kernel(const float* __restrict__ a0, const float* __restrict__ a1,
                   const float* __restrict__ a2, const float* __restrict__ a3,
                   long n)
{
    int zs = blockIdx.z;
    const float* W = (zs == 0) ? a0 : (zs == 1) ? a1 : (zs == 2) ? a2 : a3;
    h16* o = (zs == 0) ? g_wq : (zs == 1) ? g_wk : (zs == 2) ? g_wv : g_wo;
    long i = (long)blockIdx.x * 256 + threadIdx.x;
    long stride = (long)gridDim.x * 256;
    for (; i < n; i += stride) o[i] = __float2half(W[i]);
}
__global__ __launch_bounds__(256)
void wconv2_kernel(const float* __restrict__ a0, const float* __restrict__ a1, long n)
{
    int zs = blockIdx.z;
    const float* W = (zs == 0) ? a0 : a1;
    h16* o = (zs == 0) ? g_w1 : g_w2;
    long i = (long)blockIdx.x * 256 + threadIdx.x;
    long stride = (long)gridDim.x * 256;
    for (; i < n; i += stride) o[i] = __float2half(W[i]);
}

// ---------------- block reductions ------------------------------------------
__device__ __forceinline__ float blockSum(float v, float* red) {
    int tid = threadIdx.x;
    red[tid] = v; __syncthreads();
    for (int s = 128; s > 0; s >>= 1) {
        if (tid < s) red[tid] += red[tid + s];
        __syncthreads();
    }
    float r = red[0]; __syncthreads();
    return r;
}

// ---------------- embeddings + layernorm + mask -----------------------------
__global__ __launch_bounds__(256)
void embed_ln_kernel(const int* __restrict__ ids, const int* __restrict__ tids,
                     const float* __restrict__ we, const float* __restrict__ pe,
                     const float* __restrict__ te, const float* __restrict__ sc,
                     const float* __restrict__ bi, float* __restrict__ out,
                     h16* __restrict__ o16, float* __restrict__ mask)
{
    __shared__ float red[256];
    int row = blockIdx.x, s = row % SS, tid = threadIdx.x;
    int id = ids[row], tt = tids[row];
    if (tid == 0) mask[row] = (id == 0) ? -10000.0f : 0.0f;
    float v[3]; float sum = 0.f;
    #pragma unroll
    for (int i = 0; i < 3; i++) {
        int j = tid + i * 256;
        v[i] = we[(long)id * HH + j] + pe[s * HH + j] + te[tt * HH + j];
        sum += v[i];
    }
    float mu = blockSum(sum, red) * (1.0f / HH);
    float s2 = 0.f;
    #pragma unroll
    for (int i = 0; i < 3; i++) { float d = v[i] - mu; s2 += d * d; }
    float inv = rsqrtf(blockSum(s2, red) * (1.0f / HH) + 1e-12f);
    #pragma unroll
    for (int i = 0; i < 3; i++) {
        int j = tid + i * 256;
        float r = (v[i] - mu) * inv * sc[j] + bi[j];
        long o = (long)row * HH + j;
        out[o] = r;
        o16[o] = __float2half(r);
    }
}

// ---------------- residual + 3 split-K partials + bias + layernorm -----------
__global__ __launch_bounds__(256)
void add_ln3_kernel(const float* __restrict__ x, const float* __restrict__ t,
                    const float* __restrict__ pb, const float* __restrict__ sc,
                    const float* __restrict__ bi, float* __restrict__ out,
                    h16* __restrict__ o16)
{
    __shared__ float red[256];
    int row = blockIdx.x, tid = threadIdx.x;
    const float *t1 = t + (long)BSN * HH, *t2 = t + 2L * BSN * HH;
    float v[3]; float sum = 0.f;
    #pragma unroll
    for (int i = 0; i < 3; i++) {
        int j = tid + i * 256;
        long o = (long)row * HH + j;
        v[i] = x[o] + t[o] + t1[o] + t2[o] + pb[j];
        sum += v[i];
    }
    float mu = blockSum(sum, red) * (1.0f / HH);
    float s2 = 0.f;
    #pragma unroll
    for (int i = 0; i < 3; i++) { float d = v[i] - mu; s2 += d * d; }
    float inv = rsqrtf(blockSum(s2, red) * (1.0f / HH) + 1e-12f);
    #pragma unroll
    for (int i = 0; i < 3; i++) {
        int j = tid + i * 256;
        float r = (v[i] - mu) * inv * sc[j] + bi[j];
        long o = (long)row * HH + j;
        out[o] = r;
        o16[o] = __float2half(r);
    }
}

// ---------------- softmax (512) -> single fp16 -------------------------------
__global__ __launch_bounds__(256)
void softmax512_kernel(const float* __restrict__ p, h16* __restrict__ p16)
{
    __shared__ float red[256];
    long base = (long)blockIdx.x * SS;
    int tid = threadIdx.x;
    float a = p[base + tid], b = p[base + tid + 256];
    red[tid] = fmaxf(a, b); __syncthreads();
    for (int s = 128; s > 0; s >>= 1) {
        if (tid < s) red[tid] = fmaxf(red[tid], red[tid + s]);
        __syncthreads();
    }
    float m = red[0]; __syncthreads();
    float e0 = __expf(a - m), e1 = __expf(b - m);
    red[tid] = e0 + e1; __syncthreads();
    for (int s = 128; s > 0; s >>= 1) {
        if (tid < s) red[tid] += red[tid + s];
        __syncthreads();
    }
    float inv = 1.0f / red[0];
    p16[base + tid]       = __float2half(e0 * inv);
    p16[base + tid + 256] = __float2half(e1 * inv);
}

// ---------------------------------------------------------------------------
extern "C" void kernel_launch(void* const* d_in, const int* in_sizes, int n_in,
                              void* d_out, int out_size)
{
    const int*   ids  = (const int*)  d_in[0];
    const int*   tids = (const int*)  d_in[1];
    const float* we   = (const float*)d_in[2];
    const float* pe   = (const float*)d_in[3];
    const float* te   = (const float*)d_in[4];
    const float* esc  = (const float*)d_in[5];
    const float* ebi  = (const float*)d_in[6];
    const float* wq   = (const float*)d_in[7];
    const float* bq   = (const float*)d_in[8];
    const float* wk   = (const float*)d_in[9];
    const float* bk   = (const float*)d_in[10];
    const float* wv   = (const float*)d_in[11];
    const float* bv   = (const float*)d_in[12];
    const float* wo   = (const float*)d_in[13];
    const float* bo   = (const float*)d_in[14];
    const float* l1s  = (const float*)d_in[15];
    const float* l1b  = (const float*)d_in[16];
    const float* w1   = (const float*)d_in[17];
    const float* b1   = (const float*)d_in[18];
    const float* w2   = (const float*)d_in[19];
    const float* b2   = (const float*)d_in[20];
    const float* l2s  = (const float*)d_in[21];
    const float* l2b  = (const float*)d_in[22];
    float* out = (float*)d_out;

    float *h, *tmp, *sc, *mask;
    h16 *h16p, *q16, *k16, *v16, *c16, *a16, *p16;
    h16 *wo_w, *w1_w, *w2_w;
    cudaGetSymbolAddress((void**)&h,    g_h);
    cudaGetSymbolAddress((void**)&tmp,  g_tmp);
    cudaGetSymbolAddress((void**)&sc,   g_sc);
    cudaGetSymbolAddress((void**)&mask, g_mask);
    cudaGetSymbolAddress((void**)&h16p, g_h16);
    cudaGetSymbolAddress((void**)&q16,  g_q16);
    cudaGetSymbolAddress((void**)&k16,  g_k16);
    cudaGetSymbolAddress((void**)&v16,  g_v16);
    cudaGetSymbolAddress((void**)&c16,  g_c16);
    cudaGetSymbolAddress((void**)&a16,  g_a16);
    cudaGetSymbolAddress((void**)&p16,  g_p16);
    cudaGetSymbolAddress((void**)&wo_w, g_wo);
    cudaGetSymbolAddress((void**)&w1_w, g_w1);
    cudaGetSymbolAddress((void**)&w2_w, g_w2);

    // dynamic smem: STAGES * (A + B), epoch = 64 k
    const int SM_1P = 3 * (18432 + 64 * 136 * 2);   // k-major NT=128: 107520
    const int SM_NT = 2 * (18432 + 18432);          // scores (K=64, 1 epoch): 73728
    const int SM_CX = 3 * (18432 + 64 * 72 * 2);    // ctx NT=64: 82944
    cudaFuncSetAttribute((const void*)mma_gemm<128, EPI_QK,     false, 3, true,  1>, cudaFuncAttributeMaxDynamicSharedMemorySize, SM_1P);
    cudaFuncSetAttribute((const void*)mma_gemm<128, EPI_PART,   false, 3, false, 3>, cudaFuncAttributeMaxDynamicSharedMemorySize, SM_1P);
    cudaFuncSetAttribute((const void*)mma_gemm<128, EPI_GELU,   false, 3, false, 1>, cudaFuncAttributeMaxDynamicSharedMemorySize, SM_1P);
    cudaFuncSetAttribute((const void*)mma_gemm<128, EPI_SCORES, true,  2, false, 1>, cudaFuncAttributeMaxDynamicSharedMemorySize, SM_NT);
    cudaFuncSetAttribute((const void*)mma_gemm<64,  EPI_CTX,    false, 3, false, 1>, cudaFuncAttributeMaxDynamicSharedMemorySize, SM_CX);

    const dim3 gQKV(HH / 128, BSN / 128, 3);    // (6, 32, 3) fused QKV
    const dim3 gSK (HH / 128, BSN / 128, 3);    // (6, 32, 3) split-K proj/FFN2
    const dim3 gFF (FF / 128, BSN / 128, 1);    // (24, 32)
    const dim3 gSC (SS / 128, SS / 128, ZH);    // (4, 4, 96)
    const dim3 gCX (1, SS / 128, ZH);           // (1, 4, 96)

    embed_ln_kernel<<<BSN, 256>>>(ids, tids, we, pe, te, esc, ebi, h, h16p, mask);
    wconv4_kernel<<<dim3(2048, 1, 4), 256>>>(wq, wk, wv, wo, (long)LL * HH * HH);
    wconv2_kernel<<<dim3(4096, 1, 2), 256>>>(w1, w2, (long)LL * HH * FF);

    for (int l = 0; l < LL; l++) {
        long wOff = (long)l * HH * HH, bOff = (long)l * HH;
        long w1Off = (long)l * HH * FF, b1Off = (long)l * FF;

        mma_gemm<128, EPI_QK, false, 3, true, 1><<<gQKV, 256, SM_1P>>>(
            h16p, nullptr, bq + bOff, bk + bOff, bv + bOff,
            nullptr, nullptr, nullptr, BSN, HH, HH, HH, 0, wOff);

        // scores: A = Q [z][S][D], B = K [z][S][D] (NT gemm, K=64 = 1 epoch)
        mma_gemm<128, EPI_SCORES, true, 2, false, 1><<<gSC, 256, SM_NT>>>(
            q16, k16, nullptr, nullptr, nullptr, mask,
            sc, nullptr, SS, SS, DD, DD, (long)SS * DD, (long)SS * DD);

        softmax512_kernel<<<ZH * SS, 256>>>(sc, p16);

        // ctx: A = P [z][S][S], B = V [z][S][D] (k-major)
        mma_gemm<64, EPI_CTX, false, 3, false, 1><<<gCX, 256, SM_CX>>>(
            p16, v16, nullptr, nullptr, nullptr, nullptr,
            nullptr, c16, SS, DD, SS, SS, (long)SS * SS, (long)SS * DD);

        // wo-proj: split-K=3 partials into tmp[0..2]
        mma_gemm<128, EPI_PART, false, 3, false, 3><<<gSK, 256, SM_1P>>>(
            c16, wo_w + wOff, nullptr, nullptr, nullptr,
            nullptr, tmp, nullptr, BSN, HH, HH, HH, 0, 0);
        add_ln3_kernel<<<BSN, 256>>>(h, tmp, bo + bOff, l1s + bOff, l1b + bOff,
                                     h, h16p);

        mma_gemm<128, EPI_GELU, false, 3, false, 1><<<gFF, 256, SM_1P>>>(
            h16p, w1_w + w1Off, b1 + b1Off, nullptr, nullptr,
            nullptr, nullptr, a16, BSN, FF, HH, HH, 0, 0);
        // FFN2: split-K=3 partials into tmp[0..2]
        mma_gemm<128, EPI_PART, false, 3, false, 3><<<gSK, 256, SM_1P>>>(
            a16, w2_w + w1Off, nullptr, nullptr, nullptr,
            nullptr, tmp, nullptr, BSN, HH, FF, FF, 0, 0);
        add_ln3_kernel<<<BSN, 256>>>(h, tmp, b2 + bOff, l2s + bOff, l2b + bOff,
                                     (l == LL - 1) ? out : h, h16p);
    }
}